// round 10
// baseline (speedup 1.0000x reference)
#include <cuda_runtime.h>
#include <cuda_bf16.h>
#include <math.h>
#include <stdint.h>

// Problem dims (fixed)
#define BB   2
#define TT   2048
#define DD   2048
#define HH   16
#define HD   128
#define FF   4096
#define MTOK 4096            // B*T
#define QKVW (3*DD)          // 6144

// ---------------- scratch (static __device__, no allocations) ----------------
__device__ float g_x1  [(size_t)MTOK * DD];    // x after attention residual
__device__ float g_gate[(size_t)MTOK * FF];    // gate proj (fp32)

// bf16 hi/lo activation operand (h1 -> attn-out -> h2)
__device__ __nv_bfloat16 g_act_hi[(size_t)MTOK * DD];
__device__ __nv_bfloat16 g_act_lo[(size_t)MTOK * DD];

// qkv hi/lo (written by QKV GEMM epilogue; reused as ff buffer after attention)
__device__ __nv_bfloat16 g_qkv_hi[(size_t)MTOK * QKVW];
__device__ __nv_bfloat16 g_qkv_lo[(size_t)MTOK * QKVW];

// bf16 hi/lo weights (converted every launch)
__device__ __nv_bfloat16 g_wqkv_hi[(size_t)QKVW * DD];
__device__ __nv_bfloat16 g_wqkv_lo[(size_t)QKVW * DD];
__device__ __nv_bfloat16 g_wo_hi  [(size_t)DD * DD];
__device__ __nv_bfloat16 g_wo_lo  [(size_t)DD * DD];
__device__ __nv_bfloat16 g_wg_hi  [(size_t)FF * DD];
__device__ __nv_bfloat16 g_wg_lo  [(size_t)FF * DD];
__device__ __nv_bfloat16 g_wu_hi  [(size_t)FF * DD];
__device__ __nv_bfloat16 g_wu_lo  [(size_t)FF * DD];
__device__ __nv_bfloat16 g_wd_hi  [(size_t)DD * FF];
__device__ __nv_bfloat16 g_wd_lo  [(size_t)DD * FF];

// ======================= PTX helpers (baseline ISA only) =======================
__device__ __forceinline__ uint32_t smem_u32(const void* p) {
    uint32_t a;
    asm("{ .reg .u64 t; cvta.to.shared.u64 t, %1; cvt.u32.u64 %0, t; }" : "=r"(a) : "l"(p));
    return a;
}
__device__ __forceinline__ void cp_async16(uint32_t s, const void* g) {
    asm volatile("cp.async.cg.shared.global [%0], [%1], 16;" :: "r"(s), "l"(g));
}
__device__ __forceinline__ void cp_commit() { asm volatile("cp.async.commit_group;" ::: "memory"); }
#define CP_WAIT(n) asm volatile("cp.async.wait_group %0;" :: "n"(n) : "memory")

__device__ __forceinline__ void ldsm4(uint32_t* r, uint32_t addr) {
    asm volatile("ldmatrix.sync.aligned.m8n8.x4.shared.b16 {%0,%1,%2,%3}, [%4];"
        : "=r"(r[0]), "=r"(r[1]), "=r"(r[2]), "=r"(r[3]) : "r"(addr));
}
__device__ __forceinline__ void ldsm4t(uint32_t* r, uint32_t addr) {
    asm volatile("ldmatrix.sync.aligned.m8n8.x4.trans.shared.b16 {%0,%1,%2,%3}, [%4];"
        : "=r"(r[0]), "=r"(r[1]), "=r"(r[2]), "=r"(r[3]) : "r"(addr));
}
__device__ __forceinline__ void mma_bf16(float* d, const uint32_t* a, const uint32_t* b) {
    asm volatile("mma.sync.aligned.m16n8k16.row.col.f32.bf16.bf16.f32 "
        "{%0,%1,%2,%3}, {%4,%5,%6,%7}, {%8,%9}, {%0,%1,%2,%3};"
        : "+f"(d[0]), "+f"(d[1]), "+f"(d[2]), "+f"(d[3])
        : "r"(a[0]), "r"(a[1]), "r"(a[2]), "r"(a[3]), "r"(b[0]), "r"(b[1]));
}

// pack two floats into bf16x2 hi + residual lo
__device__ __forceinline__ void split_pack(float a, float b, uint32_t* hi, uint32_t* lo) {
    __nv_bfloat16 ha = __float2bfloat16(a), hb = __float2bfloat16(b);
    __nv_bfloat16 la = __float2bfloat16(a - __bfloat162float(ha));
    __nv_bfloat16 lb = __float2bfloat16(b - __bfloat162float(hb));
    *hi = ((uint32_t)__bfloat16_as_ushort(hb) << 16) | __bfloat16_as_ushort(ha);
    *lo = ((uint32_t)__bfloat16_as_ushort(lb) << 16) | __bfloat16_as_ushort(la);
}

// ======================= fp32 -> bf16 hi/lo split =======================
__device__ __forceinline__ void split2(float a, float b, __nv_bfloat162* hi, __nv_bfloat162* lo) {
    __nv_bfloat16 ha = __float2bfloat16(a), hb = __float2bfloat16(b);
    *hi = __nv_bfloat162(ha, hb);
    *lo = __nv_bfloat162(__float2bfloat16(a - __bfloat162float(ha)),
                         __float2bfloat16(b - __bfloat162float(hb)));
}

__global__ void __launch_bounds__(256) split_kernel(
    const float* __restrict__ in, __nv_bfloat16* __restrict__ hi,
    __nv_bfloat16* __restrict__ lo, int n4)
{
    int i = blockIdx.x * blockDim.x + threadIdx.x;
    if (i >= n4) return;
    float4 v = ((const float4*)in)[i];
    __nv_bfloat162 h0, l0, h1, l1;
    split2(v.x, v.y, &h0, &l0);
    split2(v.z, v.w, &h1, &l1);
    ((__nv_bfloat162*)hi)[2 * i]     = h0;
    ((__nv_bfloat162*)hi)[2 * i + 1] = h1;
    ((__nv_bfloat162*)lo)[2 * i]     = l0;
    ((__nv_bfloat162*)lo)[2 * i + 1] = l1;
}

// ---------------- RMSNorm * w * gamma + beta -> bf16 hi/lo ----------------
__global__ void __launch_bounds__(256) rmsnorm_affine_kernel(
    const float* __restrict__ x, const float* __restrict__ w,
    const float* __restrict__ gamma, const float* __restrict__ beta,
    __nv_bfloat16* __restrict__ ohi, __nv_bfloat16* __restrict__ olo)
{
    const int row = blockIdx.x;
    const float4* xr = (const float4*)(x + (size_t)row * DD);
    const int t = threadIdx.x;

    float4 v0 = xr[t];
    float4 v1 = xr[t + 256];
    float ss = v0.x*v0.x + v0.y*v0.y + v0.z*v0.z + v0.w*v0.w
             + v1.x*v1.x + v1.y*v1.y + v1.z*v1.z + v1.w*v1.w;
    #pragma unroll
    for (int d = 16; d; d >>= 1) ss += __shfl_xor_sync(0xffffffffu, ss, d);
    __shared__ float red[8];
    if ((t & 31) == 0) red[t >> 5] = ss;
    __syncthreads();
    float tot = red[0] + red[1] + red[2] + red[3] + red[4] + red[5] + red[6] + red[7];
    const float inv = rsqrtf(tot * (1.0f / DD) + 1.1920929e-07f);

    const float4* w4 = (const float4*)w;
    const float4* g4 = (const float4*)gamma;
    const float4* b4 = (const float4*)beta;
    __nv_bfloat162* oh = (__nv_bfloat162*)(ohi + (size_t)row * DD);
    __nv_bfloat162* ol = (__nv_bfloat162*)(olo + (size_t)row * DD);
    #pragma unroll
    for (int c = 0; c < 2; ++c) {
        int i = t + c * 256;
        float4 xv = (c == 0) ? v0 : v1;
        float4 wv = w4[i], gv = g4[i], bv = b4[i];
        float4 o;
        o.x = xv.x * inv * wv.x * gv.x + bv.x;
        o.y = xv.y * inv * wv.y * gv.y + bv.y;
        o.z = xv.z * inv * wv.z * gv.z + bv.z;
        o.w = xv.w * inv * wv.w * gv.w + bv.w;
        __nv_bfloat162 h0, l0, h1, l1;
        split2(o.x, o.y, &h0, &l0);
        split2(o.z, o.w, &h1, &l1);
        oh[2 * i] = h0; oh[2 * i + 1] = h1;
        ol[2 * i] = l0; ol[2 * i + 1] = l1;
    }
}

// ======================= mma.sync GEMM =======================
// C[M,N] = A[M,K] @ B[N,K]^T. CTA 128x256, BK=32, 8 warps (2Mx4N), warp 64x64.
// 4-stage cp.async ring, ONE barrier per iteration.
// MODE: 0 = fp32 out, 1 = fp32 + res, 2 = bf16 hi/lo split out,
//       3 = silu(res)*acc -> bf16 hi/lo split out (res = gate fp32)
#define BKC 32
#define STG 4
#define STAGE_B 49152
#define OFF_AH 0
#define OFF_AL 8192
#define OFF_BH 16384
#define OFF_BL 32768
#define GEMM_SMEM (STG * STAGE_B)

// swizzled byte offset for (row, 16B-unit u) in a [rows][32]bf16 tile (64B rows)
#define SWZ(r_, u_) ((uint32_t)(r_) * 64u + ((((uint32_t)(u_)) ^ (((uint32_t)(r_) >> 1) & 3u)) << 4))

template<int MODE>
__global__ void __launch_bounds__(256) gemm_mma_kernel(
    const __nv_bfloat16* __restrict__ Ahi, const __nv_bfloat16* __restrict__ Alo,
    const __nv_bfloat16* __restrict__ Bhi, const __nv_bfloat16* __restrict__ Blo,
    const float* __restrict__ res, float* __restrict__ C,
    __nv_bfloat16* __restrict__ Chi, __nv_bfloat16* __restrict__ Clo,
    int N, int K)
{
    extern __shared__ char smraw[];
    const uint32_t sb = smem_u32(smraw);
    const int tid  = threadIdx.x;
    const int lane = tid & 31;
    const int warp = tid >> 5;
    const int wm = warp >> 2, wn = warp & 3;
    const int row0 = blockIdx.y << 7;
    const int col0 = blockIdx.x << 8;

    // ---- loader mapping: thread t -> (row lr (+64,+128,+192), 16B-unit lu) ----
    const int lr = tid >> 2, lu = tid & 3;
    const uint32_t wswA0 = SWZ(lr, lu);
    const uint32_t wswA1 = SWZ(lr + 64, lu);
    const uint32_t wswB0 = wswA0;
    const uint32_t wswB1 = wswA1;
    const uint32_t wswB2 = SWZ(lr + 128, lu);
    const uint32_t wswB3 = SWZ(lr + 192, lu);
    const size_t rK64 = (size_t)64 * K;
    const __nv_bfloat16* gAh = Ahi + (size_t)(row0 + lr) * K + lu * 8;
    const __nv_bfloat16* gAl = Alo + (size_t)(row0 + lr) * K + lu * 8;
    const __nv_bfloat16* gBh = Bhi + (size_t)(col0 + lr) * K + lu * 8;
    const __nv_bfloat16* gBl = Blo + (size_t)(col0 + lr) * K + lu * 8;

#define LOAD_STAGE(kt_, st_) do {                                   \
    uint32_t b_ = sb + (uint32_t)(st_) * STAGE_B;                   \
    size_t ko_ = (size_t)(kt_) * BKC;                               \
    cp_async16(b_ + OFF_AH + wswA0, gAh + ko_);                     \
    cp_async16(b_ + OFF_AH + wswA1, gAh + rK64 + ko_);              \
    cp_async16(b_ + OFF_AL + wswA0, gAl + ko_);                     \
    cp_async16(b_ + OFF_AL + wswA1, gAl + rK64 + ko_);              \
    cp_async16(b_ + OFF_BH + wswB0, gBh + ko_);                     \
    cp_async16(b_ + OFF_BH + wswB1, gBh + rK64 + ko_);              \
    cp_async16(b_ + OFF_BH + wswB2, gBh + 2 * rK64 + ko_);          \
    cp_async16(b_ + OFF_BH + wswB3, gBh + 3 * rK64 + ko_);          \
    cp_async16(b_ + OFF_BL + wswB0, gBl + ko_);                     \
    cp_async16(b_ + OFF_BL + wswB1, gBl + rK64 + ko_);              \
    cp_async16(b_ + OFF_BL + wswB2, gBl + 2 * rK64 + ko_);          \
    cp_async16(b_ + OFF_BL + wswB3, gBl + 3 * rK64 + ko_);          \
    cp_commit();                                                    \
} while (0)

    // ---- ldmatrix per-lane smem offsets ----
    const int m8 = lane >> 3;
    uint32_t offA[4][2], offB[4][2];
    #pragma unroll
    for (int i = 0; i < 4; ++i)
        #pragma unroll
        for (int kc = 0; kc < 2; ++kc) {
            int rowa = wm * 64 + i * 16 + ((m8 & 1) << 3) + (lane & 7);
            offA[i][kc] = SWZ(rowa, kc * 2 + (m8 >> 1));
        }
    #pragma unroll
    for (int nb = 0; nb < 4; ++nb)
        #pragma unroll
        for (int kc = 0; kc < 2; ++kc) {
            int rowb = wn * 64 + nb * 16 + ((m8 >> 1) << 3) + (lane & 7);
            offB[nb][kc] = SWZ(rowb, kc * 2 + (m8 & 1));
        }

    float acc[4][8][4];
    #pragma unroll
    for (int i = 0; i < 4; ++i)
        #pragma unroll
        for (int j = 0; j < 8; ++j)
            #pragma unroll
            for (int r = 0; r < 4; ++r) acc[i][j][r] = 0.f;

    const int nk = K / BKC;

    LOAD_STAGE(0, 0);
    LOAD_STAGE(1, 1);
    LOAD_STAGE(2, 2);

    for (int kt = 0; kt < nk; ++kt) {
        const int rem = nk - 1 - kt;
        if (rem >= 2)      CP_WAIT(2);
        else if (rem == 1) CP_WAIT(1);
        else               CP_WAIT(0);
        __syncthreads();
        if (kt + 3 < nk) LOAD_STAGE(kt + 3, (kt + 3) & 3);

        const uint32_t base = sb + (uint32_t)(kt & 3) * STAGE_B;
        #pragma unroll
        for (int kc = 0; kc < 2; ++kc) {
            uint32_t ah[4][4], al[4][4];
            #pragma unroll
            for (int i = 0; i < 4; ++i) {
                ldsm4(ah[i], base + OFF_AH + offA[i][kc]);
                ldsm4(al[i], base + OFF_AL + offA[i][kc]);
            }
            #pragma unroll
            for (int nb = 0; nb < 4; ++nb) {
                uint32_t bh[4], bl[4];
                ldsm4(bh, base + OFF_BH + offB[nb][kc]);
                ldsm4(bl, base + OFF_BL + offB[nb][kc]);
                #pragma unroll
                for (int i = 0; i < 4; ++i)
                    #pragma unroll
                    for (int h2 = 0; h2 < 2; ++h2) {
                        float* a_ = acc[i][nb * 2 + h2];
                        mma_bf16(a_, ah[i], bh + 2 * h2);
                        mma_bf16(a_, ah[i], bl + 2 * h2);
                        mma_bf16(a_, al[i], bh + 2 * h2);
                    }
            }
        }
    }

    // ---- epilogue ----
    const int er = lane >> 2;
    const int ec = (lane & 3) * 2;
    #pragma unroll
    for (int i = 0; i < 4; ++i) {
        const int grow = row0 + wm * 64 + i * 16 + er;
        #pragma unroll
        for (int jf = 0; jf < 8; ++jf) {
            const int gcol = col0 + wn * 64 + jf * 8 + ec;
            float v00 = acc[i][jf][0], v01 = acc[i][jf][1];
            float v10 = acc[i][jf][2], v11 = acc[i][jf][3];
            if (MODE == 0 || MODE == 1) {
                if (MODE == 1) {
                    float2 r0 = *(const float2*)(res + (size_t)grow * N + gcol);
                    float2 r1 = *(const float2*)(res + (size_t)(grow + 8) * N + gcol);
                    v00 += r0.x; v01 += r0.y; v10 += r1.x; v11 += r1.y;
                }
                *(float2*)(C + (size_t)grow * N + gcol) = make_float2(v00, v01);
                *(float2*)(C + (size_t)(grow + 8) * N + gcol) = make_float2(v10, v11);
            } else {
                if (MODE == 3) {
                    float2 r0 = *(const float2*)(res + (size_t)grow * N + gcol);
                    float2 r1 = *(const float2*)(res + (size_t)(grow + 8) * N + gcol);
                    v00 *= r0.x / (1.f + __expf(-r0.x));
                    v01 *= r0.y / (1.f + __expf(-r0.y));
                    v10 *= r1.x / (1.f + __expf(-r1.x));
                    v11 *= r1.y / (1.f + __expf(-r1.y));
                }
                uint32_t h, l;
                split_pack(v00, v01, &h, &l);
                *(uint32_t*)(Chi + (size_t)grow * N + gcol) = h;
                *(uint32_t*)(Clo + (size_t)grow * N + gcol) = l;
                split_pack(v10, v11, &h, &l);
                *(uint32_t*)(Chi + (size_t)(grow + 8) * N + gcol) = h;
                *(uint32_t*)(Clo + (size_t)(grow + 8) * N + gcol) = l;
            }
        }
    }
#undef LOAD_STAGE
}

// ======================= tensor-core causal flash attention =======================
// BR=128 (8 warps x m16), BC=64, HD=128. Q/K/V bf16 hi/lo, 3-term mma everywhere.
// smem: Qh 32K | Ql 32K | 2 stages x (Kh,Kl,Vh,Vl 16K each = 64K) = 192KB.
#define ATT_SMEM 196608
// [128]bf16 rows = 256B = 16 units of 16B; swizzle u ^ (r&7)
#define SWA(r_, u_) ((uint32_t)(r_) * 256u + ((((uint32_t)(u_)) ^ ((uint32_t)(r_) & 7u)) << 4))

__global__ void __launch_bounds__(256) flash_attn_mma_kernel(
    const __nv_bfloat16* __restrict__ qkvh, const __nv_bfloat16* __restrict__ qkvl,
    __nv_bfloat16* __restrict__ ohi, __nv_bfloat16* __restrict__ olo)
{
    const int qt = blockIdx.x;           // q tile of 128 rows
    const int bh = blockIdx.y;
    const int b = bh >> 4, h = bh & 15;
    extern __shared__ char smraw[];
    const uint32_t sb = smem_u32(smraw);
    const uint32_t sQh = sb, sQl = sb + 32768;

    const int tid = threadIdx.x;
    const int lane = tid & 31;
    const int w = tid >> 5;
    const int bT = b * TT;
    const int hO = h * HD;
    const float sc = 0.08838834764831845f;   // 1/sqrt(128)

    // ---- load Q (128 rows x 16 units, hi+lo) ----
    {
        const int r = tid >> 1, ub = (tid & 1) * 8;
        const __nv_bfloat16* qh_row = qkvh + (size_t)(bT + qt * 128 + r) * QKVW + hO;
        const __nv_bfloat16* ql_row = qkvl + (size_t)(bT + qt * 128 + r) * QKVW + hO;
        #pragma unroll
        for (int i = 0; i < 8; ++i) {
            int u = ub + i;
            cp_async16(sQh + SWA(r, u), qh_row + u * 8);
            cp_async16(sQl + SWA(r, u), ql_row + u * 8);
        }
    }
    // ---- KV tile loader ----
    const int kvr = tid >> 2, kvu = (tid & 3) * 4;
#define LOAD_KV(jt_, s_) do {                                                        \
    uint32_t bb_ = sb + 65536u + (uint32_t)(s_) * 65536u;                            \
    size_t tok_ = (size_t)(bT + (jt_) * 64 + kvr) * QKVW + hO;                       \
    _Pragma("unroll")                                                                \
    for (int i_ = 0; i_ < 4; ++i_) {                                                 \
        int u_ = kvu + i_;                                                           \
        uint32_t so_ = SWA(kvr, u_);                                                 \
        cp_async16(bb_ + so_,          qkvh + tok_ + 2048 + u_ * 8);                 \
        cp_async16(bb_ + 16384u + so_, qkvl + tok_ + 2048 + u_ * 8);                 \
        cp_async16(bb_ + 32768u + so_, qkvh + tok_ + 4096 + u_ * 8);                 \
        cp_async16(bb_ + 49152u + so_, qkvl + tok_ + 4096 + u_ * 8);                 \
    }                                                                                \
} while (0)

    LOAD_KV(0, 0);
    cp_commit();

    // ---- ldsm offsets ----
    uint32_t offQ[8], offKB[4][8], offV[8][4];
    {
        int rq = w * 16 + ((lane >> 3) & 1) * 8 + (lane & 7);
        #pragma unroll
        for (int c = 0; c < 8; ++c) offQ[c] = SWA(rq, 2 * c + (lane >> 4));
        int rk = ((lane >> 4) << 3) + (lane & 7);
        #pragma unroll
        for (int nb = 0; nb < 4; ++nb)
            #pragma unroll
            for (int c = 0; c < 8; ++c)
                offKB[nb][c] = SWA(nb * 16 + rk, 2 * c + ((lane >> 3) & 1));
        int rv = ((lane >> 3) & 1) * 8 + (lane & 7);
        #pragma unroll
        for (int hb = 0; hb < 8; ++hb)
            #pragma unroll
            for (int c2 = 0; c2 < 4; ++c2)
                offV[hb][c2] = SWA(c2 * 16 + rv, hb * 2 + (lane >> 4));
    }

    uint32_t qh[8][4], ql[8][4];
    float Oa[16][4];
    #pragma unroll
    for (int g = 0; g < 16; ++g)
        #pragma unroll
        for (int r = 0; r < 4; ++r) Oa[g][r] = 0.f;
    float m0 = -INFINITY, m1 = -INFINITY, l0 = 0.f, l1 = 0.f;

    const int row0 = qt * 128 + w * 16 + (lane >> 2);
    const int row1 = row0 + 8;
    const int jend = 2 * qt + 1;

    for (int jt = 0; jt <= jend; ++jt) {
        const int s = jt & 1;
        if (jt < jend) { LOAD_KV(jt + 1, s ^ 1); cp_commit(); CP_WAIT(1); }
        else           { CP_WAIT(0); }
        __syncthreads();

        if (jt == 0) {
            #pragma unroll
            for (int c = 0; c < 8; ++c) {
                ldsm4(qh[c], sQh + offQ[c]);
                ldsm4(ql[c], sQl + offQ[c]);
            }
        }

        const uint32_t bK = sb + 65536u + (uint32_t)s * 65536u;
        const uint32_t bKl = bK + 16384u, bVh = bK + 32768u, bVl = bK + 49152u;

        // ---- S = Q K^T (3-term) ----
        float sf[8][4];
        #pragma unroll
        for (int i = 0; i < 8; ++i)
            #pragma unroll
            for (int r = 0; r < 4; ++r) sf[i][r] = 0.f;
        #pragma unroll
        for (int c = 0; c < 8; ++c)
            #pragma unroll
            for (int nb = 0; nb < 4; ++nb) {
                uint32_t kh[4], kl[4];
                ldsm4(kh, bK  + offKB[nb][c]);
                ldsm4(kl, bKl + offKB[nb][c]);
                mma_bf16(sf[nb * 2],     qh[c], kh);
                mma_bf16(sf[nb * 2],     qh[c], kl);
                mma_bf16(sf[nb * 2],     ql[c], kh);
                mma_bf16(sf[nb * 2 + 1], qh[c], kh + 2);
                mma_bf16(sf[nb * 2 + 1], qh[c], kl + 2);
                mma_bf16(sf[nb * 2 + 1], ql[c], kh + 2);
            }

        // ---- causal mask (only near-diagonal tiles) ----
        if (jt * 64 + 63 > qt * 128 + w * 16) {
            const int jb = jt * 64 + (lane & 3) * 2;
            #pragma unroll
            for (int i = 0; i < 8; ++i) {
                int c0 = jb + i * 8;
                if (c0     > row0) sf[i][0] = -INFINITY;
                if (c0 + 1 > row0) sf[i][1] = -INFINITY;
                if (c0     > row1) sf[i][2] = -INFINITY;
                if (c0 + 1 > row1) sf[i][3] = -INFINITY;
            }
        }

        // ---- online softmax (scaled domain) ----
        float mx0 = -INFINITY, mx1 = -INFINITY;
        #pragma unroll
        for (int i = 0; i < 8; ++i) {
            mx0 = fmaxf(mx0, fmaxf(sf[i][0], sf[i][1]));
            mx1 = fmaxf(mx1, fmaxf(sf[i][2], sf[i][3]));
        }
        mx0 *= sc; mx1 *= sc;
        mx0 = fmaxf(mx0, __shfl_xor_sync(0xffffffffu, mx0, 1));
        mx0 = fmaxf(mx0, __shfl_xor_sync(0xffffffffu, mx0, 2));
        mx1 = fmaxf(mx1, __shfl_xor_sync(0xffffffffu, mx1, 1));
        mx1 = fmaxf(mx1, __shfl_xor_sync(0xffffffffu, mx1, 2));
        float mn0 = fmaxf(m0, mx0), mn1 = fmaxf(m1, mx1);
        float al0 = __expf(m0 - mn0), al1 = __expf(m1 - mn1);
        m0 = mn0; m1 = mn1;
        float ps0 = 0.f, ps1 = 0.f;
        #pragma unroll
        for (int i = 0; i < 8; ++i) {
            sf[i][0] = __expf(fmaf(sf[i][0], sc, -m0)); ps0 += sf[i][0];
            sf[i][1] = __expf(fmaf(sf[i][1], sc, -m0)); ps0 += sf[i][1];
            sf[i][2] = __expf(fmaf(sf[i][2], sc, -m1)); ps1 += sf[i][2];
            sf[i][3] = __expf(fmaf(sf[i][3], sc, -m1)); ps1 += sf[i][3];
        }
        ps0 += __shfl_xor_sync(0xffffffffu, ps0, 1);
        ps0 += __shfl_xor_sync(0xffffffffu, ps0, 2);
        ps1 += __shfl_xor_sync(0xffffffffu, ps1, 1);
        ps1 += __shfl_xor_sync(0xffffffffu, ps1, 2);
        l0 = l0 * al0 + ps0; l1 = l1 * al1 + ps1;
        #pragma unroll
        for (int g = 0; g < 16; ++g) {
            Oa[g][0] *= al0; Oa[g][1] *= al0;
            Oa[g][2] *= al1; Oa[g][3] *= al1;
        }

        // ---- P fragments (C->A identity), hi/lo ----
        uint32_t ph[4][4], pl[4][4];
        #pragma unroll
        for (int c2 = 0; c2 < 4; ++c2) {
            split_pack(sf[2 * c2][0],     sf[2 * c2][1],     &ph[c2][0], &pl[c2][0]);
            split_pack(sf[2 * c2][2],     sf[2 * c2][3],     &ph[c2][1], &pl[c2][1]);
            split_pack(sf[2 * c2 + 1][0], sf[2 * c2 + 1][1], &ph[c2][2], &pl[c2][2]);
            split_pack(sf[2 * c2 + 1][2], sf[2 * c2 + 1][3], &ph[c2][3], &pl[c2][3]);
        }

        // ---- O += P V (3-term, V via ldmatrix.trans) ----
        #pragma unroll
        for (int c2 = 0; c2 < 4; ++c2)
            #pragma unroll
            for (int hb = 0; hb < 8; ++hb) {
                uint32_t vh[4], vl[4];
                ldsm4t(vh, bVh + offV[hb][c2]);
                ldsm4t(vl, bVl + offV[hb][c2]);
                mma_bf16(Oa[hb * 2],     ph[c2], vh);
                mma_bf16(Oa[hb * 2],     ph[c2], vl);
                mma_bf16(Oa[hb * 2],     pl[c2], vh);
                mma_bf16(Oa[hb * 2 + 1], ph[c2], vh + 2);
                mma_bf16(Oa[hb * 2 + 1], ph[c2], vl + 2);
                mma_bf16(Oa[hb * 2 + 1], pl[c2], vh + 2);
            }
        __syncthreads();
    }

    // ---- epilogue: O/l -> bf16 hi/lo ----
    const float il0 = 1.0f / l0, il1 = 1.0f / l1;
    const size_t tok0 = (size_t)(bT + row0);
    #pragma unroll
    for (int g = 0; g < 16; ++g) {
        const int col = hO + g * 8 + (lane & 3) * 2;
        uint32_t hi, lo;
        split_pack(Oa[g][0] * il0, Oa[g][1] * il0, &hi, &lo);
        *(uint32_t*)(ohi + tok0 * DD + col) = hi;
        *(uint32_t*)(olo + tok0 * DD + col) = lo;
        split_pack(Oa[g][2] * il1, Oa[g][3] * il1, &hi, &lo);
        *(uint32_t*)(ohi + (tok0 + 8) * DD + col) = hi;
        *(uint32_t*)(olo + (tok0 + 8) * DD + col) = lo;
    }
#undef LOAD_KV
}

// ---------------- launch ----------------
extern "C" void kernel_launch(void* const* d_in, const int* in_sizes, int n_in,
                              void* d_out, int out_size)
{
    const float* x      = (const float*)d_in[0];
    const float* gamma  = (const float*)d_in[1];
    const float* beta   = (const float*)d_in[2];
    const float* qkv_w  = (const float*)d_in[3];
    const float* o_w    = (const float*)d_in[4];
    const float* gate_w = (const float*)d_in[5];
    const float* up_w   = (const float*)d_in[6];
    const float* down_w = (const float*)d_in[7];
    const float* n1w    = (const float*)d_in[8];
    const float* n2w    = (const float*)d_in[9];
    float* out = (float*)d_out;

    float *x1_, *gate_;
    __nv_bfloat16 *ahi, *alo, *qkvh, *qkvl;
    __nv_bfloat16 *wqh, *wql, *woh, *wol, *wgh, *wgl, *wuh, *wul, *wdh, *wdl;
    cudaGetSymbolAddress((void**)&x1_,   g_x1);
    cudaGetSymbolAddress((void**)&gate_, g_gate);
    cudaGetSymbolAddress((void**)&ahi,  g_act_hi);
    cudaGetSymbolAddress((void**)&alo,  g_act_lo);
    cudaGetSymbolAddress((void**)&qkvh, g_qkv_hi);
    cudaGetSymbolAddress((void**)&qkvl, g_qkv_lo);
    cudaGetSymbolAddress((void**)&wqh, g_wqkv_hi);  cudaGetSymbolAddress((void**)&wql, g_wqkv_lo);
    cudaGetSymbolAddress((void**)&woh, g_wo_hi);    cudaGetSymbolAddress((void**)&wol, g_wo_lo);
    cudaGetSymbolAddress((void**)&wgh, g_wg_hi);    cudaGetSymbolAddress((void**)&wgl, g_wg_lo);
    cudaGetSymbolAddress((void**)&wuh, g_wu_hi);    cudaGetSymbolAddress((void**)&wul, g_wu_lo);
    cudaGetSymbolAddress((void**)&wdh, g_wd_hi);    cudaGetSymbolAddress((void**)&wdl, g_wd_lo);

    cudaFuncSetAttribute(flash_attn_mma_kernel,
                         cudaFuncAttributeMaxDynamicSharedMemorySize, ATT_SMEM);
    cudaFuncSetAttribute(gemm_mma_kernel<0>,
                         cudaFuncAttributeMaxDynamicSharedMemorySize, GEMM_SMEM);
    cudaFuncSetAttribute(gemm_mma_kernel<1>,
                         cudaFuncAttributeMaxDynamicSharedMemorySize, GEMM_SMEM);
    cudaFuncSetAttribute(gemm_mma_kernel<2>,
                         cudaFuncAttributeMaxDynamicSharedMemorySize, GEMM_SMEM);
    cudaFuncSetAttribute(gemm_mma_kernel<3>,
                         cudaFuncAttributeMaxDynamicSharedMemorySize, GEMM_SMEM);

    // 0. split weights to bf16 hi/lo
    {
        int n;
        n = QKVW * DD / 4; split_kernel<<<(n + 255) / 256, 256>>>(qkv_w,  wqh, wql, n);
        n = DD * DD / 4;   split_kernel<<<(n + 255) / 256, 256>>>(o_w,    woh, wol, n);
        n = FF * DD / 4;   split_kernel<<<(n + 255) / 256, 256>>>(gate_w, wgh, wgl, n);
        n = FF * DD / 4;   split_kernel<<<(n + 255) / 256, 256>>>(up_w,   wuh, wul, n);
        n = DD * FF / 4;   split_kernel<<<(n + 255) / 256, 256>>>(down_w, wdh, wdl, n);
    }

    // 1. h = rmsnorm(x, n1)*gamma+beta  -> act (bf16 hi/lo)
    rmsnorm_affine_kernel<<<MTOK, 256>>>(x, n1w, gamma, beta, ahi, alo);
    // 2. qkv = h @ qkv_w^T -> bf16 hi/lo directly
    gemm_mma_kernel<2><<<dim3(QKVW / 256, MTOK / 128), 256, GEMM_SMEM>>>(
        ahi, alo, wqh, wql, nullptr, nullptr, qkvh, qkvl, QKVW, DD);
    // 3. attention (tensor cores) -> act (bf16 hi/lo)
    flash_attn_mma_kernel<<<dim3(TT / 128, BB * HH), 256, ATT_SMEM>>>(qkvh, qkvl, ahi, alo);
    // 4. x1 = x + attn @ o_w^T
    gemm_mma_kernel<1><<<dim3(DD / 256, MTOK / 128), 256, GEMM_SMEM>>>(
        ahi, alo, woh, wol, x, x1_, nullptr, nullptr, DD, DD);
    // 5. h = rmsnorm(x1, n2)*gamma+beta -> act
    rmsnorm_affine_kernel<<<MTOK, 256>>>(x1_, n2w, gamma, beta, ahi, alo);
    // 6. gate (fp32 out)
    gemm_mma_kernel<0><<<dim3(FF / 256, MTOK / 128), 256, GEMM_SMEM>>>(
        ahi, alo, wgh, wgl, nullptr, gate_, nullptr, nullptr, FF, DD);
    // 7. up GEMM with fused silu(gate)*up -> ff (bf16 hi/lo) into qkv buffers (no aliasing!)
    gemm_mma_kernel<3><<<dim3(FF / 256, MTOK / 128), 256, GEMM_SMEM>>>(
        ahi, alo, wuh, wul, gate_, nullptr, qkvh, qkvl, FF, DD);
    // 8. out = x1 + ff @ down_w^T  (ff read from qkv buffers)
    gemm_mma_kernel<1><<<dim3(DD / 256, MTOK / 128), 256, GEMM_SMEM>>>(
        qkvh, qkvl, wdh, wdl, x1_, out, nullptr, nullptr, DD, FF);
}

// round 11
// speedup vs baseline: 1.2128x; 1.2128x over previous
#include <cuda_runtime.h>
#include <cuda_bf16.h>
#include <cuda_fp16.h>
#include <math.h>
#include <stdint.h>

// Problem dims (fixed)
#define BB   2
#define TT   2048
#define DD   2048
#define HH   16
#define HD   128
#define FF   4096
#define MTOK 4096            // B*T
#define QKVW (3*DD)          // 6144

// ---------------- scratch (static __device__, no allocations) ----------------
__device__ float g_x1  [(size_t)MTOK * DD];    // x after attention residual
__device__ float g_gate[(size_t)MTOK * FF];    // gate proj (fp32)

// hi/lo activation operand (h1 bf16 -> attn-out fp16 -> h2 fp16)
__device__ __nv_bfloat16 g_act_hi[(size_t)MTOK * DD];
__device__ __nv_bfloat16 g_act_lo[(size_t)MTOK * DD];

// qkv hi/lo bf16 (QKV GEMM out); reused as fp16 ff buffer after attention
__device__ __nv_bfloat16 g_qkv_hi[(size_t)MTOK * QKVW];
__device__ __nv_bfloat16 g_qkv_lo[(size_t)MTOK * QKVW];

// weights: qkv bf16 hi/lo; o/gate/up/down single fp16 (in *_hi)
__device__ __nv_bfloat16 g_wqkv_hi[(size_t)QKVW * DD];
__device__ __nv_bfloat16 g_wqkv_lo[(size_t)QKVW * DD];
__device__ __nv_bfloat16 g_wo_hi  [(size_t)DD * DD];
__device__ __nv_bfloat16 g_wg_hi  [(size_t)FF * DD];
__device__ __nv_bfloat16 g_wu_hi  [(size_t)FF * DD];
__device__ __nv_bfloat16 g_wd_hi  [(size_t)DD * FF];

// ======================= PTX helpers (baseline ISA only) =======================
__device__ __forceinline__ uint32_t smem_u32(const void* p) {
    uint32_t a;
    asm("{ .reg .u64 t; cvta.to.shared.u64 t, %1; cvt.u32.u64 %0, t; }" : "=r"(a) : "l"(p));
    return a;
}
__device__ __forceinline__ void cp_async16(uint32_t s, const void* g) {
    asm volatile("cp.async.cg.shared.global [%0], [%1], 16;" :: "r"(s), "l"(g));
}
__device__ __forceinline__ void cp_commit() { asm volatile("cp.async.commit_group;" ::: "memory"); }
#define CP_WAIT(n) asm volatile("cp.async.wait_group %0;" :: "n"(n) : "memory")

__device__ __forceinline__ void ldsm4(uint32_t* r, uint32_t addr) {
    asm volatile("ldmatrix.sync.aligned.m8n8.x4.shared.b16 {%0,%1,%2,%3}, [%4];"
        : "=r"(r[0]), "=r"(r[1]), "=r"(r[2]), "=r"(r[3]) : "r"(addr));
}
__device__ __forceinline__ void ldsm4t(uint32_t* r, uint32_t addr) {
    asm volatile("ldmatrix.sync.aligned.m8n8.x4.trans.shared.b16 {%0,%1,%2,%3}, [%4];"
        : "=r"(r[0]), "=r"(r[1]), "=r"(r[2]), "=r"(r[3]) : "r"(addr));
}
__device__ __forceinline__ void mma_bf16(float* d, const uint32_t* a, const uint32_t* b) {
    asm volatile("mma.sync.aligned.m16n8k16.row.col.f32.bf16.bf16.f32 "
        "{%0,%1,%2,%3}, {%4,%5,%6,%7}, {%8,%9}, {%0,%1,%2,%3};"
        : "+f"(d[0]), "+f"(d[1]), "+f"(d[2]), "+f"(d[3])
        : "r"(a[0]), "r"(a[1]), "r"(a[2]), "r"(a[3]), "r"(b[0]), "r"(b[1]));
}
__device__ __forceinline__ void mma_f16(float* d, const uint32_t* a, const uint32_t* b) {
    asm volatile("mma.sync.aligned.m16n8k16.row.col.f32.f16.f16.f32 "
        "{%0,%1,%2,%3}, {%4,%5,%6,%7}, {%8,%9}, {%0,%1,%2,%3};"
        : "+f"(d[0]), "+f"(d[1]), "+f"(d[2]), "+f"(d[3])
        : "r"(a[0]), "r"(a[1]), "r"(a[2]), "r"(a[3]), "r"(b[0]), "r"(b[1]));
}

// pack two floats into bf16x2 hi + residual bf16x2 lo
__device__ __forceinline__ void split_pack(float a, float b, uint32_t* hi, uint32_t* lo) {
    __nv_bfloat16 ha = __float2bfloat16(a), hb = __float2bfloat16(b);
    __nv_bfloat16 la = __float2bfloat16(a - __bfloat162float(ha));
    __nv_bfloat16 lb = __float2bfloat16(b - __bfloat162float(hb));
    *hi = ((uint32_t)__bfloat16_as_ushort(hb) << 16) | __bfloat16_as_ushort(ha);
    *lo = ((uint32_t)__bfloat16_as_ushort(lb) << 16) | __bfloat16_as_ushort(la);
}
// pack two floats into fp16x2 hi + residual fp16x2 lo
__device__ __forceinline__ void split_pack_h(float a, float b, uint32_t* hi, uint32_t* lo) {
    __half ha = __float2half_rn(a), hb = __float2half_rn(b);
    __half la = __float2half_rn(a - __half2float(ha));
    __half lb = __float2half_rn(b - __half2float(hb));
    *hi = ((uint32_t)__half_as_ushort(hb) << 16) | __half_as_ushort(ha);
    *lo = ((uint32_t)__half_as_ushort(lb) << 16) | __half_as_ushort(la);
}

__device__ __forceinline__ void split2(float a, float b, __nv_bfloat162* hi, __nv_bfloat162* lo) {
    __nv_bfloat16 ha = __float2bfloat16(a), hb = __float2bfloat16(b);
    *hi = __nv_bfloat162(ha, hb);
    *lo = __nv_bfloat162(__float2bfloat16(a - __bfloat162float(ha)),
                         __float2bfloat16(b - __bfloat162float(hb)));
}
__device__ __forceinline__ void split2h(float a, float b, __half2* hi, __half2* lo) {
    __half ha = __float2half_rn(a), hb = __float2half_rn(b);
    *hi = __halves2half2(ha, hb);
    *lo = __halves2half2(__float2half_rn(a - __half2float(ha)),
                         __float2half_rn(b - __half2float(hb)));
}

// fp32 -> bf16 hi/lo split (weights: qkv)
__global__ void __launch_bounds__(256) split_kernel(
    const float* __restrict__ in, __nv_bfloat16* __restrict__ hi,
    __nv_bfloat16* __restrict__ lo, int n4)
{
    int i = blockIdx.x * blockDim.x + threadIdx.x;
    if (i >= n4) return;
    float4 v = ((const float4*)in)[i];
    __nv_bfloat162 h0, l0, h1, l1;
    split2(v.x, v.y, &h0, &l0);
    split2(v.z, v.w, &h1, &l1);
    ((__nv_bfloat162*)hi)[2 * i]     = h0;
    ((__nv_bfloat162*)hi)[2 * i + 1] = h1;
    ((__nv_bfloat162*)lo)[2 * i]     = l0;
    ((__nv_bfloat162*)lo)[2 * i + 1] = l1;
}

// fp32 -> single fp16 (weights: o/gate/up/down)
__global__ void __launch_bounds__(256) cvt_h_kernel(
    const float* __restrict__ in, __half* __restrict__ out, int n4)
{
    int i = blockIdx.x * blockDim.x + threadIdx.x;
    if (i >= n4) return;
    float4 v = ((const float4*)in)[i];
    ((__half2*)out)[2 * i]     = __floats2half2_rn(v.x, v.y);
    ((__half2*)out)[2 * i + 1] = __floats2half2_rn(v.z, v.w);
}

// ---------------- RMSNorm * w * gamma + beta -> hi/lo (OF: 0=bf16, 1=fp16) ----------------
template<int OF>
__global__ void __launch_bounds__(256) rmsnorm_affine_kernel(
    const float* __restrict__ x, const float* __restrict__ w,
    const float* __restrict__ gamma, const float* __restrict__ beta,
    __nv_bfloat16* __restrict__ ohi, __nv_bfloat16* __restrict__ olo)
{
    const int row = blockIdx.x;
    const float4* xr = (const float4*)(x + (size_t)row * DD);
    const int t = threadIdx.x;

    float4 v0 = xr[t];
    float4 v1 = xr[t + 256];
    float ss = v0.x*v0.x + v0.y*v0.y + v0.z*v0.z + v0.w*v0.w
             + v1.x*v1.x + v1.y*v1.y + v1.z*v1.z + v1.w*v1.w;
    #pragma unroll
    for (int d = 16; d; d >>= 1) ss += __shfl_xor_sync(0xffffffffu, ss, d);
    __shared__ float red[8];
    if ((t & 31) == 0) red[t >> 5] = ss;
    __syncthreads();
    float tot = red[0] + red[1] + red[2] + red[3] + red[4] + red[5] + red[6] + red[7];
    const float inv = rsqrtf(tot * (1.0f / DD) + 1.1920929e-07f);

    const float4* w4 = (const float4*)w;
    const float4* g4 = (const float4*)gamma;
    const float4* b4 = (const float4*)beta;
    #pragma unroll
    for (int c = 0; c < 2; ++c) {
        int i = t + c * 256;
        float4 xv = (c == 0) ? v0 : v1;
        float4 wv = w4[i], gv = g4[i], bv = b4[i];
        float4 o;
        o.x = xv.x * inv * wv.x * gv.x + bv.x;
        o.y = xv.y * inv * wv.y * gv.y + bv.y;
        o.z = xv.z * inv * wv.z * gv.z + bv.z;
        o.w = xv.w * inv * wv.w * gv.w + bv.w;
        if (OF == 0) {
            __nv_bfloat162 h0, l0, h1, l1;
            split2(o.x, o.y, &h0, &l0);
            split2(o.z, o.w, &h1, &l1);
            ((__nv_bfloat162*)(ohi + (size_t)row * DD))[2 * i]     = h0;
            ((__nv_bfloat162*)(ohi + (size_t)row * DD))[2 * i + 1] = h1;
            ((__nv_bfloat162*)(olo + (size_t)row * DD))[2 * i]     = l0;
            ((__nv_bfloat162*)(olo + (size_t)row * DD))[2 * i + 1] = l1;
        } else {
            __half2 h0, l0, h1, l1;
            split2h(o.x, o.y, &h0, &l0);
            split2h(o.z, o.w, &h1, &l1);
            ((__half2*)(ohi + (size_t)row * DD))[2 * i]     = h0;
            ((__half2*)(ohi + (size_t)row * DD))[2 * i + 1] = h1;
            ((__half2*)(olo + (size_t)row * DD))[2 * i]     = l0;
            ((__half2*)(olo + (size_t)row * DD))[2 * i + 1] = l1;
        }
    }
}

// ======================= mma.sync GEMM =======================
// C[M,N] = A[M,K] @ B[N,K]^T. CTA 128x256, BK=32, 8 warps (2Mx4N), warp 64x64.
// 4-stage cp.async ring, ONE barrier per iteration.
// FMT: 0 = bf16 3-term (A hi/lo, B hi/lo), 1 = fp16 2-term (A hi/lo, B single)
// MODE: 0 = fp32 out, 1 = fp32 + res, 2 = hi/lo split out,
//       3 = silu(res)*acc -> hi/lo split out (res = gate fp32)
#define BKC 32
#define STG 4
#define STAGE_B 49152
#define OFF_AH 0
#define OFF_AL 8192
#define OFF_BH 16384
#define OFF_BL 32768
#define GEMM_SMEM (STG * STAGE_B)

// swizzled byte offset for (row, 16B-unit u) in a [rows][32]x16bit tile (64B rows)
#define SWZ(r_, u_) ((uint32_t)(r_) * 64u + ((((uint32_t)(u_)) ^ (((uint32_t)(r_) >> 1) & 3u)) << 4))

template<int MODE, int FMT>
__global__ void __launch_bounds__(256) gemm_mma_kernel(
    const __nv_bfloat16* __restrict__ Ahi, const __nv_bfloat16* __restrict__ Alo,
    const __nv_bfloat16* __restrict__ Bhi, const __nv_bfloat16* __restrict__ Blo,
    const float* __restrict__ res, float* __restrict__ C,
    __nv_bfloat16* __restrict__ Chi, __nv_bfloat16* __restrict__ Clo,
    int N, int K)
{
    extern __shared__ char smraw[];
    const uint32_t sb = smem_u32(smraw);
    const int tid  = threadIdx.x;
    const int lane = tid & 31;
    const int warp = tid >> 5;
    const int wm = warp >> 2, wn = warp & 3;
    const int row0 = blockIdx.y << 7;
    const int col0 = blockIdx.x << 8;

    const int lr = tid >> 2, lu = tid & 3;
    const uint32_t wswA0 = SWZ(lr, lu);
    const uint32_t wswA1 = SWZ(lr + 64, lu);
    const uint32_t wswB2 = SWZ(lr + 128, lu);
    const uint32_t wswB3 = SWZ(lr + 192, lu);
    const size_t rK64 = (size_t)64 * K;
    const __nv_bfloat16* gAh = Ahi + (size_t)(row0 + lr) * K + lu * 8;
    const __nv_bfloat16* gAl = Alo + (size_t)(row0 + lr) * K + lu * 8;
    const __nv_bfloat16* gBh = Bhi + (size_t)(col0 + lr) * K + lu * 8;
    const __nv_bfloat16* gBl = (FMT == 0) ? (Blo + (size_t)(col0 + lr) * K + lu * 8) : nullptr;

#define LOAD_STAGE(kt_, st_) do {                                   \
    uint32_t b_ = sb + (uint32_t)(st_) * STAGE_B;                   \
    size_t ko_ = (size_t)(kt_) * BKC;                               \
    cp_async16(b_ + OFF_AH + wswA0, gAh + ko_);                     \
    cp_async16(b_ + OFF_AH + wswA1, gAh + rK64 + ko_);              \
    cp_async16(b_ + OFF_AL + wswA0, gAl + ko_);                     \
    cp_async16(b_ + OFF_AL + wswA1, gAl + rK64 + ko_);              \
    cp_async16(b_ + OFF_BH + wswA0, gBh + ko_);                     \
    cp_async16(b_ + OFF_BH + wswA1, gBh + rK64 + ko_);              \
    cp_async16(b_ + OFF_BH + wswB2, gBh + 2 * rK64 + ko_);          \
    cp_async16(b_ + OFF_BH + wswB3, gBh + 3 * rK64 + ko_);          \
    if (FMT == 0) {                                                 \
        cp_async16(b_ + OFF_BL + wswA0, gBl + ko_);                 \
        cp_async16(b_ + OFF_BL + wswA1, gBl + rK64 + ko_);          \
        cp_async16(b_ + OFF_BL + wswB2, gBl + 2 * rK64 + ko_);      \
        cp_async16(b_ + OFF_BL + wswB3, gBl + 3 * rK64 + ko_);      \
    }                                                               \
    cp_commit();                                                    \
} while (0)

    const int m8 = lane >> 3;
    uint32_t offA[4][2], offB[4][2];
    #pragma unroll
    for (int i = 0; i < 4; ++i)
        #pragma unroll
        for (int kc = 0; kc < 2; ++kc) {
            int rowa = wm * 64 + i * 16 + ((m8 & 1) << 3) + (lane & 7);
            offA[i][kc] = SWZ(rowa, kc * 2 + (m8 >> 1));
        }
    #pragma unroll
    for (int nb = 0; nb < 4; ++nb)
        #pragma unroll
        for (int kc = 0; kc < 2; ++kc) {
            int rowb = wn * 64 + nb * 16 + ((m8 >> 1) << 3) + (lane & 7);
            offB[nb][kc] = SWZ(rowb, kc * 2 + (m8 & 1));
        }

    float acc[4][8][4];
    #pragma unroll
    for (int i = 0; i < 4; ++i)
        #pragma unroll
        for (int j = 0; j < 8; ++j)
            #pragma unroll
            for (int r = 0; r < 4; ++r) acc[i][j][r] = 0.f;

    const int nk = K / BKC;

    LOAD_STAGE(0, 0);
    LOAD_STAGE(1, 1);
    LOAD_STAGE(2, 2);

    for (int kt = 0; kt < nk; ++kt) {
        const int rem = nk - 1 - kt;
        if (rem >= 2)      CP_WAIT(2);
        else if (rem == 1) CP_WAIT(1);
        else               CP_WAIT(0);
        __syncthreads();
        if (kt + 3 < nk) LOAD_STAGE(kt + 3, (kt + 3) & 3);

        const uint32_t base = sb + (uint32_t)(kt & 3) * STAGE_B;
        #pragma unroll
        for (int kc = 0; kc < 2; ++kc) {
            uint32_t ah[4][4], al[4][4];
            #pragma unroll
            for (int i = 0; i < 4; ++i) {
                ldsm4(ah[i], base + OFF_AH + offA[i][kc]);
                ldsm4(al[i], base + OFF_AL + offA[i][kc]);
            }
            #pragma unroll
            for (int nb = 0; nb < 4; ++nb) {
                uint32_t bh[4], bl[4];
                ldsm4(bh, base + OFF_BH + offB[nb][kc]);
                if (FMT == 0) ldsm4(bl, base + OFF_BL + offB[nb][kc]);
                #pragma unroll
                for (int i = 0; i < 4; ++i)
                    #pragma unroll
                    for (int h2 = 0; h2 < 2; ++h2) {
                        float* a_ = acc[i][nb * 2 + h2];
                        if (FMT == 0) {
                            mma_bf16(a_, ah[i], bh + 2 * h2);
                            mma_bf16(a_, ah[i], bl + 2 * h2);
                            mma_bf16(a_, al[i], bh + 2 * h2);
                        } else {
                            mma_f16(a_, ah[i], bh + 2 * h2);
                            mma_f16(a_, al[i], bh + 2 * h2);
                        }
                    }
            }
        }
    }

    // ---- epilogue ----
    const int er = lane >> 2;
    const int ec = (lane & 3) * 2;
    #pragma unroll
    for (int i = 0; i < 4; ++i) {
        const int grow = row0 + wm * 64 + i * 16 + er;
        #pragma unroll
        for (int jf = 0; jf < 8; ++jf) {
            const int gcol = col0 + wn * 64 + jf * 8 + ec;
            float v00 = acc[i][jf][0], v01 = acc[i][jf][1];
            float v10 = acc[i][jf][2], v11 = acc[i][jf][3];
            if (MODE == 0 || MODE == 1) {
                if (MODE == 1) {
                    float2 r0 = *(const float2*)(res + (size_t)grow * N + gcol);
                    float2 r1 = *(const float2*)(res + (size_t)(grow + 8) * N + gcol);
                    v00 += r0.x; v01 += r0.y; v10 += r1.x; v11 += r1.y;
                }
                *(float2*)(C + (size_t)grow * N + gcol) = make_float2(v00, v01);
                *(float2*)(C + (size_t)(grow + 8) * N + gcol) = make_float2(v10, v11);
            } else {
                if (MODE == 3) {
                    float2 r0 = *(const float2*)(res + (size_t)grow * N + gcol);
                    float2 r1 = *(const float2*)(res + (size_t)(grow + 8) * N + gcol);
                    v00 *= r0.x / (1.f + __expf(-r0.x));
                    v01 *= r0.y / (1.f + __expf(-r0.y));
                    v10 *= r1.x / (1.f + __expf(-r1.x));
                    v11 *= r1.y / (1.f + __expf(-r1.y));
                }
                uint32_t h, l;
                if (FMT == 0) split_pack(v00, v01, &h, &l);
                else          split_pack_h(v00, v01, &h, &l);
                *(uint32_t*)(Chi + (size_t)grow * N + gcol) = h;
                *(uint32_t*)(Clo + (size_t)grow * N + gcol) = l;
                if (FMT == 0) split_pack(v10, v11, &h, &l);
                else          split_pack_h(v10, v11, &h, &l);
                *(uint32_t*)(Chi + (size_t)(grow + 8) * N + gcol) = h;
                *(uint32_t*)(Clo + (size_t)(grow + 8) * N + gcol) = l;
            }
        }
    }
#undef LOAD_STAGE
}

// ======================= tensor-core causal flash attention =======================
// BR=128 (8 warps x m16), BC=64, HD=128. Q/K/V bf16 hi/lo, 3-term mma internally.
// OUTPUT: fp16 hi/lo (feeds 2-term fp16 o-proj).
#define ATT_SMEM 196608
// [128]bf16 rows = 256B = 16 units of 16B; swizzle u ^ (r&7)
#define SWA(r_, u_) ((uint32_t)(r_) * 256u + ((((uint32_t)(u_)) ^ ((uint32_t)(r_) & 7u)) << 4))

__global__ void __launch_bounds__(256) flash_attn_mma_kernel(
    const __nv_bfloat16* __restrict__ qkvh, const __nv_bfloat16* __restrict__ qkvl,
    __nv_bfloat16* __restrict__ ohi, __nv_bfloat16* __restrict__ olo)
{
    const int qt = blockIdx.x;           // q tile of 128 rows
    const int bh = blockIdx.y;
    const int b = bh >> 4, h = bh & 15;
    extern __shared__ char smraw[];
    const uint32_t sb = smem_u32(smraw);
    const uint32_t sQh = sb, sQl = sb + 32768;

    const int tid = threadIdx.x;
    const int lane = tid & 31;
    const int w = tid >> 5;
    const int bT = b * TT;
    const int hO = h * HD;
    const float sc = 0.08838834764831845f;   // 1/sqrt(128)

    // ---- load Q (128 rows x 16 units, hi+lo) ----
    {
        const int r = tid >> 1, ub = (tid & 1) * 8;
        const __nv_bfloat16* qh_row = qkvh + (size_t)(bT + qt * 128 + r) * QKVW + hO;
        const __nv_bfloat16* ql_row = qkvl + (size_t)(bT + qt * 128 + r) * QKVW + hO;
        #pragma unroll
        for (int i = 0; i < 8; ++i) {
            int u = ub + i;
            cp_async16(sQh + SWA(r, u), qh_row + u * 8);
            cp_async16(sQl + SWA(r, u), ql_row + u * 8);
        }
    }
    // ---- KV tile loader ----
    const int kvr = tid >> 2, kvu = (tid & 3) * 4;
#define LOAD_KV(jt_, s_) do {                                                        \
    uint32_t bb_ = sb + 65536u + (uint32_t)(s_) * 65536u;                            \
    size_t tok_ = (size_t)(bT + (jt_) * 64 + kvr) * QKVW + hO;                       \
    _Pragma("unroll")                                                                \
    for (int i_ = 0; i_ < 4; ++i_) {                                                 \
        int u_ = kvu + i_;                                                           \
        uint32_t so_ = SWA(kvr, u_);                                                 \
        cp_async16(bb_ + so_,          qkvh + tok_ + 2048 + u_ * 8);                 \
        cp_async16(bb_ + 16384u + so_, qkvl + tok_ + 2048 + u_ * 8);                 \
        cp_async16(bb_ + 32768u + so_, qkvh + tok_ + 4096 + u_ * 8);                 \
        cp_async16(bb_ + 49152u + so_, qkvl + tok_ + 4096 + u_ * 8);                 \
    }                                                                                \
} while (0)

    LOAD_KV(0, 0);
    cp_commit();

    // ---- ldsm offsets ----
    uint32_t offQ[8], offKB[4][8], offV[8][4];
    {
        int rq = w * 16 + ((lane >> 3) & 1) * 8 + (lane & 7);
        #pragma unroll
        for (int c = 0; c < 8; ++c) offQ[c] = SWA(rq, 2 * c + (lane >> 4));
        int rk = ((lane >> 4) << 3) + (lane & 7);
        #pragma unroll
        for (int nb = 0; nb < 4; ++nb)
            #pragma unroll
            for (int c = 0; c < 8; ++c)
                offKB[nb][c] = SWA(nb * 16 + rk, 2 * c + ((lane >> 3) & 1));
        int rv = ((lane >> 3) & 1) * 8 + (lane & 7);
        #pragma unroll
        for (int hb = 0; hb < 8; ++hb)
            #pragma unroll
            for (int c2 = 0; c2 < 4; ++c2)
                offV[hb][c2] = SWA(c2 * 16 + rv, hb * 2 + (lane >> 4));
    }

    uint32_t qh[8][4], ql[8][4];
    float Oa[16][4];
    #pragma unroll
    for (int g = 0; g < 16; ++g)
        #pragma unroll
        for (int r = 0; r < 4; ++r) Oa[g][r] = 0.f;
    float m0 = -INFINITY, m1 = -INFINITY, l0 = 0.f, l1 = 0.f;

    const int row0 = qt * 128 + w * 16 + (lane >> 2);
    const int row1 = row0 + 8;
    const int jend = 2 * qt + 1;

    for (int jt = 0; jt <= jend; ++jt) {
        const int s = jt & 1;
        if (jt < jend) { LOAD_KV(jt + 1, s ^ 1); cp_commit(); CP_WAIT(1); }
        else           { CP_WAIT(0); }
        __syncthreads();

        if (jt == 0) {
            #pragma unroll
            for (int c = 0; c < 8; ++c) {
                ldsm4(qh[c], sQh + offQ[c]);
                ldsm4(ql[c], sQl + offQ[c]);
            }
        }

        const uint32_t bK = sb + 65536u + (uint32_t)s * 65536u;
        const uint32_t bKl = bK + 16384u, bVh = bK + 32768u, bVl = bK + 49152u;

        // ---- S = Q K^T (3-term) ----
        float sf[8][4];
        #pragma unroll
        for (int i = 0; i < 8; ++i)
            #pragma unroll
            for (int r = 0; r < 4; ++r) sf[i][r] = 0.f;
        #pragma unroll
        for (int c = 0; c < 8; ++c)
            #pragma unroll
            for (int nb = 0; nb < 4; ++nb) {
                uint32_t kh[4], kl[4];
                ldsm4(kh, bK  + offKB[nb][c]);
                ldsm4(kl, bKl + offKB[nb][c]);
                mma_bf16(sf[nb * 2],     qh[c], kh);
                mma_bf16(sf[nb * 2],     qh[c], kl);
                mma_bf16(sf[nb * 2],     ql[c], kh);
                mma_bf16(sf[nb * 2 + 1], qh[c], kh + 2);
                mma_bf16(sf[nb * 2 + 1], qh[c], kl + 2);
                mma_bf16(sf[nb * 2 + 1], ql[c], kh + 2);
            }

        // ---- causal mask (only near-diagonal tiles) ----
        if (jt * 64 + 63 > qt * 128 + w * 16) {
            const int jb = jt * 64 + (lane & 3) * 2;
            #pragma unroll
            for (int i = 0; i < 8; ++i) {
                int c0 = jb + i * 8;
                if (c0     > row0) sf[i][0] = -INFINITY;
                if (c0 + 1 > row0) sf[i][1] = -INFINITY;
                if (c0     > row1) sf[i][2] = -INFINITY;
                if (c0 + 1 > row1) sf[i][3] = -INFINITY;
            }
        }

        // ---- online softmax (scaled domain) ----
        float mx0 = -INFINITY, mx1 = -INFINITY;
        #pragma unroll
        for (int i = 0; i < 8; ++i) {
            mx0 = fmaxf(mx0, fmaxf(sf[i][0], sf[i][1]));
            mx1 = fmaxf(mx1, fmaxf(sf[i][2], sf[i][3]));
        }
        mx0 *= sc; mx1 *= sc;
        mx0 = fmaxf(mx0, __shfl_xor_sync(0xffffffffu, mx0, 1));
        mx0 = fmaxf(mx0, __shfl_xor_sync(0xffffffffu, mx0, 2));
        mx1 = fmaxf(mx1, __shfl_xor_sync(0xffffffffu, mx1, 1));
        mx1 = fmaxf(mx1, __shfl_xor_sync(0xffffffffu, mx1, 2));
        float mn0 = fmaxf(m0, mx0), mn1 = fmaxf(m1, mx1);
        float al0 = __expf(m0 - mn0), al1 = __expf(m1 - mn1);
        m0 = mn0; m1 = mn1;
        float ps0 = 0.f, ps1 = 0.f;
        #pragma unroll
        for (int i = 0; i < 8; ++i) {
            sf[i][0] = __expf(fmaf(sf[i][0], sc, -m0)); ps0 += sf[i][0];
            sf[i][1] = __expf(fmaf(sf[i][1], sc, -m0)); ps0 += sf[i][1];
            sf[i][2] = __expf(fmaf(sf[i][2], sc, -m1)); ps1 += sf[i][2];
            sf[i][3] = __expf(fmaf(sf[i][3], sc, -m1)); ps1 += sf[i][3];
        }
        ps0 += __shfl_xor_sync(0xffffffffu, ps0, 1);
        ps0 += __shfl_xor_sync(0xffffffffu, ps0, 2);
        ps1 += __shfl_xor_sync(0xffffffffu, ps1, 1);
        ps1 += __shfl_xor_sync(0xffffffffu, ps1, 2);
        l0 = l0 * al0 + ps0; l1 = l1 * al1 + ps1;
        #pragma unroll
        for (int g = 0; g < 16; ++g) {
            Oa[g][0] *= al0; Oa[g][1] *= al0;
            Oa[g][2] *= al1; Oa[g][3] *= al1;
        }

        // ---- P fragments (C->A identity), hi/lo bf16 ----
        uint32_t ph[4][4], pl[4][4];
        #pragma unroll
        for (int c2 = 0; c2 < 4; ++c2) {
            split_pack(sf[2 * c2][0],     sf[2 * c2][1],     &ph[c2][0], &pl[c2][0]);
            split_pack(sf[2 * c2][2],     sf[2 * c2][3],     &ph[c2][1], &pl[c2][1]);
            split_pack(sf[2 * c2 + 1][0], sf[2 * c2 + 1][1], &ph[c2][2], &pl[c2][2]);
            split_pack(sf[2 * c2 + 1][2], sf[2 * c2 + 1][3], &ph[c2][3], &pl[c2][3]);
        }

        // ---- O += P V (3-term, V via ldmatrix.trans) ----
        #pragma unroll
        for (int c2 = 0; c2 < 4; ++c2)
            #pragma unroll
            for (int hb = 0; hb < 8; ++hb) {
                uint32_t vh[4], vl[4];
                ldsm4t(vh, bVh + offV[hb][c2]);
                ldsm4t(vl, bVl + offV[hb][c2]);
                mma_bf16(Oa[hb * 2],     ph[c2], vh);
                mma_bf16(Oa[hb * 2],     ph[c2], vl);
                mma_bf16(Oa[hb * 2],     pl[c2], vh);
                mma_bf16(Oa[hb * 2 + 1], ph[c2], vh + 2);
                mma_bf16(Oa[hb * 2 + 1], ph[c2], vl + 2);
                mma_bf16(Oa[hb * 2 + 1], pl[c2], vh + 2);
            }
        __syncthreads();
    }

    // ---- epilogue: O/l -> fp16 hi/lo (for 2-term fp16 o-proj) ----
    const float il0 = 1.0f / l0, il1 = 1.0f / l1;
    const size_t tok0 = (size_t)(bT + row0);
    #pragma unroll
    for (int g = 0; g < 16; ++g) {
        const int col = hO + g * 8 + (lane & 3) * 2;
        uint32_t hi, lo;
        split_pack_h(Oa[g][0] * il0, Oa[g][1] * il0, &hi, &lo);
        *(uint32_t*)(ohi + tok0 * DD + col) = hi;
        *(uint32_t*)(olo + tok0 * DD + col) = lo;
        split_pack_h(Oa[g][2] * il1, Oa[g][3] * il1, &hi, &lo);
        *(uint32_t*)(ohi + (tok0 + 8) * DD + col) = hi;
        *(uint32_t*)(olo + (tok0 + 8) * DD + col) = lo;
    }
#undef LOAD_KV
}

// ---------------- launch ----------------
extern "C" void kernel_launch(void* const* d_in, const int* in_sizes, int n_in,
                              void* d_out, int out_size)
{
    const float* x      = (const float*)d_in[0];
    const float* gamma  = (const float*)d_in[1];
    const float* beta   = (const float*)d_in[2];
    const float* qkv_w  = (const float*)d_in[3];
    const float* o_w    = (const float*)d_in[4];
    const float* gate_w = (const float*)d_in[5];
    const float* up_w   = (const float*)d_in[6];
    const float* down_w = (const float*)d_in[7];
    const float* n1w    = (const float*)d_in[8];
    const float* n2w    = (const float*)d_in[9];
    float* out = (float*)d_out;

    float *x1_, *gate_;
    __nv_bfloat16 *ahi, *alo, *qkvh, *qkvl;
    __nv_bfloat16 *wqh, *wql, *woh, *wgh, *wuh, *wdh;
    cudaGetSymbolAddress((void**)&x1_,   g_x1);
    cudaGetSymbolAddress((void**)&gate_, g_gate);
    cudaGetSymbolAddress((void**)&ahi,  g_act_hi);
    cudaGetSymbolAddress((void**)&alo,  g_act_lo);
    cudaGetSymbolAddress((void**)&qkvh, g_qkv_hi);
    cudaGetSymbolAddress((void**)&qkvl, g_qkv_lo);
    cudaGetSymbolAddress((void**)&wqh, g_wqkv_hi);
    cudaGetSymbolAddress((void**)&wql, g_wqkv_lo);
    cudaGetSymbolAddress((void**)&woh, g_wo_hi);
    cudaGetSymbolAddress((void**)&wgh, g_wg_hi);
    cudaGetSymbolAddress((void**)&wuh, g_wu_hi);
    cudaGetSymbolAddress((void**)&wdh, g_wd_hi);

    cudaFuncSetAttribute(flash_attn_mma_kernel,
                         cudaFuncAttributeMaxDynamicSharedMemorySize, ATT_SMEM);
    cudaFuncSetAttribute(gemm_mma_kernel<2, 0>,
                         cudaFuncAttributeMaxDynamicSharedMemorySize, GEMM_SMEM);
    cudaFuncSetAttribute(gemm_mma_kernel<1, 1>,
                         cudaFuncAttributeMaxDynamicSharedMemorySize, GEMM_SMEM);
    cudaFuncSetAttribute(gemm_mma_kernel<0, 1>,
                         cudaFuncAttributeMaxDynamicSharedMemorySize, GEMM_SMEM);
    cudaFuncSetAttribute(gemm_mma_kernel<3, 1>,
                         cudaFuncAttributeMaxDynamicSharedMemorySize, GEMM_SMEM);

    // 0. weights: qkv -> bf16 hi/lo; o/gate/up/down -> single fp16
    {
        int n;
        n = QKVW * DD / 4; split_kernel<<<(n + 255) / 256, 256>>>(qkv_w, wqh, wql, n);
        n = DD * DD / 4;   cvt_h_kernel<<<(n + 255) / 256, 256>>>(o_w,    (__half*)woh, n);
        n = FF * DD / 4;   cvt_h_kernel<<<(n + 255) / 256, 256>>>(gate_w, (__half*)wgh, n);
        n = FF * DD / 4;   cvt_h_kernel<<<(n + 255) / 256, 256>>>(up_w,   (__half*)wuh, n);
        n = DD * FF / 4;   cvt_h_kernel<<<(n + 255) / 256, 256>>>(down_w, (__half*)wdh, n);
    }

    // 1. h = rmsnorm(x, n1)*gamma+beta -> act (bf16 hi/lo)
    rmsnorm_affine_kernel<0><<<MTOK, 256>>>(x, n1w, gamma, beta, ahi, alo);
    // 2. qkv = h @ qkv_w^T -> bf16 hi/lo (3-term bf16)
    gemm_mma_kernel<2, 0><<<dim3(QKVW / 256, MTOK / 128), 256, GEMM_SMEM>>>(
        ahi, alo, wqh, wql, nullptr, nullptr, qkvh, qkvl, QKVW, DD);
    // 3. attention -> act (fp16 hi/lo)
    flash_attn_mma_kernel<<<dim3(TT / 128, BB * HH), 256, ATT_SMEM>>>(qkvh, qkvl, ahi, alo);
    // 4. x1 = x + attn @ o_w^T (2-term fp16)
    gemm_mma_kernel<1, 1><<<dim3(DD / 256, MTOK / 128), 256, GEMM_SMEM>>>(
        ahi, alo, woh, nullptr, x, x1_, nullptr, nullptr, DD, DD);
    // 5. h = rmsnorm(x1, n2)*gamma+beta -> act (fp16 hi/lo)
    rmsnorm_affine_kernel<1><<<MTOK, 256>>>(x1_, n2w, gamma, beta, ahi, alo);
    // 6. gate (2-term fp16, fp32 out)
    gemm_mma_kernel<0, 1><<<dim3(FF / 256, MTOK / 128), 256, GEMM_SMEM>>>(
        ahi, alo, wgh, nullptr, nullptr, gate_, nullptr, nullptr, FF, DD);
    // 7. up with fused silu(gate)*up -> ff (fp16 hi/lo) into qkv buffers
    gemm_mma_kernel<3, 1><<<dim3(FF / 256, MTOK / 128), 256, GEMM_SMEM>>>(
        ahi, alo, wuh, nullptr, gate_, nullptr, qkvh, qkvl, FF, DD);
    // 8. out = x1 + ff @ down_w^T (2-term fp16)
    gemm_mma_kernel<1, 1><<<dim3(DD / 256, MTOK / 128), 256, GEMM_SMEM>>>(
        qkvh, qkvl, wdh, nullptr, x1_, out, nullptr, nullptr, DD, FF);
}

// round 12
// speedup vs baseline: 1.4083x; 1.1612x over previous
#include <cuda_runtime.h>
#include <cuda_bf16.h>
#include <cuda_fp16.h>
#include <math.h>
#include <stdint.h>

// Problem dims (fixed)
#define BB   2
#define TT   2048
#define DD   2048
#define HH   16
#define HD   128
#define FF   4096
#define MTOK 4096            // B*T
#define QKVW (3*DD)          // 6144

// ---------------- scratch (static __device__, no allocations) ----------------
__device__ float g_x1  [(size_t)MTOK * DD];    // x after attention residual
__device__ float g_gate[(size_t)MTOK * FF];    // gate proj (fp32)

// hi/lo activation operand (fp16 everywhere now)
__device__ __nv_bfloat16 g_act_hi[(size_t)MTOK * DD];
__device__ __nv_bfloat16 g_act_lo[(size_t)MTOK * DD];

// qkv hi/lo fp16 (QKV GEMM out); reused as fp16 ff buffer after attention
__device__ __nv_bfloat16 g_qkv_hi[(size_t)MTOK * QKVW];
__device__ __nv_bfloat16 g_qkv_lo[(size_t)MTOK * QKVW];

// weights: all single fp16
__device__ __nv_bfloat16 g_wqkv_hi[(size_t)QKVW * DD];
__device__ __nv_bfloat16 g_wo_hi  [(size_t)DD * DD];
__device__ __nv_bfloat16 g_wg_hi  [(size_t)FF * DD];
__device__ __nv_bfloat16 g_wu_hi  [(size_t)FF * DD];
__device__ __nv_bfloat16 g_wd_hi  [(size_t)DD * FF];

// ======================= PTX helpers (baseline ISA only) =======================
__device__ __forceinline__ uint32_t smem_u32(const void* p) {
    uint32_t a;
    asm("{ .reg .u64 t; cvta.to.shared.u64 t, %1; cvt.u32.u64 %0, t; }" : "=r"(a) : "l"(p));
    return a;
}
__device__ __forceinline__ void cp_async16(uint32_t s, const void* g) {
    asm volatile("cp.async.cg.shared.global [%0], [%1], 16;" :: "r"(s), "l"(g));
}
__device__ __forceinline__ void cp_commit() { asm volatile("cp.async.commit_group;" ::: "memory"); }
#define CP_WAIT(n) asm volatile("cp.async.wait_group %0;" :: "n"(n) : "memory")

__device__ __forceinline__ void ldsm4(uint32_t* r, uint32_t addr) {
    asm volatile("ldmatrix.sync.aligned.m8n8.x4.shared.b16 {%0,%1,%2,%3}, [%4];"
        : "=r"(r[0]), "=r"(r[1]), "=r"(r[2]), "=r"(r[3]) : "r"(addr));
}
__device__ __forceinline__ void ldsm4t(uint32_t* r, uint32_t addr) {
    asm volatile("ldmatrix.sync.aligned.m8n8.x4.trans.shared.b16 {%0,%1,%2,%3}, [%4];"
        : "=r"(r[0]), "=r"(r[1]), "=r"(r[2]), "=r"(r[3]) : "r"(addr));
}
__device__ __forceinline__ void mma_f16(float* d, const uint32_t* a, const uint32_t* b) {
    asm volatile("mma.sync.aligned.m16n8k16.row.col.f32.f16.f16.f32 "
        "{%0,%1,%2,%3}, {%4,%5,%6,%7}, {%8,%9}, {%0,%1,%2,%3};"
        : "+f"(d[0]), "+f"(d[1]), "+f"(d[2]), "+f"(d[3])
        : "r"(a[0]), "r"(a[1]), "r"(a[2]), "r"(a[3]), "r"(b[0]), "r"(b[1]));
}

// pack two floats into fp16x2 hi + residual fp16x2 lo
__device__ __forceinline__ void split_pack_h(float a, float b, uint32_t* hi, uint32_t* lo) {
    __half ha = __float2half_rn(a), hb = __float2half_rn(b);
    __half la = __float2half_rn(a - __half2float(ha));
    __half lb = __float2half_rn(b - __half2float(hb));
    *hi = ((uint32_t)__half_as_ushort(hb) << 16) | __half_as_ushort(ha);
    *lo = ((uint32_t)__half_as_ushort(lb) << 16) | __half_as_ushort(la);
}
__device__ __forceinline__ void split2h(float a, float b, __half2* hi, __half2* lo) {
    __half ha = __float2half_rn(a), hb = __float2half_rn(b);
    *hi = __halves2half2(ha, hb);
    *lo = __halves2half2(__float2half_rn(a - __half2float(ha)),
                         __float2half_rn(b - __half2float(hb)));
}

// fp32 -> single fp16 (all weights)
__global__ void __launch_bounds__(256) cvt_h_kernel(
    const float* __restrict__ in, __half* __restrict__ out, int n4)
{
    int i = blockIdx.x * blockDim.x + threadIdx.x;
    if (i >= n4) return;
    float4 v = ((const float4*)in)[i];
    ((__half2*)out)[2 * i]     = __floats2half2_rn(v.x, v.y);
    ((__half2*)out)[2 * i + 1] = __floats2half2_rn(v.z, v.w);
}

// ---------------- RMSNorm * w * gamma + beta -> fp16 hi/lo ----------------
__global__ void __launch_bounds__(256) rmsnorm_affine_kernel(
    const float* __restrict__ x, const float* __restrict__ w,
    const float* __restrict__ gamma, const float* __restrict__ beta,
    __nv_bfloat16* __restrict__ ohi, __nv_bfloat16* __restrict__ olo)
{
    const int row = blockIdx.x;
    const float4* xr = (const float4*)(x + (size_t)row * DD);
    const int t = threadIdx.x;

    float4 v0 = xr[t];
    float4 v1 = xr[t + 256];
    float ss = v0.x*v0.x + v0.y*v0.y + v0.z*v0.z + v0.w*v0.w
             + v1.x*v1.x + v1.y*v1.y + v1.z*v1.z + v1.w*v1.w;
    #pragma unroll
    for (int d = 16; d; d >>= 1) ss += __shfl_xor_sync(0xffffffffu, ss, d);
    __shared__ float red[8];
    if ((t & 31) == 0) red[t >> 5] = ss;
    __syncthreads();
    float tot = red[0] + red[1] + red[2] + red[3] + red[4] + red[5] + red[6] + red[7];
    const float inv = rsqrtf(tot * (1.0f / DD) + 1.1920929e-07f);

    const float4* w4 = (const float4*)w;
    const float4* g4 = (const float4*)gamma;
    const float4* b4 = (const float4*)beta;
    #pragma unroll
    for (int c = 0; c < 2; ++c) {
        int i = t + c * 256;
        float4 xv = (c == 0) ? v0 : v1;
        float4 wv = w4[i], gv = g4[i], bv = b4[i];
        float4 o;
        o.x = xv.x * inv * wv.x * gv.x + bv.x;
        o.y = xv.y * inv * wv.y * gv.y + bv.y;
        o.z = xv.z * inv * wv.z * gv.z + bv.z;
        o.w = xv.w * inv * wv.w * gv.w + bv.w;
        __half2 h0, l0, h1, l1;
        split2h(o.x, o.y, &h0, &l0);
        split2h(o.z, o.w, &h1, &l1);
        ((__half2*)(ohi + (size_t)row * DD))[2 * i]     = h0;
        ((__half2*)(ohi + (size_t)row * DD))[2 * i + 1] = h1;
        ((__half2*)(olo + (size_t)row * DD))[2 * i]     = l0;
        ((__half2*)(olo + (size_t)row * DD))[2 * i + 1] = l1;
    }
}

// ======================= mma.sync GEMM (fp16 2-term) =======================
// C[M,N] = A[M,K] @ B[N,K]^T. CTA 128x256, BK=32, 8 warps (2Mx4N), warp 64x64.
// A fp16 hi/lo, B single fp16: C = (Ah+Al)*B, 2 MMAs per fragment step.
// MODE: 0 = fp32 out, 1 = fp32 + res, 2 = fp16 hi/lo split out,
//       3 = silu(res)*acc -> fp16 hi/lo split out (res = gate fp32)
#define BKC 32
#define STG 4
#define STAGE_B 32768            // Ah 8K | Al 8K | B 16K
#define OFF_AH 0
#define OFF_AL 8192
#define OFF_BH 16384
#define GEMM_SMEM (STG * STAGE_B)

// swizzled byte offset for (row, 16B-unit u) in a [rows][32]x16bit tile (64B rows)
#define SWZ(r_, u_) ((uint32_t)(r_) * 64u + ((((uint32_t)(u_)) ^ (((uint32_t)(r_) >> 1) & 3u)) << 4))

template<int MODE>
__global__ void __launch_bounds__(256) gemm_mma_kernel(
    const __nv_bfloat16* __restrict__ Ahi, const __nv_bfloat16* __restrict__ Alo,
    const __nv_bfloat16* __restrict__ Bhi,
    const float* __restrict__ res, float* __restrict__ C,
    __nv_bfloat16* __restrict__ Chi, __nv_bfloat16* __restrict__ Clo,
    int N, int K)
{
    extern __shared__ char smraw[];
    const uint32_t sb = smem_u32(smraw);
    const int tid  = threadIdx.x;
    const int lane = tid & 31;
    const int warp = tid >> 5;
    const int wm = warp >> 2, wn = warp & 3;
    const int row0 = blockIdx.y << 7;
    const int col0 = blockIdx.x << 8;

    const int lr = tid >> 2, lu = tid & 3;
    const uint32_t wswA0 = SWZ(lr, lu);
    const uint32_t wswA1 = SWZ(lr + 64, lu);
    const uint32_t wswB2 = SWZ(lr + 128, lu);
    const uint32_t wswB3 = SWZ(lr + 192, lu);
    const size_t rK64 = (size_t)64 * K;
    const __nv_bfloat16* gAh = Ahi + (size_t)(row0 + lr) * K + lu * 8;
    const __nv_bfloat16* gAl = Alo + (size_t)(row0 + lr) * K + lu * 8;
    const __nv_bfloat16* gBh = Bhi + (size_t)(col0 + lr) * K + lu * 8;

#define LOAD_STAGE(kt_, st_) do {                                   \
    uint32_t b_ = sb + (uint32_t)(st_) * STAGE_B;                   \
    size_t ko_ = (size_t)(kt_) * BKC;                               \
    cp_async16(b_ + OFF_AH + wswA0, gAh + ko_);                     \
    cp_async16(b_ + OFF_AH + wswA1, gAh + rK64 + ko_);              \
    cp_async16(b_ + OFF_AL + wswA0, gAl + ko_);                     \
    cp_async16(b_ + OFF_AL + wswA1, gAl + rK64 + ko_);              \
    cp_async16(b_ + OFF_BH + wswA0, gBh + ko_);                     \
    cp_async16(b_ + OFF_BH + wswA1, gBh + rK64 + ko_);              \
    cp_async16(b_ + OFF_BH + wswB2, gBh + 2 * rK64 + ko_);          \
    cp_async16(b_ + OFF_BH + wswB3, gBh + 3 * rK64 + ko_);          \
    cp_commit();                                                    \
} while (0)

    const int m8 = lane >> 3;
    uint32_t offA[4][2], offB[4][2];
    #pragma unroll
    for (int i = 0; i < 4; ++i)
        #pragma unroll
        for (int kc = 0; kc < 2; ++kc) {
            int rowa = wm * 64 + i * 16 + ((m8 & 1) << 3) + (lane & 7);
            offA[i][kc] = SWZ(rowa, kc * 2 + (m8 >> 1));
        }
    #pragma unroll
    for (int nb = 0; nb < 4; ++nb)
        #pragma unroll
        for (int kc = 0; kc < 2; ++kc) {
            int rowb = wn * 64 + nb * 16 + ((m8 >> 1) << 3) + (lane & 7);
            offB[nb][kc] = SWZ(rowb, kc * 2 + (m8 & 1));
        }

    float acc[4][8][4];
    #pragma unroll
    for (int i = 0; i < 4; ++i)
        #pragma unroll
        for (int j = 0; j < 8; ++j)
            #pragma unroll
            for (int r = 0; r < 4; ++r) acc[i][j][r] = 0.f;

    const int nk = K / BKC;

    LOAD_STAGE(0, 0);
    LOAD_STAGE(1, 1);
    LOAD_STAGE(2, 2);

    for (int kt = 0; kt < nk; ++kt) {
        const int rem = nk - 1 - kt;
        if (rem >= 2)      CP_WAIT(2);
        else if (rem == 1) CP_WAIT(1);
        else               CP_WAIT(0);
        __syncthreads();
        if (kt + 3 < nk) LOAD_STAGE(kt + 3, (kt + 3) & 3);

        const uint32_t base = sb + (uint32_t)(kt & 3) * STAGE_B;
        #pragma unroll
        for (int kc = 0; kc < 2; ++kc) {
            uint32_t ah[4][4], al[4][4];
            #pragma unroll
            for (int i = 0; i < 4; ++i) {
                ldsm4(ah[i], base + OFF_AH + offA[i][kc]);
                ldsm4(al[i], base + OFF_AL + offA[i][kc]);
            }
            #pragma unroll
            for (int nb = 0; nb < 4; ++nb) {
                uint32_t bh[4];
                ldsm4(bh, base + OFF_BH + offB[nb][kc]);
                #pragma unroll
                for (int i = 0; i < 4; ++i)
                    #pragma unroll
                    for (int h2 = 0; h2 < 2; ++h2) {
                        float* a_ = acc[i][nb * 2 + h2];
                        mma_f16(a_, ah[i], bh + 2 * h2);
                        mma_f16(a_, al[i], bh + 2 * h2);
                    }
            }
        }
    }

    // ---- epilogue ----
    const int er = lane >> 2;
    const int ec = (lane & 3) * 2;
    #pragma unroll
    for (int i = 0; i < 4; ++i) {
        const int grow = row0 + wm * 64 + i * 16 + er;
        #pragma unroll
        for (int jf = 0; jf < 8; ++jf) {
            const int gcol = col0 + wn * 64 + jf * 8 + ec;
            float v00 = acc[i][jf][0], v01 = acc[i][jf][1];
            float v10 = acc[i][jf][2], v11 = acc[i][jf][3];
            if (MODE == 0 || MODE == 1) {
                if (MODE == 1) {
                    float2 r0 = *(const float2*)(res + (size_t)grow * N + gcol);
                    float2 r1 = *(const float2*)(res + (size_t)(grow + 8) * N + gcol);
                    v00 += r0.x; v01 += r0.y; v10 += r1.x; v11 += r1.y;
                }
                *(float2*)(C + (size_t)grow * N + gcol) = make_float2(v00, v01);
                *(float2*)(C + (size_t)(grow + 8) * N + gcol) = make_float2(v10, v11);
            } else {
                if (MODE == 3) {
                    float2 r0 = *(const float2*)(res + (size_t)grow * N + gcol);
                    float2 r1 = *(const float2*)(res + (size_t)(grow + 8) * N + gcol);
                    v00 *= r0.x / (1.f + __expf(-r0.x));
                    v01 *= r0.y / (1.f + __expf(-r0.y));
                    v10 *= r1.x / (1.f + __expf(-r1.x));
                    v11 *= r1.y / (1.f + __expf(-r1.y));
                }
                uint32_t h, l;
                split_pack_h(v00, v01, &h, &l);
                *(uint32_t*)(Chi + (size_t)grow * N + gcol) = h;
                *(uint32_t*)(Clo + (size_t)grow * N + gcol) = l;
                split_pack_h(v10, v11, &h, &l);
                *(uint32_t*)(Chi + (size_t)(grow + 8) * N + gcol) = h;
                *(uint32_t*)(Clo + (size_t)(grow + 8) * N + gcol) = l;
            }
        }
    }
#undef LOAD_STAGE
}

// ======================= tensor-core causal flash attention (fp16 2-term) =======================
// BR=128 (8 warps x m16), BC=64, HD=128.
// Q fp16 hi/lo (registers), K/V single fp16, P fp16 hi/lo. 2 MMAs per step.
// smem: Qh 32K | Ql 32K | 2 stages x (Kh 16K, Vh 16K) = 128KB.
#define ATT_SMEM 131072
// [128]fp16 rows = 256B = 16 units of 16B; swizzle u ^ (r&7)
#define SWA(r_, u_) ((uint32_t)(r_) * 256u + ((((uint32_t)(u_)) ^ ((uint32_t)(r_) & 7u)) << 4))

__global__ void __launch_bounds__(256) flash_attn_mma_kernel(
    const __nv_bfloat16* __restrict__ qkvh, const __nv_bfloat16* __restrict__ qkvl,
    __nv_bfloat16* __restrict__ ohi, __nv_bfloat16* __restrict__ olo)
{
    const int qt = blockIdx.x;           // q tile of 128 rows
    const int bh = blockIdx.y;
    const int b = bh >> 4, h = bh & 15;
    extern __shared__ char smraw[];
    const uint32_t sb = smem_u32(smraw);
    const uint32_t sQh = sb, sQl = sb + 32768;

    const int tid = threadIdx.x;
    const int lane = tid & 31;
    const int w = tid >> 5;
    const int bT = b * TT;
    const int hO = h * HD;
    const float sc = 0.08838834764831845f;   // 1/sqrt(128)

    // ---- load Q (128 rows x 16 units, hi+lo) ----
    {
        const int r = tid >> 1, ub = (tid & 1) * 8;
        const __nv_bfloat16* qh_row = qkvh + (size_t)(bT + qt * 128 + r) * QKVW + hO;
        const __nv_bfloat16* ql_row = qkvl + (size_t)(bT + qt * 128 + r) * QKVW + hO;
        #pragma unroll
        for (int i = 0; i < 8; ++i) {
            int u = ub + i;
            cp_async16(sQh + SWA(r, u), qh_row + u * 8);
            cp_async16(sQl + SWA(r, u), ql_row + u * 8);
        }
    }
    // ---- KV tile loader (hi only: K at +2048, V at +4096) ----
    const int kvr = tid >> 2, kvu = (tid & 3) * 4;
#define LOAD_KV(jt_, s_) do {                                                        \
    uint32_t bb_ = sb + 65536u + (uint32_t)(s_) * 32768u;                            \
    size_t tok_ = (size_t)(bT + (jt_) * 64 + kvr) * QKVW + hO;                       \
    _Pragma("unroll")                                                                \
    for (int i_ = 0; i_ < 4; ++i_) {                                                 \
        int u_ = kvu + i_;                                                           \
        uint32_t so_ = SWA(kvr, u_);                                                 \
        cp_async16(bb_ + so_,          qkvh + tok_ + 2048 + u_ * 8);                 \
        cp_async16(bb_ + 16384u + so_, qkvh + tok_ + 4096 + u_ * 8);                 \
    }                                                                                \
} while (0)

    LOAD_KV(0, 0);
    cp_commit();

    // ---- ldsm offsets ----
    uint32_t offQ[8], offKB[4][8], offV[8][4];
    {
        int rq = w * 16 + ((lane >> 3) & 1) * 8 + (lane & 7);
        #pragma unroll
        for (int c = 0; c < 8; ++c) offQ[c] = SWA(rq, 2 * c + (lane >> 4));
        int rk = ((lane >> 4) << 3) + (lane & 7);
        #pragma unroll
        for (int nb = 0; nb < 4; ++nb)
            #pragma unroll
            for (int c = 0; c < 8; ++c)
                offKB[nb][c] = SWA(nb * 16 + rk, 2 * c + ((lane >> 3) & 1));
        int rv = ((lane >> 3) & 1) * 8 + (lane & 7);
        #pragma unroll
        for (int hb = 0; hb < 8; ++hb)
            #pragma unroll
            for (int c2 = 0; c2 < 4; ++c2)
                offV[hb][c2] = SWA(c2 * 16 + rv, hb * 2 + (lane >> 4));
    }

    uint32_t qh[8][4], ql[8][4];
    float Oa[16][4];
    #pragma unroll
    for (int g = 0; g < 16; ++g)
        #pragma unroll
        for (int r = 0; r < 4; ++r) Oa[g][r] = 0.f;
    float m0 = -INFINITY, m1 = -INFINITY, l0 = 0.f, l1 = 0.f;

    const int row0 = qt * 128 + w * 16 + (lane >> 2);
    const int row1 = row0 + 8;
    const int jend = 2 * qt + 1;

    for (int jt = 0; jt <= jend; ++jt) {
        const int s = jt & 1;
        if (jt < jend) { LOAD_KV(jt + 1, s ^ 1); cp_commit(); CP_WAIT(1); }
        else           { CP_WAIT(0); }
        __syncthreads();

        if (jt == 0) {
            #pragma unroll
            for (int c = 0; c < 8; ++c) {
                ldsm4(qh[c], sQh + offQ[c]);
                ldsm4(ql[c], sQl + offQ[c]);
            }
        }

        const uint32_t bK = sb + 65536u + (uint32_t)s * 32768u;
        const uint32_t bVh = bK + 16384u;

        // ---- S = Q K^T (2-term: (Qh+Ql) * K) ----
        float sf[8][4];
        #pragma unroll
        for (int i = 0; i < 8; ++i)
            #pragma unroll
            for (int r = 0; r < 4; ++r) sf[i][r] = 0.f;
        #pragma unroll
        for (int c = 0; c < 8; ++c)
            #pragma unroll
            for (int nb = 0; nb < 4; ++nb) {
                uint32_t kh[4];
                ldsm4(kh, bK + offKB[nb][c]);
                mma_f16(sf[nb * 2],     qh[c], kh);
                mma_f16(sf[nb * 2],     ql[c], kh);
                mma_f16(sf[nb * 2 + 1], qh[c], kh + 2);
                mma_f16(sf[nb * 2 + 1], ql[c], kh + 2);
            }

        // ---- causal mask (only near-diagonal tiles) ----
        if (jt * 64 + 63 > qt * 128 + w * 16) {
            const int jb = jt * 64 + (lane & 3) * 2;
            #pragma unroll
            for (int i = 0; i < 8; ++i) {
                int c0 = jb + i * 8;
                if (c0     > row0) sf[i][0] = -INFINITY;
                if (c0 + 1 > row0) sf[i][1] = -INFINITY;
                if (c0     > row1) sf[i][2] = -INFINITY;
                if (c0 + 1 > row1) sf[i][3] = -INFINITY;
            }
        }

        // ---- online softmax (scaled domain) ----
        float mx0 = -INFINITY, mx1 = -INFINITY;
        #pragma unroll
        for (int i = 0; i < 8; ++i) {
            mx0 = fmaxf(mx0, fmaxf(sf[i][0], sf[i][1]));
            mx1 = fmaxf(mx1, fmaxf(sf[i][2], sf[i][3]));
        }
        mx0 *= sc; mx1 *= sc;
        mx0 = fmaxf(mx0, __shfl_xor_sync(0xffffffffu, mx0, 1));
        mx0 = fmaxf(mx0, __shfl_xor_sync(0xffffffffu, mx0, 2));
        mx1 = fmaxf(mx1, __shfl_xor_sync(0xffffffffu, mx1, 1));
        mx1 = fmaxf(mx1, __shfl_xor_sync(0xffffffffu, mx1, 2));
        float mn0 = fmaxf(m0, mx0), mn1 = fmaxf(m1, mx1);
        float al0 = __expf(m0 - mn0), al1 = __expf(m1 - mn1);
        m0 = mn0; m1 = mn1;
        float ps0 = 0.f, ps1 = 0.f;
        #pragma unroll
        for (int i = 0; i < 8; ++i) {
            sf[i][0] = __expf(fmaf(sf[i][0], sc, -m0)); ps0 += sf[i][0];
            sf[i][1] = __expf(fmaf(sf[i][1], sc, -m0)); ps0 += sf[i][1];
            sf[i][2] = __expf(fmaf(sf[i][2], sc, -m1)); ps1 += sf[i][2];
            sf[i][3] = __expf(fmaf(sf[i][3], sc, -m1)); ps1 += sf[i][3];
        }
        ps0 += __shfl_xor_sync(0xffffffffu, ps0, 1);
        ps0 += __shfl_xor_sync(0xffffffffu, ps0, 2);
        ps1 += __shfl_xor_sync(0xffffffffu, ps1, 1);
        ps1 += __shfl_xor_sync(0xffffffffu, ps1, 2);
        l0 = l0 * al0 + ps0; l1 = l1 * al1 + ps1;
        #pragma unroll
        for (int g = 0; g < 16; ++g) {
            Oa[g][0] *= al0; Oa[g][1] *= al0;
            Oa[g][2] *= al1; Oa[g][3] *= al1;
        }

        // ---- P fragments (C->A identity), hi/lo fp16 ----
        uint32_t ph[4][4], pl[4][4];
        #pragma unroll
        for (int c2 = 0; c2 < 4; ++c2) {
            split_pack_h(sf[2 * c2][0],     sf[2 * c2][1],     &ph[c2][0], &pl[c2][0]);
            split_pack_h(sf[2 * c2][2],     sf[2 * c2][3],     &ph[c2][1], &pl[c2][1]);
            split_pack_h(sf[2 * c2 + 1][0], sf[2 * c2 + 1][1], &ph[c2][2], &pl[c2][2]);
            split_pack_h(sf[2 * c2 + 1][2], sf[2 * c2 + 1][3], &ph[c2][3], &pl[c2][3]);
        }

        // ---- O += P V (2-term: (Ph+Pl) * V, V via ldmatrix.trans) ----
        #pragma unroll
        for (int c2 = 0; c2 < 4; ++c2)
            #pragma unroll
            for (int hb = 0; hb < 8; ++hb) {
                uint32_t vh[4];
                ldsm4t(vh, bVh + offV[hb][c2]);
                mma_f16(Oa[hb * 2],     ph[c2], vh);
                mma_f16(Oa[hb * 2],     pl[c2], vh);
                mma_f16(Oa[hb * 2 + 1], ph[c2], vh + 2);
                mma_f16(Oa[hb * 2 + 1], pl[c2], vh + 2);
            }
        __syncthreads();
    }

    // ---- epilogue: O/l -> fp16 hi/lo ----
    const float il0 = 1.0f / l0, il1 = 1.0f / l1;
    const size_t tok0 = (size_t)(bT + row0);
    #pragma unroll
    for (int g = 0; g < 16; ++g) {
        const int col = hO + g * 8 + (lane & 3) * 2;
        uint32_t hi, lo;
        split_pack_h(Oa[g][0] * il0, Oa[g][1] * il0, &hi, &lo);
        *(uint32_t*)(ohi + tok0 * DD + col) = hi;
        *(uint32_t*)(olo + tok0 * DD + col) = lo;
        split_pack_h(Oa[g][2] * il1, Oa[g][3] * il1, &hi, &lo);
        *(uint32_t*)(ohi + (tok0 + 8) * DD + col) = hi;
        *(uint32_t*)(olo + (tok0 + 8) * DD + col) = lo;
    }
#undef LOAD_KV
}

// ---------------- launch ----------------
extern "C" void kernel_launch(void* const* d_in, const int* in_sizes, int n_in,
                              void* d_out, int out_size)
{
    const float* x      = (const float*)d_in[0];
    const float* gamma  = (const float*)d_in[1];
    const float* beta   = (const float*)d_in[2];
    const float* qkv_w  = (const float*)d_in[3];
    const float* o_w    = (const float*)d_in[4];
    const float* gate_w = (const float*)d_in[5];
    const float* up_w   = (const float*)d_in[6];
    const float* down_w = (const float*)d_in[7];
    const float* n1w    = (const float*)d_in[8];
    const float* n2w    = (const float*)d_in[9];
    float* out = (float*)d_out;

    float *x1_, *gate_;
    __nv_bfloat16 *ahi, *alo, *qkvh, *qkvl;
    __nv_bfloat16 *wqh, *woh, *wgh, *wuh, *wdh;
    cudaGetSymbolAddress((void**)&x1_,   g_x1);
    cudaGetSymbolAddress((void**)&gate_, g_gate);
    cudaGetSymbolAddress((void**)&ahi,  g_act_hi);
    cudaGetSymbolAddress((void**)&alo,  g_act_lo);
    cudaGetSymbolAddress((void**)&qkvh, g_qkv_hi);
    cudaGetSymbolAddress((void**)&qkvl, g_qkv_lo);
    cudaGetSymbolAddress((void**)&wqh, g_wqkv_hi);
    cudaGetSymbolAddress((void**)&woh, g_wo_hi);
    cudaGetSymbolAddress((void**)&wgh, g_wg_hi);
    cudaGetSymbolAddress((void**)&wuh, g_wu_hi);
    cudaGetSymbolAddress((void**)&wdh, g_wd_hi);

    cudaFuncSetAttribute(flash_attn_mma_kernel,
                         cudaFuncAttributeMaxDynamicSharedMemorySize, ATT_SMEM);
    cudaFuncSetAttribute(gemm_mma_kernel<0>,
                         cudaFuncAttributeMaxDynamicSharedMemorySize, GEMM_SMEM);
    cudaFuncSetAttribute(gemm_mma_kernel<1>,
                         cudaFuncAttributeMaxDynamicSharedMemorySize, GEMM_SMEM);
    cudaFuncSetAttribute(gemm_mma_kernel<2>,
                         cudaFuncAttributeMaxDynamicSharedMemorySize, GEMM_SMEM);
    cudaFuncSetAttribute(gemm_mma_kernel<3>,
                         cudaFuncAttributeMaxDynamicSharedMemorySize, GEMM_SMEM);

    // 0. all weights -> single fp16
    {
        int n;
        n = QKVW * DD / 4; cvt_h_kernel<<<(n + 255) / 256, 256>>>(qkv_w,  (__half*)wqh, n);
        n = DD * DD / 4;   cvt_h_kernel<<<(n + 255) / 256, 256>>>(o_w,    (__half*)woh, n);
        n = FF * DD / 4;   cvt_h_kernel<<<(n + 255) / 256, 256>>>(gate_w, (__half*)wgh, n);
        n = FF * DD / 4;   cvt_h_kernel<<<(n + 255) / 256, 256>>>(up_w,   (__half*)wuh, n);
        n = DD * FF / 4;   cvt_h_kernel<<<(n + 255) / 256, 256>>>(down_w, (__half*)wdh, n);
    }

    // 1. h = rmsnorm(x, n1)*gamma+beta -> act (fp16 hi/lo)
    rmsnorm_affine_kernel<<<MTOK, 256>>>(x, n1w, gamma, beta, ahi, alo);
    // 2. qkv = h @ qkv_w^T -> fp16 hi/lo (2-term fp16)
    gemm_mma_kernel<2><<<dim3(QKVW / 256, MTOK / 128), 256, GEMM_SMEM>>>(
        ahi, alo, wqh, nullptr, nullptr, qkvh, qkvl, QKVW, DD);
    // 3. attention -> act (fp16 hi/lo)
    flash_attn_mma_kernel<<<dim3(TT / 128, BB * HH), 256, ATT_SMEM>>>(qkvh, qkvl, ahi, alo);
    // 4. x1 = x + attn @ o_w^T (2-term fp16)
    gemm_mma_kernel<1><<<dim3(DD / 256, MTOK / 128), 256, GEMM_SMEM>>>(
        ahi, alo, woh, x, x1_, nullptr, nullptr, DD, DD);
    // 5. h = rmsnorm(x1, n2)*gamma+beta -> act (fp16 hi/lo)
    rmsnorm_affine_kernel<<<MTOK, 256>>>(x1_, n2w, gamma, beta, ahi, alo);
    // 6. gate (2-term fp16, fp32 out)
    gemm_mma_kernel<0><<<dim3(FF / 256, MTOK / 128), 256, GEMM_SMEM>>>(
        ahi, alo, wgh, nullptr, gate_, nullptr, nullptr, FF, DD);
    // 7. up with fused silu(gate)*up -> ff (fp16 hi/lo) into qkv buffers
    gemm_mma_kernel<3><<<dim3(FF / 256, MTOK / 128), 256, GEMM_SMEM>>>(
        ahi, alo, wuh, gate_, nullptr, qkvh, qkvl, FF, DD);
    // 8. out = x1 + ff @ down_w^T (2-term fp16)
    gemm_mma_kernel<1><<<dim3(DD / 256, MTOK / 128), 256, GEMM_SMEM>>>(
        qkvh, qkvl, wdh, x1_, out, nullptr, nullptr, DD, FF);
}

// round 13
// speedup vs baseline: 2.3217x; 1.6486x over previous
#include <cuda_runtime.h>
#include <cuda_bf16.h>
#include <cuda_fp16.h>
#include <math.h>
#include <stdint.h>

// Problem dims (fixed)
#define BB   2
#define TT   2048
#define DD   2048
#define HH   16
#define HD   128
#define FF   4096
#define MTOK 4096            // B*T
#define QKVW (3*DD)          // 6144

// ---------------- scratch (static __device__, no allocations) ----------------
__device__ float g_x1  [(size_t)MTOK * DD];    // x after attention residual
__device__ float g_gate[(size_t)MTOK * FF];    // gate proj (fp32)

// fp16 activation operand (h1 -> attn-out -> h2)
__device__ __half g_act [(size_t)MTOK * DD];
// fp16 qkv (QKV GEMM out); reused as ff buffer after attention
__device__ __half g_qkv [(size_t)MTOK * QKVW];

// weights: all single fp16
__device__ __half g_wqkv[(size_t)QKVW * DD];
__device__ __half g_wo  [(size_t)DD * DD];
__device__ __half g_wg  [(size_t)FF * DD];
__device__ __half g_wu  [(size_t)FF * DD];
__device__ __half g_wd  [(size_t)DD * FF];

// ======================= PTX helpers (baseline ISA only) =======================
__device__ __forceinline__ uint32_t smem_u32(const void* p) {
    uint32_t a;
    asm("{ .reg .u64 t; cvta.to.shared.u64 t, %1; cvt.u32.u64 %0, t; }" : "=r"(a) : "l"(p));
    return a;
}
__device__ __forceinline__ void cp_async16(uint32_t s, const void* g) {
    asm volatile("cp.async.cg.shared.global [%0], [%1], 16;" :: "r"(s), "l"(g));
}
__device__ __forceinline__ void cp_commit() { asm volatile("cp.async.commit_group;" ::: "memory"); }
#define CP_WAIT(n) asm volatile("cp.async.wait_group %0;" :: "n"(n) : "memory")

__device__ __forceinline__ void ldsm4(uint32_t* r, uint32_t addr) {
    asm volatile("ldmatrix.sync.aligned.m8n8.x4.shared.b16 {%0,%1,%2,%3}, [%4];"
        : "=r"(r[0]), "=r"(r[1]), "=r"(r[2]), "=r"(r[3]) : "r"(addr));
}
__device__ __forceinline__ void ldsm4t(uint32_t* r, uint32_t addr) {
    asm volatile("ldmatrix.sync.aligned.m8n8.x4.trans.shared.b16 {%0,%1,%2,%3}, [%4];"
        : "=r"(r[0]), "=r"(r[1]), "=r"(r[2]), "=r"(r[3]) : "r"(addr));
}
__device__ __forceinline__ void mma_f16(float* d, const uint32_t* a, const uint32_t* b) {
    asm volatile("mma.sync.aligned.m16n8k16.row.col.f32.f16.f16.f32 "
        "{%0,%1,%2,%3}, {%4,%5,%6,%7}, {%8,%9}, {%0,%1,%2,%3};"
        : "+f"(d[0]), "+f"(d[1]), "+f"(d[2]), "+f"(d[3])
        : "r"(a[0]), "r"(a[1]), "r"(a[2]), "r"(a[3]), "r"(b[0]), "r"(b[1]));
}

__device__ __forceinline__ uint32_t pack_h2(float a, float b) {
    __half2 h = __floats2half2_rn(a, b);
    return *(uint32_t*)&h;
}

// fp32 -> single fp16 (weights)
__global__ void __launch_bounds__(256) cvt_h_kernel(
    const float* __restrict__ in, __half* __restrict__ out, int n4)
{
    int i = blockIdx.x * blockDim.x + threadIdx.x;
    if (i >= n4) return;
    float4 v = ((const float4*)in)[i];
    ((__half2*)out)[2 * i]     = __floats2half2_rn(v.x, v.y);
    ((__half2*)out)[2 * i + 1] = __floats2half2_rn(v.z, v.w);
}

// ---------------- RMSNorm * w * gamma + beta -> fp16 ----------------
__global__ void __launch_bounds__(256) rmsnorm_affine_kernel(
    const float* __restrict__ x, const float* __restrict__ w,
    const float* __restrict__ gamma, const float* __restrict__ beta,
    __half* __restrict__ o)
{
    const int row = blockIdx.x;
    const float4* xr = (const float4*)(x + (size_t)row * DD);
    const int t = threadIdx.x;

    float4 v0 = xr[t];
    float4 v1 = xr[t + 256];
    float ss = v0.x*v0.x + v0.y*v0.y + v0.z*v0.z + v0.w*v0.w
             + v1.x*v1.x + v1.y*v1.y + v1.z*v1.z + v1.w*v1.w;
    #pragma unroll
    for (int d = 16; d; d >>= 1) ss += __shfl_xor_sync(0xffffffffu, ss, d);
    __shared__ float red[8];
    if ((t & 31) == 0) red[t >> 5] = ss;
    __syncthreads();
    float tot = red[0] + red[1] + red[2] + red[3] + red[4] + red[5] + red[6] + red[7];
    const float inv = rsqrtf(tot * (1.0f / DD) + 1.1920929e-07f);

    const float4* w4 = (const float4*)w;
    const float4* g4 = (const float4*)gamma;
    const float4* b4 = (const float4*)beta;
    __half2* orow = (__half2*)(o + (size_t)row * DD);
    #pragma unroll
    for (int c = 0; c < 2; ++c) {
        int i = t + c * 256;
        float4 xv = (c == 0) ? v0 : v1;
        float4 wv = w4[i], gv = g4[i], bv = b4[i];
        float4 r;
        r.x = xv.x * inv * wv.x * gv.x + bv.x;
        r.y = xv.y * inv * wv.y * gv.y + bv.y;
        r.z = xv.z * inv * wv.z * gv.z + bv.z;
        r.w = xv.w * inv * wv.w * gv.w + bv.w;
        orow[2 * i]     = __floats2half2_rn(r.x, r.y);
        orow[2 * i + 1] = __floats2half2_rn(r.z, r.w);
    }
}

// ======================= mma.sync GEMM (single fp16) =======================
// C[M,N] = A[M,K] @ B[N,K]^T. CTA 128x256, BK=32, 8 warps (2Mx4N), warp 64x64.
// MODE: 0 = fp32 out, 1 = fp32 + res, 2 = fp16 out,
//       3 = silu(res)*acc -> fp16 out (res = gate fp32)
#define BKC 32
#define STG 4
#define STAGE_B 24576            // A 8K | B 16K
#define OFF_A 0
#define OFF_B 8192
#define GEMM_SMEM (STG * STAGE_B)

// swizzled byte offset for (row, 16B-unit u) in a [rows][32]x16bit tile (64B rows)
#define SWZ(r_, u_) ((uint32_t)(r_) * 64u + ((((uint32_t)(u_)) ^ (((uint32_t)(r_) >> 1) & 3u)) << 4))

template<int MODE>
__global__ void __launch_bounds__(256) gemm_mma_kernel(
    const __half* __restrict__ A, const __half* __restrict__ B,
    const float* __restrict__ res, float* __restrict__ C,
    __half* __restrict__ Ch, int N, int K)
{
    extern __shared__ char smraw[];
    const uint32_t sb = smem_u32(smraw);
    const int tid  = threadIdx.x;
    const int lane = tid & 31;
    const int warp = tid >> 5;
    const int wm = warp >> 2, wn = warp & 3;
    const int row0 = blockIdx.y << 7;
    const int col0 = blockIdx.x << 8;

    const int lr = tid >> 2, lu = tid & 3;
    const uint32_t wsw0 = SWZ(lr, lu);
    const uint32_t wsw1 = SWZ(lr + 64, lu);
    const uint32_t wsw2 = SWZ(lr + 128, lu);
    const uint32_t wsw3 = SWZ(lr + 192, lu);
    const size_t rK64 = (size_t)64 * K;
    const __half* gA = A + (size_t)(row0 + lr) * K + lu * 8;
    const __half* gB = B + (size_t)(col0 + lr) * K + lu * 8;

#define LOAD_STAGE(kt_, st_) do {                                   \
    uint32_t b_ = sb + (uint32_t)(st_) * STAGE_B;                   \
    size_t ko_ = (size_t)(kt_) * BKC;                               \
    cp_async16(b_ + OFF_A + wsw0, gA + ko_);                        \
    cp_async16(b_ + OFF_A + wsw1, gA + rK64 + ko_);                 \
    cp_async16(b_ + OFF_B + wsw0, gB + ko_);                        \
    cp_async16(b_ + OFF_B + wsw1, gB + rK64 + ko_);                 \
    cp_async16(b_ + OFF_B + wsw2, gB + 2 * rK64 + ko_);             \
    cp_async16(b_ + OFF_B + wsw3, gB + 3 * rK64 + ko_);             \
    cp_commit();                                                    \
} while (0)

    const int m8 = lane >> 3;
    uint32_t offA[4][2], offB[4][2];
    #pragma unroll
    for (int i = 0; i < 4; ++i)
        #pragma unroll
        for (int kc = 0; kc < 2; ++kc) {
            int rowa = wm * 64 + i * 16 + ((m8 & 1) << 3) + (lane & 7);
            offA[i][kc] = SWZ(rowa, kc * 2 + (m8 >> 1));
        }
    #pragma unroll
    for (int nb = 0; nb < 4; ++nb)
        #pragma unroll
        for (int kc = 0; kc < 2; ++kc) {
            int rowb = wn * 64 + nb * 16 + ((m8 >> 1) << 3) + (lane & 7);
            offB[nb][kc] = SWZ(rowb, kc * 2 + (m8 & 1));
        }

    float acc[4][8][4];
    #pragma unroll
    for (int i = 0; i < 4; ++i)
        #pragma unroll
        for (int j = 0; j < 8; ++j)
            #pragma unroll
            for (int r = 0; r < 4; ++r) acc[i][j][r] = 0.f;

    const int nk = K / BKC;

    LOAD_STAGE(0, 0);
    LOAD_STAGE(1, 1);
    LOAD_STAGE(2, 2);

    for (int kt = 0; kt < nk; ++kt) {
        const int rem = nk - 1 - kt;
        if (rem >= 2)      CP_WAIT(2);
        else if (rem == 1) CP_WAIT(1);
        else               CP_WAIT(0);
        __syncthreads();
        if (kt + 3 < nk) LOAD_STAGE(kt + 3, (kt + 3) & 3);

        const uint32_t base = sb + (uint32_t)(kt & 3) * STAGE_B;
        #pragma unroll
        for (int kc = 0; kc < 2; ++kc) {
            uint32_t ah[4][4];
            #pragma unroll
            for (int i = 0; i < 4; ++i)
                ldsm4(ah[i], base + OFF_A + offA[i][kc]);
            #pragma unroll
            for (int nb = 0; nb < 4; ++nb) {
                uint32_t bh[4];
                ldsm4(bh, base + OFF_B + offB[nb][kc]);
                #pragma unroll
                for (int i = 0; i < 4; ++i) {
                    mma_f16(acc[i][nb * 2],     ah[i], bh);
                    mma_f16(acc[i][nb * 2 + 1], ah[i], bh + 2);
                }
            }
        }
    }

    // ---- epilogue ----
    const int er = lane >> 2;
    const int ec = (lane & 3) * 2;
    #pragma unroll
    for (int i = 0; i < 4; ++i) {
        const int grow = row0 + wm * 64 + i * 16 + er;
        #pragma unroll
        for (int jf = 0; jf < 8; ++jf) {
            const int gcol = col0 + wn * 64 + jf * 8 + ec;
            float v00 = acc[i][jf][0], v01 = acc[i][jf][1];
            float v10 = acc[i][jf][2], v11 = acc[i][jf][3];
            if (MODE == 0 || MODE == 1) {
                if (MODE == 1) {
                    float2 r0 = *(const float2*)(res + (size_t)grow * N + gcol);
                    float2 r1 = *(const float2*)(res + (size_t)(grow + 8) * N + gcol);
                    v00 += r0.x; v01 += r0.y; v10 += r1.x; v11 += r1.y;
                }
                *(float2*)(C + (size_t)grow * N + gcol) = make_float2(v00, v01);
                *(float2*)(C + (size_t)(grow + 8) * N + gcol) = make_float2(v10, v11);
            } else {
                if (MODE == 3) {
                    float2 r0 = *(const float2*)(res + (size_t)grow * N + gcol);
                    float2 r1 = *(const float2*)(res + (size_t)(grow + 8) * N + gcol);
                    v00 *= r0.x / (1.f + __expf(-r0.x));
                    v01 *= r0.y / (1.f + __expf(-r0.y));
                    v10 *= r1.x / (1.f + __expf(-r1.x));
                    v11 *= r1.y / (1.f + __expf(-r1.y));
                }
                *(uint32_t*)(Ch + (size_t)grow * N + gcol) = pack_h2(v00, v01);
                *(uint32_t*)(Ch + (size_t)(grow + 8) * N + gcol) = pack_h2(v10, v11);
            }
        }
    }
#undef LOAD_STAGE
}

// ======================= tensor-core causal flash attention (single fp16) =======================
// BR=128 (8 warps x m16), BC=64, HD=128. Q regs, K/V smem, P fp16. 1 MMA per step.
// smem: Q 32K | 2 stages x (K 16K, V 16K) = 96KB.
#define ATT_SMEM 98304
// [128]fp16 rows = 256B = 16 units of 16B; swizzle u ^ (r&7)
#define SWA(r_, u_) ((uint32_t)(r_) * 256u + ((((uint32_t)(u_)) ^ ((uint32_t)(r_) & 7u)) << 4))

__global__ void __launch_bounds__(256) flash_attn_mma_kernel(
    const __half* __restrict__ qkv, __half* __restrict__ o)
{
    const int qt = blockIdx.x;           // q tile of 128 rows
    const int bh = blockIdx.y;
    const int b = bh >> 4, h = bh & 15;
    extern __shared__ char smraw[];
    const uint32_t sb = smem_u32(smraw);
    const uint32_t sQ = sb;

    const int tid = threadIdx.x;
    const int lane = tid & 31;
    const int w = tid >> 5;
    const int bT = b * TT;
    const int hO = h * HD;
    const float sc = 0.08838834764831845f;   // 1/sqrt(128)

    // ---- load Q (128 rows x 16 units) ----
    {
        const int r = tid >> 1, ub = (tid & 1) * 8;
        const __half* q_row = qkv + (size_t)(bT + qt * 128 + r) * QKVW + hO;
        #pragma unroll
        for (int i = 0; i < 8; ++i) {
            int u = ub + i;
            cp_async16(sQ + SWA(r, u), q_row + u * 8);
        }
    }
    // ---- KV tile loader ----
    const int kvr = tid >> 2, kvu = (tid & 3) * 4;
#define LOAD_KV(jt_, s_) do {                                                        \
    uint32_t bb_ = sb + 32768u + (uint32_t)(s_) * 32768u;                            \
    size_t tok_ = (size_t)(bT + (jt_) * 64 + kvr) * QKVW + hO;                       \
    _Pragma("unroll")                                                                \
    for (int i_ = 0; i_ < 4; ++i_) {                                                 \
        int u_ = kvu + i_;                                                           \
        uint32_t so_ = SWA(kvr, u_);                                                 \
        cp_async16(bb_ + so_,          qkv + tok_ + 2048 + u_ * 8);                  \
        cp_async16(bb_ + 16384u + so_, qkv + tok_ + 4096 + u_ * 8);                  \
    }                                                                                \
} while (0)

    LOAD_KV(0, 0);
    cp_commit();

    // ---- ldsm offsets ----
    uint32_t offQ[8], offKB[4][8], offV[8][4];
    {
        int rq = w * 16 + ((lane >> 3) & 1) * 8 + (lane & 7);
        #pragma unroll
        for (int c = 0; c < 8; ++c) offQ[c] = SWA(rq, 2 * c + (lane >> 4));
        int rk = ((lane >> 4) << 3) + (lane & 7);
        #pragma unroll
        for (int nb = 0; nb < 4; ++nb)
            #pragma unroll
            for (int c = 0; c < 8; ++c)
                offKB[nb][c] = SWA(nb * 16 + rk, 2 * c + ((lane >> 3) & 1));
        int rv = ((lane >> 3) & 1) * 8 + (lane & 7);
        #pragma unroll
        for (int hb = 0; hb < 8; ++hb)
            #pragma unroll
            for (int c2 = 0; c2 < 4; ++c2)
                offV[hb][c2] = SWA(c2 * 16 + rv, hb * 2 + (lane >> 4));
    }

    uint32_t qr[8][4];
    float Oa[16][4];
    #pragma unroll
    for (int g = 0; g < 16; ++g)
        #pragma unroll
        for (int r = 0; r < 4; ++r) Oa[g][r] = 0.f;
    float m0 = -INFINITY, m1 = -INFINITY, l0 = 0.f, l1 = 0.f;

    const int row0 = qt * 128 + w * 16 + (lane >> 2);
    const int row1 = row0 + 8;
    const int jend = 2 * qt + 1;

    for (int jt = 0; jt <= jend; ++jt) {
        const int s = jt & 1;
        if (jt < jend) { LOAD_KV(jt + 1, s ^ 1); cp_commit(); CP_WAIT(1); }
        else           { CP_WAIT(0); }
        __syncthreads();

        if (jt == 0) {
            #pragma unroll
            for (int c = 0; c < 8; ++c) ldsm4(qr[c], sQ + offQ[c]);
        }

        const uint32_t bK = sb + 32768u + (uint32_t)s * 32768u;
        const uint32_t bV = bK + 16384u;

        // ---- S = Q K^T ----
        float sf[8][4];
        #pragma unroll
        for (int i = 0; i < 8; ++i)
            #pragma unroll
            for (int r = 0; r < 4; ++r) sf[i][r] = 0.f;
        #pragma unroll
        for (int c = 0; c < 8; ++c)
            #pragma unroll
            for (int nb = 0; nb < 4; ++nb) {
                uint32_t kh[4];
                ldsm4(kh, bK + offKB[nb][c]);
                mma_f16(sf[nb * 2],     qr[c], kh);
                mma_f16(sf[nb * 2 + 1], qr[c], kh + 2);
            }

        // ---- causal mask (only near-diagonal tiles) ----
        if (jt * 64 + 63 > qt * 128 + w * 16) {
            const int jb = jt * 64 + (lane & 3) * 2;
            #pragma unroll
            for (int i = 0; i < 8; ++i) {
                int c0 = jb + i * 8;
                if (c0     > row0) sf[i][0] = -INFINITY;
                if (c0 + 1 > row0) sf[i][1] = -INFINITY;
                if (c0     > row1) sf[i][2] = -INFINITY;
                if (c0 + 1 > row1) sf[i][3] = -INFINITY;
            }
        }

        // ---- online softmax (scaled domain) ----
        float mx0 = -INFINITY, mx1 = -INFINITY;
        #pragma unroll
        for (int i = 0; i < 8; ++i) {
            mx0 = fmaxf(mx0, fmaxf(sf[i][0], sf[i][1]));
            mx1 = fmaxf(mx1, fmaxf(sf[i][2], sf[i][3]));
        }
        mx0 *= sc; mx1 *= sc;
        mx0 = fmaxf(mx0, __shfl_xor_sync(0xffffffffu, mx0, 1));
        mx0 = fmaxf(mx0, __shfl_xor_sync(0xffffffffu, mx0, 2));
        mx1 = fmaxf(mx1, __shfl_xor_sync(0xffffffffu, mx1, 1));
        mx1 = fmaxf(mx1, __shfl_xor_sync(0xffffffffu, mx1, 2));
        float mn0 = fmaxf(m0, mx0), mn1 = fmaxf(m1, mx1);
        float al0 = __expf(m0 - mn0), al1 = __expf(m1 - mn1);
        m0 = mn0; m1 = mn1;
        float ps0 = 0.f, ps1 = 0.f;
        #pragma unroll
        for (int i = 0; i < 8; ++i) {
            sf[i][0] = __expf(fmaf(sf[i][0], sc, -m0)); ps0 += sf[i][0];
            sf[i][1] = __expf(fmaf(sf[i][1], sc, -m0)); ps0 += sf[i][1];
            sf[i][2] = __expf(fmaf(sf[i][2], sc, -m1)); ps1 += sf[i][2];
            sf[i][3] = __expf(fmaf(sf[i][3], sc, -m1)); ps1 += sf[i][3];
        }
        ps0 += __shfl_xor_sync(0xffffffffu, ps0, 1);
        ps0 += __shfl_xor_sync(0xffffffffu, ps0, 2);
        ps1 += __shfl_xor_sync(0xffffffffu, ps1, 1);
        ps1 += __shfl_xor_sync(0xffffffffu, ps1, 2);
        l0 = l0 * al0 + ps0; l1 = l1 * al1 + ps1;
        #pragma unroll
        for (int g = 0; g < 16; ++g) {
            Oa[g][0] *= al0; Oa[g][1] *= al0;
            Oa[g][2] *= al1; Oa[g][3] *= al1;
        }

        // ---- P fragments (C->A identity), single fp16 ----
        uint32_t ph[4][4];
        #pragma unroll
        for (int c2 = 0; c2 < 4; ++c2) {
            ph[c2][0] = pack_h2(sf[2 * c2][0],     sf[2 * c2][1]);
            ph[c2][1] = pack_h2(sf[2 * c2][2],     sf[2 * c2][3]);
            ph[c2][2] = pack_h2(sf[2 * c2 + 1][0], sf[2 * c2 + 1][1]);
            ph[c2][3] = pack_h2(sf[2 * c2 + 1][2], sf[2 * c2 + 1][3]);
        }

        // ---- O += P V (V via ldmatrix.trans) ----
        #pragma unroll
        for (int c2 = 0; c2 < 4; ++c2)
            #pragma unroll
            for (int hb = 0; hb < 8; ++hb) {
                uint32_t vh[4];
                ldsm4t(vh, bV + offV[hb][c2]);
                mma_f16(Oa[hb * 2],     ph[c2], vh);
                mma_f16(Oa[hb * 2 + 1], ph[c2], vh + 2);
            }
        __syncthreads();
    }

    // ---- epilogue: O/l -> fp16 ----
    const float il0 = 1.0f / l0, il1 = 1.0f / l1;
    const size_t tok0 = (size_t)(bT + row0);
    #pragma unroll
    for (int g = 0; g < 16; ++g) {
        const int col = hO + g * 8 + (lane & 3) * 2;
        *(uint32_t*)(o + tok0 * DD + col) = pack_h2(Oa[g][0] * il0, Oa[g][1] * il0);
        *(uint32_t*)(o + (tok0 + 8) * DD + col) = pack_h2(Oa[g][2] * il1, Oa[g][3] * il1);
    }
#undef LOAD_KV
}

// ---------------- launch ----------------
extern "C" void kernel_launch(void* const* d_in, const int* in_sizes, int n_in,
                              void* d_out, int out_size)
{
    const float* x      = (const float*)d_in[0];
    const float* gamma  = (const float*)d_in[1];
    const float* beta   = (const float*)d_in[2];
    const float* qkv_w  = (const float*)d_in[3];
    const float* o_w    = (const float*)d_in[4];
    const float* gate_w = (const float*)d_in[5];
    const float* up_w   = (const float*)d_in[6];
    const float* down_w = (const float*)d_in[7];
    const float* n1w    = (const float*)d_in[8];
    const float* n2w    = (const float*)d_in[9];
    float* out = (float*)d_out;

    float *x1_, *gate_;
    __half *act_, *qkv_, *wq_, *wo_, *wg_, *wu_, *wd_;
    cudaGetSymbolAddress((void**)&x1_,   g_x1);
    cudaGetSymbolAddress((void**)&gate_, g_gate);
    cudaGetSymbolAddress((void**)&act_,  g_act);
    cudaGetSymbolAddress((void**)&qkv_,  g_qkv);
    cudaGetSymbolAddress((void**)&wq_, g_wqkv);
    cudaGetSymbolAddress((void**)&wo_, g_wo);
    cudaGetSymbolAddress((void**)&wg_, g_wg);
    cudaGetSymbolAddress((void**)&wu_, g_wu);
    cudaGetSymbolAddress((void**)&wd_, g_wd);

    cudaFuncSetAttribute(flash_attn_mma_kernel,
                         cudaFuncAttributeMaxDynamicSharedMemorySize, ATT_SMEM);
    cudaFuncSetAttribute(gemm_mma_kernel<0>,
                         cudaFuncAttributeMaxDynamicSharedMemorySize, GEMM_SMEM);
    cudaFuncSetAttribute(gemm_mma_kernel<1>,
                         cudaFuncAttributeMaxDynamicSharedMemorySize, GEMM_SMEM);
    cudaFuncSetAttribute(gemm_mma_kernel<2>,
                         cudaFuncAttributeMaxDynamicSharedMemorySize, GEMM_SMEM);
    cudaFuncSetAttribute(gemm_mma_kernel<3>,
                         cudaFuncAttributeMaxDynamicSharedMemorySize, GEMM_SMEM);

    // 0. all weights -> single fp16
    {
        int n;
        n = QKVW * DD / 4; cvt_h_kernel<<<(n + 255) / 256, 256>>>(qkv_w,  wq_, n);
        n = DD * DD / 4;   cvt_h_kernel<<<(n + 255) / 256, 256>>>(o_w,    wo_, n);
        n = FF * DD / 4;   cvt_h_kernel<<<(n + 255) / 256, 256>>>(gate_w, wg_, n);
        n = FF * DD / 4;   cvt_h_kernel<<<(n + 255) / 256, 256>>>(up_w,   wu_, n);
        n = DD * FF / 4;   cvt_h_kernel<<<(n + 255) / 256, 256>>>(down_w, wd_, n);
    }

    // 1. h = rmsnorm(x, n1)*gamma+beta -> act (fp16)
    rmsnorm_affine_kernel<<<MTOK, 256>>>(x, n1w, gamma, beta, act_);
    // 2. qkv = h @ qkv_w^T -> fp16
    gemm_mma_kernel<2><<<dim3(QKVW / 256, MTOK / 128), 256, GEMM_SMEM>>>(
        act_, wq_, nullptr, nullptr, qkv_, QKVW, DD);
    // 3. attention -> act (fp16)
    flash_attn_mma_kernel<<<dim3(TT / 128, BB * HH), 256, ATT_SMEM>>>(qkv_, act_);
    // 4. x1 = x + attn @ o_w^T
    gemm_mma_kernel<1><<<dim3(DD / 256, MTOK / 128), 256, GEMM_SMEM>>>(
        act_, wo_, x, x1_, nullptr, DD, DD);
    // 5. h = rmsnorm(x1, n2)*gamma+beta -> act (fp16)
    rmsnorm_affine_kernel<<<MTOK, 256>>>(x1_, n2w, gamma, beta, act_);
    // 6. gate (fp32 out)
    gemm_mma_kernel<0><<<dim3(FF / 256, MTOK / 128), 256, GEMM_SMEM>>>(
        act_, wg_, nullptr, gate_, nullptr, FF, DD);
    // 7. up with fused silu(gate)*up -> ff (fp16) into qkv buffer
    gemm_mma_kernel<3><<<dim3(FF / 256, MTOK / 128), 256, GEMM_SMEM>>>(
        act_, wu_, gate_, nullptr, qkv_, FF, DD);
    // 8. out = x1 + ff @ down_w^T
    gemm_mma_kernel<1><<<dim3(DD / 256, MTOK / 128), 256, GEMM_SMEM>>>(
        qkv_, wd_, x1_, out, nullptr, DD, FF);
}

// round 14
// speedup vs baseline: 2.3362x; 1.0063x over previous
#include <cuda_runtime.h>
#include <cuda_bf16.h>
#include <cuda_fp16.h>
#include <math.h>
#include <stdint.h>

// Problem dims (fixed)
#define BB   2
#define TT   2048
#define DD   2048
#define HH   16
#define HD   128
#define FF   4096
#define MTOK 4096            // B*T
#define QKVW (3*DD)          // 6144

// ---------------- scratch (static __device__, no allocations) ----------------
__device__ float g_x1  [(size_t)MTOK * DD];    // x after attention residual
__device__ __half g_gate[(size_t)MTOK * FF];   // gate proj (fp16)

// fp16 activation operand (h1 -> attn-out -> h2)
__device__ __half g_act [(size_t)MTOK * DD];
// fp16 qkv (QKV GEMM out); reused as ff buffer after attention
__device__ __half g_qkv [(size_t)MTOK * QKVW];

// weights: all single fp16
__device__ __half g_wqkv[(size_t)QKVW * DD];
__device__ __half g_wo  [(size_t)DD * DD];
__device__ __half g_wg  [(size_t)FF * DD];
__device__ __half g_wu  [(size_t)FF * DD];
__device__ __half g_wd  [(size_t)DD * FF];

// ======================= PTX helpers (baseline ISA only) =======================
__device__ __forceinline__ uint32_t smem_u32(const void* p) {
    uint32_t a;
    asm("{ .reg .u64 t; cvta.to.shared.u64 t, %1; cvt.u32.u64 %0, t; }" : "=r"(a) : "l"(p));
    return a;
}
__device__ __forceinline__ void cp_async16(uint32_t s, const void* g) {
    asm volatile("cp.async.cg.shared.global [%0], [%1], 16;" :: "r"(s), "l"(g));
}
__device__ __forceinline__ void cp_commit() { asm volatile("cp.async.commit_group;" ::: "memory"); }
#define CP_WAIT(n) asm volatile("cp.async.wait_group %0;" :: "n"(n) : "memory")

__device__ __forceinline__ void ldsm4(uint32_t* r, uint32_t addr) {
    asm volatile("ldmatrix.sync.aligned.m8n8.x4.shared.b16 {%0,%1,%2,%3}, [%4];"
        : "=r"(r[0]), "=r"(r[1]), "=r"(r[2]), "=r"(r[3]) : "r"(addr));
}
__device__ __forceinline__ void ldsm4t(uint32_t* r, uint32_t addr) {
    asm volatile("ldmatrix.sync.aligned.m8n8.x4.trans.shared.b16 {%0,%1,%2,%3}, [%4];"
        : "=r"(r[0]), "=r"(r[1]), "=r"(r[2]), "=r"(r[3]) : "r"(addr));
}
__device__ __forceinline__ void mma_f16(float* d, const uint32_t* a, const uint32_t* b) {
    asm volatile("mma.sync.aligned.m16n8k16.row.col.f32.f16.f16.f32 "
        "{%0,%1,%2,%3}, {%4,%5,%6,%7}, {%8,%9}, {%0,%1,%2,%3};"
        : "+f"(d[0]), "+f"(d[1]), "+f"(d[2]), "+f"(d[3])
        : "r"(a[0]), "r"(a[1]), "r"(a[2]), "r"(a[3]), "r"(b[0]), "r"(b[1]));
}

__device__ __forceinline__ uint32_t pack_h2(float a, float b) {
    __half2 h = __floats2half2_rn(a, b);
    return *(uint32_t*)&h;
}

// fp32 -> single fp16 (weights)
__global__ void __launch_bounds__(256) cvt_h_kernel(
    const float* __restrict__ in, __half* __restrict__ out, int n4)
{
    int i = blockIdx.x * blockDim.x + threadIdx.x;
    if (i >= n4) return;
    float4 v = ((const float4*)in)[i];
    ((__half2*)out)[2 * i]     = __floats2half2_rn(v.x, v.y);
    ((__half2*)out)[2 * i + 1] = __floats2half2_rn(v.z, v.w);
}

// ---------------- RMSNorm * w * gamma + beta -> fp16 ----------------
__global__ void __launch_bounds__(256) rmsnorm_affine_kernel(
    const float* __restrict__ x, const float* __restrict__ w,
    const float* __restrict__ gamma, const float* __restrict__ beta,
    __half* __restrict__ o)
{
    const int row = blockIdx.x;
    const float4* xr = (const float4*)(x + (size_t)row * DD);
    const int t = threadIdx.x;

    float4 v0 = xr[t];
    float4 v1 = xr[t + 256];
    float ss = v0.x*v0.x + v0.y*v0.y + v0.z*v0.z + v0.w*v0.w
             + v1.x*v1.x + v1.y*v1.y + v1.z*v1.z + v1.w*v1.w;
    #pragma unroll
    for (int d = 16; d; d >>= 1) ss += __shfl_xor_sync(0xffffffffu, ss, d);
    __shared__ float red[8];
    if ((t & 31) == 0) red[t >> 5] = ss;
    __syncthreads();
    float tot = red[0] + red[1] + red[2] + red[3] + red[4] + red[5] + red[6] + red[7];
    const float inv = rsqrtf(tot * (1.0f / DD) + 1.1920929e-07f);

    const float4* w4 = (const float4*)w;
    const float4* g4 = (const float4*)gamma;
    const float4* b4 = (const float4*)beta;
    __half2* orow = (__half2*)(o + (size_t)row * DD);
    #pragma unroll
    for (int c = 0; c < 2; ++c) {
        int i = t + c * 256;
        float4 xv = (c == 0) ? v0 : v1;
        float4 wv = w4[i], gv = g4[i], bv = b4[i];
        float4 r;
        r.x = xv.x * inv * wv.x * gv.x + bv.x;
        r.y = xv.y * inv * wv.y * gv.y + bv.y;
        r.z = xv.z * inv * wv.z * gv.z + bv.z;
        r.w = xv.w * inv * wv.w * gv.w + bv.w;
        orow[2 * i]     = __floats2half2_rn(r.x, r.y);
        orow[2 * i + 1] = __floats2half2_rn(r.z, r.w);
    }
}

// ======================= mma.sync GEMM (single fp16) =======================
// C[M,N] = A[M,K] @ B[N,K]^T. CTA 128x256, BK=32, 8 warps (2Mx4N), warp 64x64.
// MODE: 1 = fp32 + res(fp32), 2 = fp16 out, 3 = silu(res16)*acc -> fp16 out
#define BKC 32
#define STG 4
#define STAGE_B 24576            // A 8K | B 16K
#define OFF_A 0
#define OFF_B 8192
#define GEMM_SMEM (STG * STAGE_B)

// swizzled byte offset for (row, 16B-unit u) in a [rows][32]x16bit tile (64B rows)
#define SWZ(r_, u_) ((uint32_t)(r_) * 64u + ((((uint32_t)(u_)) ^ (((uint32_t)(r_) >> 1) & 3u)) << 4))

template<int MODE>
__global__ void __launch_bounds__(256) gemm_mma_kernel(
    const __half* __restrict__ A, const __half* __restrict__ B,
    const float* __restrict__ res, float* __restrict__ C,
    __half* __restrict__ Ch, const __half* __restrict__ resh,
    int N, int K)
{
    extern __shared__ char smraw[];
    const uint32_t sb = smem_u32(smraw);
    const int tid  = threadIdx.x;
    const int lane = tid & 31;
    const int warp = tid >> 5;
    const int wm = warp >> 2, wn = warp & 3;
    const int row0 = blockIdx.y << 7;
    const int col0 = blockIdx.x << 8;

    const int lr = tid >> 2, lu = tid & 3;
    const uint32_t wsw0 = SWZ(lr, lu);
    const uint32_t wsw1 = SWZ(lr + 64, lu);
    const uint32_t wsw2 = SWZ(lr + 128, lu);
    const uint32_t wsw3 = SWZ(lr + 192, lu);
    const size_t rK64 = (size_t)64 * K;
    const __half* gA = A + (size_t)(row0 + lr) * K + lu * 8;
    const __half* gB = B + (size_t)(col0 + lr) * K + lu * 8;

#define LOAD_STAGE(kt_, st_) do {                                   \
    uint32_t b_ = sb + (uint32_t)(st_) * STAGE_B;                   \
    size_t ko_ = (size_t)(kt_) * BKC;                               \
    cp_async16(b_ + OFF_A + wsw0, gA + ko_);                        \
    cp_async16(b_ + OFF_A + wsw1, gA + rK64 + ko_);                 \
    cp_async16(b_ + OFF_B + wsw0, gB + ko_);                        \
    cp_async16(b_ + OFF_B + wsw1, gB + rK64 + ko_);                 \
    cp_async16(b_ + OFF_B + wsw2, gB + 2 * rK64 + ko_);             \
    cp_async16(b_ + OFF_B + wsw3, gB + 3 * rK64 + ko_);             \
    cp_commit();                                                    \
} while (0)

    const int m8 = lane >> 3;
    uint32_t offA[4][2], offB[4][2];
    #pragma unroll
    for (int i = 0; i < 4; ++i)
        #pragma unroll
        for (int kc = 0; kc < 2; ++kc) {
            int rowa = wm * 64 + i * 16 + ((m8 & 1) << 3) + (lane & 7);
            offA[i][kc] = SWZ(rowa, kc * 2 + (m8 >> 1));
        }
    #pragma unroll
    for (int nb = 0; nb < 4; ++nb)
        #pragma unroll
        for (int kc = 0; kc < 2; ++kc) {
            int rowb = wn * 64 + nb * 16 + ((m8 >> 1) << 3) + (lane & 7);
            offB[nb][kc] = SWZ(rowb, kc * 2 + (m8 & 1));
        }

    float acc[4][8][4];
    #pragma unroll
    for (int i = 0; i < 4; ++i)
        #pragma unroll
        for (int j = 0; j < 8; ++j)
            #pragma unroll
            for (int r = 0; r < 4; ++r) acc[i][j][r] = 0.f;

    const int nk = K / BKC;

    LOAD_STAGE(0, 0);
    LOAD_STAGE(1, 1);
    LOAD_STAGE(2, 2);

    for (int kt = 0; kt < nk; ++kt) {
        const int rem = nk - 1 - kt;
        if (rem >= 2)      CP_WAIT(2);
        else if (rem == 1) CP_WAIT(1);
        else               CP_WAIT(0);
        __syncthreads();
        if (kt + 3 < nk) LOAD_STAGE(kt + 3, (kt + 3) & 3);

        const uint32_t base = sb + (uint32_t)(kt & 3) * STAGE_B;
        #pragma unroll
        for (int kc = 0; kc < 2; ++kc) {
            uint32_t ah[4][4];
            #pragma unroll
            for (int i = 0; i < 4; ++i)
                ldsm4(ah[i], base + OFF_A + offA[i][kc]);
            #pragma unroll
            for (int nb = 0; nb < 4; ++nb) {
                uint32_t bh[4];
                ldsm4(bh, base + OFF_B + offB[nb][kc]);
                #pragma unroll
                for (int i = 0; i < 4; ++i) {
                    mma_f16(acc[i][nb * 2],     ah[i], bh);
                    mma_f16(acc[i][nb * 2 + 1], ah[i], bh + 2);
                }
            }
        }
    }

    // ---- epilogue ----
    const int er = lane >> 2;
    const int ec = (lane & 3) * 2;
    #pragma unroll
    for (int i = 0; i < 4; ++i) {
        const int grow = row0 + wm * 64 + i * 16 + er;
        #pragma unroll
        for (int jf = 0; jf < 8; ++jf) {
            const int gcol = col0 + wn * 64 + jf * 8 + ec;
            float v00 = acc[i][jf][0], v01 = acc[i][jf][1];
            float v10 = acc[i][jf][2], v11 = acc[i][jf][3];
            if (MODE == 1) {
                float2 r0 = *(const float2*)(res + (size_t)grow * N + gcol);
                float2 r1 = *(const float2*)(res + (size_t)(grow + 8) * N + gcol);
                v00 += r0.x; v01 += r0.y; v10 += r1.x; v11 += r1.y;
                *(float2*)(C + (size_t)grow * N + gcol) = make_float2(v00, v01);
                *(float2*)(C + (size_t)(grow + 8) * N + gcol) = make_float2(v10, v11);
            } else {
                if (MODE == 3) {
                    uint32_t u0 = *(const uint32_t*)(resh + (size_t)grow * N + gcol);
                    uint32_t u1 = *(const uint32_t*)(resh + (size_t)(grow + 8) * N + gcol);
                    float2 r0 = __half22float2(*(__half2*)&u0);
                    float2 r1 = __half22float2(*(__half2*)&u1);
                    v00 *= r0.x / (1.f + __expf(-r0.x));
                    v01 *= r0.y / (1.f + __expf(-r0.y));
                    v10 *= r1.x / (1.f + __expf(-r1.x));
                    v11 *= r1.y / (1.f + __expf(-r1.y));
                }
                *(uint32_t*)(Ch + (size_t)grow * N + gcol) = pack_h2(v00, v01);
                *(uint32_t*)(Ch + (size_t)(grow + 8) * N + gcol) = pack_h2(v10, v11);
            }
        }
    }
#undef LOAD_STAGE
}

// ======================= tensor-core causal flash attention (fp16, BC=128) =======================
// BR=128 (8 warps x m16), BC=128, HD=128. Q regs, K/V smem double-buffered.
// smem: Q 32K | 2 stages x (K 32K, V 32K) = 160KB.
#define ATT_SMEM 163840
// [128]fp16 rows = 256B = 16 units of 16B; swizzle u ^ (r&7)
#define SWA(r_, u_) ((uint32_t)(r_) * 256u + ((((uint32_t)(u_)) ^ ((uint32_t)(r_) & 7u)) << 4))

__global__ void __launch_bounds__(256) flash_attn_mma_kernel(
    const __half* __restrict__ qkv, __half* __restrict__ o)
{
    const int qt = blockIdx.x;           // q tile of 128 rows
    const int bh = blockIdx.y;
    const int b = bh >> 4, h = bh & 15;
    extern __shared__ char smraw[];
    const uint32_t sb = smem_u32(smraw);
    const uint32_t sQ = sb;

    const int tid = threadIdx.x;
    const int lane = tid & 31;
    const int w = tid >> 5;
    const int bT = b * TT;
    const int hO = h * HD;
    const float sc = 0.08838834764831845f;   // 1/sqrt(128)

    // ---- load Q (128 rows x 16 units) ----
    {
        const int r = tid >> 1, ub = (tid & 1) * 8;
        const __half* q_row = qkv + (size_t)(bT + qt * 128 + r) * QKVW + hO;
        #pragma unroll
        for (int i = 0; i < 8; ++i) {
            int u = ub + i;
            cp_async16(sQ + SWA(r, u), q_row + u * 8);
        }
    }
    // ---- KV tile loader: 128 rows of K and V ----
    const int kvr = tid >> 1, kvu = (tid & 1) * 8;
#define LOAD_KV(jt_, s_) do {                                                        \
    uint32_t bb_ = sb + 32768u + (uint32_t)(s_) * 65536u;                            \
    size_t tok_ = (size_t)(bT + (jt_) * 128 + kvr) * QKVW + hO;                      \
    _Pragma("unroll")                                                                \
    for (int i_ = 0; i_ < 8; ++i_) {                                                 \
        int u_ = kvu + i_;                                                           \
        uint32_t so_ = SWA(kvr, u_);                                                 \
        cp_async16(bb_ + so_,          qkv + tok_ + 2048 + u_ * 8);                  \
        cp_async16(bb_ + 32768u + so_, qkv + tok_ + 4096 + u_ * 8);                  \
    }                                                                                \
} while (0)

    LOAD_KV(0, 0);
    cp_commit();

    // ---- base ldsm offsets (within first 16-row block; add nb*4096 per block) ----
    uint32_t offQ[8], offK[8], offV[8];
    {
        int rq = w * 16 + ((lane >> 3) & 1) * 8 + (lane & 7);
        #pragma unroll
        for (int c = 0; c < 8; ++c) offQ[c] = SWA(rq, 2 * c + (lane >> 4));
        int rk = ((lane >> 4) << 3) + (lane & 7);
        #pragma unroll
        for (int c = 0; c < 8; ++c) offK[c] = SWA(rk, 2 * c + ((lane >> 3) & 1));
        int rv = ((lane >> 3) & 1) * 8 + (lane & 7);
        #pragma unroll
        for (int hb = 0; hb < 8; ++hb) offV[hb] = SWA(rv, hb * 2 + (lane >> 4));
    }

    uint32_t qr[8][4];
    float Oa[16][4];
    #pragma unroll
    for (int g = 0; g < 16; ++g)
        #pragma unroll
        for (int r = 0; r < 4; ++r) Oa[g][r] = 0.f;
    float m0 = -INFINITY, m1 = -INFINITY, l0 = 0.f, l1 = 0.f;

    const int row0 = qt * 128 + w * 16 + (lane >> 2);
    const int row1 = row0 + 8;

    for (int jt = 0; jt <= qt; ++jt) {
        const int s = jt & 1;
        if (jt < qt) { LOAD_KV(jt + 1, s ^ 1); cp_commit(); CP_WAIT(1); }
        else         { CP_WAIT(0); }
        __syncthreads();

        if (jt == 0) {
            #pragma unroll
            for (int c = 0; c < 8; ++c) ldsm4(qr[c], sQ + offQ[c]);
        }

        const uint32_t bK = sb + 32768u + (uint32_t)s * 65536u;
        const uint32_t bV = bK + 32768u;

        // ---- S = Q K^T : 16 n-groups (128 cols) ----
        float sf[16][4];
        #pragma unroll
        for (int i = 0; i < 16; ++i)
            #pragma unroll
            for (int r = 0; r < 4; ++r) sf[i][r] = 0.f;
        #pragma unroll
        for (int nb = 0; nb < 8; ++nb) {
            const uint32_t bKn = bK + (uint32_t)nb * 4096u;
            #pragma unroll
            for (int c = 0; c < 8; ++c) {
                uint32_t kh[4];
                ldsm4(kh, bKn + offK[c]);
                mma_f16(sf[nb * 2],     qr[c], kh);
                mma_f16(sf[nb * 2 + 1], qr[c], kh + 2);
            }
        }

        // ---- causal mask (only diagonal tile jt == qt) ----
        if (jt == qt) {
            const int jb = jt * 128 + (lane & 3) * 2;
            #pragma unroll
            for (int i = 0; i < 16; ++i) {
                int c0 = jb + i * 8;
                if (c0     > row0) sf[i][0] = -INFINITY;
                if (c0 + 1 > row0) sf[i][1] = -INFINITY;
                if (c0     > row1) sf[i][2] = -INFINITY;
                if (c0 + 1 > row1) sf[i][3] = -INFINITY;
            }
        }

        // ---- online softmax (scaled domain) ----
        float mx0 = -INFINITY, mx1 = -INFINITY;
        #pragma unroll
        for (int i = 0; i < 16; ++i) {
            mx0 = fmaxf(mx0, fmaxf(sf[i][0], sf[i][1]));
            mx1 = fmaxf(mx1, fmaxf(sf[i][2], sf[i][3]));
        }
        mx0 *= sc; mx1 *= sc;
        mx0 = fmaxf(mx0, __shfl_xor_sync(0xffffffffu, mx0, 1));
        mx0 = fmaxf(mx0, __shfl_xor_sync(0xffffffffu, mx0, 2));
        mx1 = fmaxf(mx1, __shfl_xor_sync(0xffffffffu, mx1, 1));
        mx1 = fmaxf(mx1, __shfl_xor_sync(0xffffffffu, mx1, 2));
        float mn0 = fmaxf(m0, mx0), mn1 = fmaxf(m1, mx1);
        float al0 = __expf(m0 - mn0), al1 = __expf(m1 - mn1);
        m0 = mn0; m1 = mn1;
        float ps0 = 0.f, ps1 = 0.f;
        #pragma unroll
        for (int i = 0; i < 16; ++i) {
            sf[i][0] = __expf(fmaf(sf[i][0], sc, -m0)); ps0 += sf[i][0];
            sf[i][1] = __expf(fmaf(sf[i][1], sc, -m0)); ps0 += sf[i][1];
            sf[i][2] = __expf(fmaf(sf[i][2], sc, -m1)); ps1 += sf[i][2];
            sf[i][3] = __expf(fmaf(sf[i][3], sc, -m1)); ps1 += sf[i][3];
        }
        ps0 += __shfl_xor_sync(0xffffffffu, ps0, 1);
        ps0 += __shfl_xor_sync(0xffffffffu, ps0, 2);
        ps1 += __shfl_xor_sync(0xffffffffu, ps1, 1);
        ps1 += __shfl_xor_sync(0xffffffffu, ps1, 2);
        l0 = l0 * al0 + ps0; l1 = l1 * al1 + ps1;
        #pragma unroll
        for (int g = 0; g < 16; ++g) {
            Oa[g][0] *= al0; Oa[g][1] *= al0;
            Oa[g][2] *= al1; Oa[g][3] *= al1;
        }

        // ---- O += P V (P built per k-chunk; V via ldmatrix.trans) ----
        #pragma unroll
        for (int c2 = 0; c2 < 8; ++c2) {
            uint32_t ph[4];
            ph[0] = pack_h2(sf[2 * c2][0],     sf[2 * c2][1]);
            ph[1] = pack_h2(sf[2 * c2][2],     sf[2 * c2][3]);
            ph[2] = pack_h2(sf[2 * c2 + 1][0], sf[2 * c2 + 1][1]);
            ph[3] = pack_h2(sf[2 * c2 + 1][2], sf[2 * c2 + 1][3]);
            const uint32_t bVc = bV + (uint32_t)c2 * 4096u;
            #pragma unroll
            for (int hb = 0; hb < 8; ++hb) {
                uint32_t vh[4];
                ldsm4t(vh, bVc + offV[hb]);
                mma_f16(Oa[hb * 2],     ph, vh);
                mma_f16(Oa[hb * 2 + 1], ph, vh + 2);
            }
        }
        __syncthreads();
    }

    // ---- epilogue: O/l -> fp16 ----
    const float il0 = 1.0f / l0, il1 = 1.0f / l1;
    const size_t tok0 = (size_t)(bT + row0);
    #pragma unroll
    for (int g = 0; g < 16; ++g) {
        const int col = hO + g * 8 + (lane & 3) * 2;
        *(uint32_t*)(o + tok0 * DD + col) = pack_h2(Oa[g][0] * il0, Oa[g][1] * il0);
        *(uint32_t*)(o + (tok0 + 8) * DD + col) = pack_h2(Oa[g][2] * il1, Oa[g][3] * il1);
    }
#undef LOAD_KV
}

// ---------------- launch ----------------
extern "C" void kernel_launch(void* const* d_in, const int* in_sizes, int n_in,
                              void* d_out, int out_size)
{
    const float* x      = (const float*)d_in[0];
    const float* gamma  = (const float*)d_in[1];
    const float* beta   = (const float*)d_in[2];
    const float* qkv_w  = (const float*)d_in[3];
    const float* o_w    = (const float*)d_in[4];
    const float* gate_w = (const float*)d_in[5];
    const float* up_w   = (const float*)d_in[6];
    const float* down_w = (const float*)d_in[7];
    const float* n1w    = (const float*)d_in[8];
    const float* n2w    = (const float*)d_in[9];
    float* out = (float*)d_out;

    float *x1_;
    __half *gate_, *act_, *qkv_, *wq_, *wo_, *wg_, *wu_, *wd_;
    cudaGetSymbolAddress((void**)&x1_,   g_x1);
    cudaGetSymbolAddress((void**)&gate_, g_gate);
    cudaGetSymbolAddress((void**)&act_,  g_act);
    cudaGetSymbolAddress((void**)&qkv_,  g_qkv);
    cudaGetSymbolAddress((void**)&wq_, g_wqkv);
    cudaGetSymbolAddress((void**)&wo_, g_wo);
    cudaGetSymbolAddress((void**)&wg_, g_wg);
    cudaGetSymbolAddress((void**)&wu_, g_wu);
    cudaGetSymbolAddress((void**)&wd_, g_wd);

    cudaFuncSetAttribute(flash_attn_mma_kernel,
                         cudaFuncAttributeMaxDynamicSharedMemorySize, ATT_SMEM);
    cudaFuncSetAttribute(gemm_mma_kernel<1>,
                         cudaFuncAttributeMaxDynamicSharedMemorySize, GEMM_SMEM);
    cudaFuncSetAttribute(gemm_mma_kernel<2>,
                         cudaFuncAttributeMaxDynamicSharedMemorySize, GEMM_SMEM);
    cudaFuncSetAttribute(gemm_mma_kernel<3>,
                         cudaFuncAttributeMaxDynamicSharedMemorySize, GEMM_SMEM);

    // 0. all weights -> single fp16
    {
        int n;
        n = QKVW * DD / 4; cvt_h_kernel<<<(n + 255) / 256, 256>>>(qkv_w,  wq_, n);
        n = DD * DD / 4;   cvt_h_kernel<<<(n + 255) / 256, 256>>>(o_w,    wo_, n);
        n = FF * DD / 4;   cvt_h_kernel<<<(n + 255) / 256, 256>>>(gate_w, wg_, n);
        n = FF * DD / 4;   cvt_h_kernel<<<(n + 255) / 256, 256>>>(up_w,   wu_, n);
        n = DD * FF / 4;   cvt_h_kernel<<<(n + 255) / 256, 256>>>(down_w, wd_, n);
    }

    // 1. h = rmsnorm(x, n1)*gamma+beta -> act (fp16)
    rmsnorm_affine_kernel<<<MTOK, 256>>>(x, n1w, gamma, beta, act_);
    // 2. qkv = h @ qkv_w^T -> fp16
    gemm_mma_kernel<2><<<dim3(QKVW / 256, MTOK / 128), 256, GEMM_SMEM>>>(
        act_, wq_, nullptr, nullptr, qkv_, nullptr, QKVW, DD);
    // 3. attention -> act (fp16)
    flash_attn_mma_kernel<<<dim3(TT / 128, BB * HH), 256, ATT_SMEM>>>(qkv_, act_);
    // 4. x1 = x + attn @ o_w^T
    gemm_mma_kernel<1><<<dim3(DD / 256, MTOK / 128), 256, GEMM_SMEM>>>(
        act_, wo_, x, x1_, nullptr, nullptr, DD, DD);
    // 5. h = rmsnorm(x1, n2)*gamma+beta -> act (fp16)
    rmsnorm_affine_kernel<<<MTOK, 256>>>(x1_, n2w, gamma, beta, act_);
    // 6. gate -> fp16
    gemm_mma_kernel<2><<<dim3(FF / 256, MTOK / 128), 256, GEMM_SMEM>>>(
        act_, wg_, nullptr, nullptr, gate_, nullptr, FF, DD);
    // 7. up with fused silu(gate)*up -> ff (fp16) into qkv buffer
    gemm_mma_kernel<3><<<dim3(FF / 256, MTOK / 128), 256, GEMM_SMEM>>>(
        act_, wu_, nullptr, nullptr, qkv_, gate_, FF, DD);
    // 8. out = x1 + ff @ down_w^T
    gemm_mma_kernel<1><<<dim3(DD / 256, MTOK / 128), 256, GEMM_SMEM>>>(
        qkv_, wd_, x1_, out, nullptr, nullptr, DD, FF);
}

// round 15
// speedup vs baseline: 2.4292x; 1.0398x over previous
#include <cuda_runtime.h>
#include <cuda_bf16.h>
#include <cuda_fp16.h>
#include <math.h>
#include <stdint.h>

// Problem dims (fixed)
#define BB   2
#define TT   2048
#define DD   2048
#define HH   16
#define HD   128
#define FF   4096
#define MTOK 4096            // B*T
#define QKVW (3*DD)          // 6144

// ---------------- scratch (static __device__, no allocations) ----------------
__device__ float g_x1  [(size_t)MTOK * DD];    // x after attention residual
__device__ __half g_gate[(size_t)MTOK * FF];   // gate proj (fp16)

// fp16 activation operand (h1 -> attn-out -> h2)
__device__ __half g_act [(size_t)MTOK * DD];
// fp16 qkv (QKV GEMM out); reused as ff buffer after attention
__device__ __half g_qkv [(size_t)MTOK * QKVW];

// weights: all single fp16 in ONE slab:
// [qkv | o | gate | up | down] = 12M + 4M + 8M + 8M + 8M = 40M halves
#define W_QKV_OFF  0
#define W_O_OFF    ((size_t)QKVW * DD)                    // 12.58M
#define W_G_OFF    (W_O_OFF + (size_t)DD * DD)
#define W_U_OFF    (W_G_OFF + (size_t)FF * DD)
#define W_D_OFF    (W_U_OFF + (size_t)FF * DD)
#define W_TOTAL    (W_D_OFF + (size_t)DD * FF)
__device__ __half g_w[W_TOTAL];

// ======================= PTX helpers (baseline ISA only) =======================
__device__ __forceinline__ uint32_t smem_u32(const void* p) {
    uint32_t a;
    asm("{ .reg .u64 t; cvta.to.shared.u64 t, %1; cvt.u32.u64 %0, t; }" : "=r"(a) : "l"(p));
    return a;
}
__device__ __forceinline__ void cp_async16(uint32_t s, const void* g) {
    asm volatile("cp.async.cg.shared.global [%0], [%1], 16;" :: "r"(s), "l"(g));
}
__device__ __forceinline__ void cp_commit() { asm volatile("cp.async.commit_group;" ::: "memory"); }
#define CP_WAIT(n) asm volatile("cp.async.wait_group %0;" :: "n"(n) : "memory")

__device__ __forceinline__ void ldsm4(uint32_t* r, uint32_t addr) {
    asm volatile("ldmatrix.sync.aligned.m8n8.x4.shared.b16 {%0,%1,%2,%3}, [%4];"
        : "=r"(r[0]), "=r"(r[1]), "=r"(r[2]), "=r"(r[3]) : "r"(addr));
}
__device__ __forceinline__ void ldsm4t(uint32_t* r, uint32_t addr) {
    asm volatile("ldmatrix.sync.aligned.m8n8.x4.trans.shared.b16 {%0,%1,%2,%3}, [%4];"
        : "=r"(r[0]), "=r"(r[1]), "=r"(r[2]), "=r"(r[3]) : "r"(addr));
}
__device__ __forceinline__ void mma_f16(float* d, const uint32_t* a, const uint32_t* b) {
    asm volatile("mma.sync.aligned.m16n8k16.row.col.f32.f16.f16.f32 "
        "{%0,%1,%2,%3}, {%4,%5,%6,%7}, {%8,%9}, {%0,%1,%2,%3};"
        : "+f"(d[0]), "+f"(d[1]), "+f"(d[2]), "+f"(d[3])
        : "r"(a[0]), "r"(a[1]), "r"(a[2]), "r"(a[3]), "r"(b[0]), "r"(b[1]));
}

__device__ __forceinline__ uint32_t pack_h2(float a, float b) {
    __half2 h = __floats2half2_rn(a, b);
    return *(uint32_t*)&h;
}

// ---- ONE merged weight convert: 5 sources -> one fp16 slab ----
// src pointers passed as args; segment boundaries in units of float4 (4 floats).
__global__ void __launch_bounds__(256) cvt_all_kernel(
    const float* __restrict__ s0, const float* __restrict__ s1,
    const float* __restrict__ s2, const float* __restrict__ s3,
    const float* __restrict__ s4, __half* __restrict__ out)
{
    const int n0 = QKVW * DD / 4;           // qkv
    const int n1 = n0 + DD * DD / 4;        // + o
    const int n2 = n1 + FF * DD / 4;        // + gate
    const int n3 = n2 + FF * DD / 4;        // + up
    const int n4 = n3 + DD * FF / 4;        // + down
    const int stride = gridDim.x * blockDim.x;
    for (int i = blockIdx.x * blockDim.x + threadIdx.x; i < n4; i += stride) {
        const float* src;
        int j;
        if (i < n0)      { src = s0; j = i; }
        else if (i < n1) { src = s1; j = i - n0; }
        else if (i < n2) { src = s2; j = i - n1; }
        else if (i < n3) { src = s3; j = i - n2; }
        else             { src = s4; j = i - n3; }
        float4 v = ((const float4*)src)[j];
        ((__half2*)out)[2 * (size_t)i]     = __floats2half2_rn(v.x, v.y);
        ((__half2*)out)[2 * (size_t)i + 1] = __floats2half2_rn(v.z, v.w);
    }
}

// ---------------- RMSNorm * w * gamma + beta -> fp16 ----------------
__global__ void __launch_bounds__(256) rmsnorm_affine_kernel(
    const float* __restrict__ x, const float* __restrict__ w,
    const float* __restrict__ gamma, const float* __restrict__ beta,
    __half* __restrict__ o)
{
    const int row = blockIdx.x;
    const float4* xr = (const float4*)(x + (size_t)row * DD);
    const int t = threadIdx.x;

    float4 v0 = xr[t];
    float4 v1 = xr[t + 256];
    float ss = v0.x*v0.x + v0.y*v0.y + v0.z*v0.z + v0.w*v0.w
             + v1.x*v1.x + v1.y*v1.y + v1.z*v1.z + v1.w*v1.w;
    #pragma unroll
    for (int d = 16; d; d >>= 1) ss += __shfl_xor_sync(0xffffffffu, ss, d);
    __shared__ float red[8];
    if ((t & 31) == 0) red[t >> 5] = ss;
    __syncthreads();
    float tot = red[0] + red[1] + red[2] + red[3] + red[4] + red[5] + red[6] + red[7];
    const float inv = rsqrtf(tot * (1.0f / DD) + 1.1920929e-07f);

    const float4* w4 = (const float4*)w;
    const float4* g4 = (const float4*)gamma;
    const float4* b4 = (const float4*)beta;
    __half2* orow = (__half2*)(o + (size_t)row * DD);
    #pragma unroll
    for (int c = 0; c < 2; ++c) {
        int i = t + c * 256;
        float4 xv = (c == 0) ? v0 : v1;
        float4 wv = w4[i], gv = g4[i], bv = b4[i];
        float4 r;
        r.x = xv.x * inv * wv.x * gv.x + bv.x;
        r.y = xv.y * inv * wv.y * gv.y + bv.y;
        r.z = xv.z * inv * wv.z * gv.z + bv.z;
        r.w = xv.w * inv * wv.w * gv.w + bv.w;
        orow[2 * i]     = __floats2half2_rn(r.x, r.y);
        orow[2 * i + 1] = __floats2half2_rn(r.z, r.w);
    }
}

// ======================= mma.sync GEMM (single fp16) =======================
// C[M,N] = A[M,K] @ B[N,K]^T. CTA 128x256, BK=32, 8 warps (2Mx4N), warp 64x64.
// MODE: 1 = fp32 + res(fp32), 2 = fp16 out, 3 = silu(res16)*acc -> fp16 out
#define BKC 32
#define STG 4
#define STAGE_B 24576            // A 8K | B 16K
#define OFF_A 0
#define OFF_B 8192
#define GEMM_SMEM (STG * STAGE_B)

// swizzled byte offset for (row, 16B-unit u) in a [rows][32]x16bit tile (64B rows)
#define SWZ(r_, u_) ((uint32_t)(r_) * 64u + ((((uint32_t)(u_)) ^ (((uint32_t)(r_) >> 1) & 3u)) << 4))

template<int MODE>
__global__ void __launch_bounds__(256) gemm_mma_kernel(
    const __half* __restrict__ A, const __half* __restrict__ B,
    const float* __restrict__ res, float* __restrict__ C,
    __half* __restrict__ Ch, const __half* __restrict__ resh,
    int N, int K)
{
    extern __shared__ char smraw[];
    const uint32_t sb = smem_u32(smraw);
    const int tid  = threadIdx.x;
    const int lane = tid & 31;
    const int warp = tid >> 5;
    const int wm = warp >> 2, wn = warp & 3;
    const int row0 = blockIdx.y << 7;
    const int col0 = blockIdx.x << 8;

    const int lr = tid >> 2, lu = tid & 3;
    const uint32_t wsw0 = SWZ(lr, lu);
    const uint32_t wsw1 = SWZ(lr + 64, lu);
    const uint32_t wsw2 = SWZ(lr + 128, lu);
    const uint32_t wsw3 = SWZ(lr + 192, lu);
    const size_t rK64 = (size_t)64 * K;
    const __half* gA = A + (size_t)(row0 + lr) * K + lu * 8;
    const __half* gB = B + (size_t)(col0 + lr) * K + lu * 8;

#define LOAD_STAGE(kt_, st_) do {                                   \
    uint32_t b_ = sb + (uint32_t)(st_) * STAGE_B;                   \
    size_t ko_ = (size_t)(kt_) * BKC;                               \
    cp_async16(b_ + OFF_A + wsw0, gA + ko_);                        \
    cp_async16(b_ + OFF_A + wsw1, gA + rK64 + ko_);                 \
    cp_async16(b_ + OFF_B + wsw0, gB + ko_);                        \
    cp_async16(b_ + OFF_B + wsw1, gB + rK64 + ko_);                 \
    cp_async16(b_ + OFF_B + wsw2, gB + 2 * rK64 + ko_);             \
    cp_async16(b_ + OFF_B + wsw3, gB + 3 * rK64 + ko_);             \
    cp_commit();                                                    \
} while (0)

    const int m8 = lane >> 3;
    uint32_t offA[4][2], offB[4][2];
    #pragma unroll
    for (int i = 0; i < 4; ++i)
        #pragma unroll
        for (int kc = 0; kc < 2; ++kc) {
            int rowa = wm * 64 + i * 16 + ((m8 & 1) << 3) + (lane & 7);
            offA[i][kc] = SWZ(rowa, kc * 2 + (m8 >> 1));
        }
    #pragma unroll
    for (int nb = 0; nb < 4; ++nb)
        #pragma unroll
        for (int kc = 0; kc < 2; ++kc) {
            int rowb = wn * 64 + nb * 16 + ((m8 >> 1) << 3) + (lane & 7);
            offB[nb][kc] = SWZ(rowb, kc * 2 + (m8 & 1));
        }

    float acc[4][8][4];
    #pragma unroll
    for (int i = 0; i < 4; ++i)
        #pragma unroll
        for (int j = 0; j < 8; ++j)
            #pragma unroll
            for (int r = 0; r < 4; ++r) acc[i][j][r] = 0.f;

    const int nk = K / BKC;

    LOAD_STAGE(0, 0);
    LOAD_STAGE(1, 1);
    LOAD_STAGE(2, 2);

    for (int kt = 0; kt < nk; ++kt) {
        const int rem = nk - 1 - kt;
        if (rem >= 2)      CP_WAIT(2);
        else if (rem == 1) CP_WAIT(1);
        else               CP_WAIT(0);
        __syncthreads();
        if (kt + 3 < nk) LOAD_STAGE(kt + 3, (kt + 3) & 3);

        const uint32_t base = sb + (uint32_t)(kt & 3) * STAGE_B;
        #pragma unroll
        for (int kc = 0; kc < 2; ++kc) {
            uint32_t ah[4][4];
            #pragma unroll
            for (int i = 0; i < 4; ++i)
                ldsm4(ah[i], base + OFF_A + offA[i][kc]);
            #pragma unroll
            for (int nb = 0; nb < 4; ++nb) {
                uint32_t bh[4];
                ldsm4(bh, base + OFF_B + offB[nb][kc]);
                #pragma unroll
                for (int i = 0; i < 4; ++i) {
                    mma_f16(acc[i][nb * 2],     ah[i], bh);
                    mma_f16(acc[i][nb * 2 + 1], ah[i], bh + 2);
                }
            }
        }
    }

    // ---- epilogue ----
    const int er = lane >> 2;
    const int ec = (lane & 3) * 2;
    #pragma unroll
    for (int i = 0; i < 4; ++i) {
        const int grow = row0 + wm * 64 + i * 16 + er;
        #pragma unroll
        for (int jf = 0; jf < 8; ++jf) {
            const int gcol = col0 + wn * 64 + jf * 8 + ec;
            float v00 = acc[i][jf][0], v01 = acc[i][jf][1];
            float v10 = acc[i][jf][2], v11 = acc[i][jf][3];
            if (MODE == 1) {
                float2 r0 = *(const float2*)(res + (size_t)grow * N + gcol);
                float2 r1 = *(const float2*)(res + (size_t)(grow + 8) * N + gcol);
                v00 += r0.x; v01 += r0.y; v10 += r1.x; v11 += r1.y;
                *(float2*)(C + (size_t)grow * N + gcol) = make_float2(v00, v01);
                *(float2*)(C + (size_t)(grow + 8) * N + gcol) = make_float2(v10, v11);
            } else {
                if (MODE == 3) {
                    uint32_t u0 = *(const uint32_t*)(resh + (size_t)grow * N + gcol);
                    uint32_t u1 = *(const uint32_t*)(resh + (size_t)(grow + 8) * N + gcol);
                    float2 r0 = __half22float2(*(__half2*)&u0);
                    float2 r1 = __half22float2(*(__half2*)&u1);
                    v00 *= r0.x / (1.f + __expf(-r0.x));
                    v01 *= r0.y / (1.f + __expf(-r0.y));
                    v10 *= r1.x / (1.f + __expf(-r1.x));
                    v11 *= r1.y / (1.f + __expf(-r1.y));
                }
                *(uint32_t*)(Ch + (size_t)grow * N + gcol) = pack_h2(v00, v01);
                *(uint32_t*)(Ch + (size_t)(grow + 8) * N + gcol) = pack_h2(v10, v11);
            }
        }
    }
#undef LOAD_STAGE
}

// ======================= tensor-core causal flash attention (fp16, BC=128) =======================
// BR=128 (8 warps x m16), BC=128, HD=128. Q regs, K/V smem double-buffered.
// Heavy Q-tiles scheduled FIRST (qt descending) to kill the causal-imbalance tail.
// smem: Q 32K | 2 stages x (K 32K, V 32K) = 160KB.
#define ATT_SMEM 163840
// [128]fp16 rows = 256B = 16 units of 16B; swizzle u ^ (r&7)
#define SWA(r_, u_) ((uint32_t)(r_) * 256u + ((((uint32_t)(u_)) ^ ((uint32_t)(r_) & 7u)) << 4))

__global__ void __launch_bounds__(256) flash_attn_mma_kernel(
    const __half* __restrict__ qkv, __half* __restrict__ o)
{
    // flat grid: heaviest q-tiles (largest qt) first in launch order
    const int flat = blockIdx.x;
    const int qt = (TT / 128 - 1) - (flat >> 5);   // 15 .. 0
    const int bh = flat & 31;
    const int b = bh >> 4, h = bh & 15;
    extern __shared__ char smraw[];
    const uint32_t sb = smem_u32(smraw);
    const uint32_t sQ = sb;

    const int tid = threadIdx.x;
    const int lane = tid & 31;
    const int w = tid >> 5;
    const int bT = b * TT;
    const int hO = h * HD;
    const float sc = 0.08838834764831845f;   // 1/sqrt(128)

    // ---- load Q (128 rows x 16 units) ----
    {
        const int r = tid >> 1, ub = (tid & 1) * 8;
        const __half* q_row = qkv + (size_t)(bT + qt * 128 + r) * QKVW + hO;
        #pragma unroll
        for (int i = 0; i < 8; ++i) {
            int u = ub + i;
            cp_async16(sQ + SWA(r, u), q_row + u * 8);
        }
    }
    // ---- KV tile loader: 128 rows of K and V ----
    const int kvr = tid >> 1, kvu = (tid & 1) * 8;
#define LOAD_KV(jt_, s_) do {                                                        \
    uint32_t bb_ = sb + 32768u + (uint32_t)(s_) * 65536u;                            \
    size_t tok_ = (size_t)(bT + (jt_) * 128 + kvr) * QKVW + hO;                      \
    _Pragma("unroll")                                                                \
    for (int i_ = 0; i_ < 8; ++i_) {                                                 \
        int u_ = kvu + i_;                                                           \
        uint32_t so_ = SWA(kvr, u_);                                                 \
        cp_async16(bb_ + so_,          qkv + tok_ + 2048 + u_ * 8);                  \
        cp_async16(bb_ + 32768u + so_, qkv + tok_ + 4096 + u_ * 8);                  \
    }                                                                                \
} while (0)

    LOAD_KV(0, 0);
    cp_commit();

    // ---- base ldsm offsets (within first 16-row block; add nb*4096 per block) ----
    uint32_t offQ[8], offK[8], offV[8];
    {
        int rq = w * 16 + ((lane >> 3) & 1) * 8 + (lane & 7);
        #pragma unroll
        for (int c = 0; c < 8; ++c) offQ[c] = SWA(rq, 2 * c + (lane >> 4));
        int rk = ((lane >> 4) << 3) + (lane & 7);
        #pragma unroll
        for (int c = 0; c < 8; ++c) offK[c] = SWA(rk, 2 * c + ((lane >> 3) & 1));
        int rv = ((lane >> 3) & 1) * 8 + (lane & 7);
        #pragma unroll
        for (int hb = 0; hb < 8; ++hb) offV[hb] = SWA(rv, hb * 2 + (lane >> 4));
    }

    uint32_t qr[8][4];
    float Oa[16][4];
    #pragma unroll
    for (int g = 0; g < 16; ++g)
        #pragma unroll
        for (int r = 0; r < 4; ++r) Oa[g][r] = 0.f;
    float m0 = -INFINITY, m1 = -INFINITY, l0 = 0.f, l1 = 0.f;

    const int row0 = qt * 128 + w * 16 + (lane >> 2);
    const int row1 = row0 + 8;

    for (int jt = 0; jt <= qt; ++jt) {
        const int s = jt & 1;
        if (jt < qt) { LOAD_KV(jt + 1, s ^ 1); cp_commit(); CP_WAIT(1); }
        else         { CP_WAIT(0); }
        __syncthreads();

        if (jt == 0) {
            #pragma unroll
            for (int c = 0; c < 8; ++c) ldsm4(qr[c], sQ + offQ[c]);
        }

        const uint32_t bK = sb + 32768u + (uint32_t)s * 65536u;
        const uint32_t bV = bK + 32768u;

        // ---- S = Q K^T : 16 n-groups (128 cols) ----
        float sf[16][4];
        #pragma unroll
        for (int i = 0; i < 16; ++i)
            #pragma unroll
            for (int r = 0; r < 4; ++r) sf[i][r] = 0.f;
        #pragma unroll
        for (int nb = 0; nb < 8; ++nb) {
            const uint32_t bKn = bK + (uint32_t)nb * 4096u;
            #pragma unroll
            for (int c = 0; c < 8; ++c) {
                uint32_t kh[4];
                ldsm4(kh, bKn + offK[c]);
                mma_f16(sf[nb * 2],     qr[c], kh);
                mma_f16(sf[nb * 2 + 1], qr[c], kh + 2);
            }
        }

        // ---- causal mask (only diagonal tile jt == qt) ----
        if (jt == qt) {
            const int jb = jt * 128 + (lane & 3) * 2;
            #pragma unroll
            for (int i = 0; i < 16; ++i) {
                int c0 = jb + i * 8;
                if (c0     > row0) sf[i][0] = -INFINITY;
                if (c0 + 1 > row0) sf[i][1] = -INFINITY;
                if (c0     > row1) sf[i][2] = -INFINITY;
                if (c0 + 1 > row1) sf[i][3] = -INFINITY;
            }
        }

        // ---- online softmax (scaled domain) ----
        float mx0 = -INFINITY, mx1 = -INFINITY;
        #pragma unroll
        for (int i = 0; i < 16; ++i) {
            mx0 = fmaxf(mx0, fmaxf(sf[i][0], sf[i][1]));
            mx1 = fmaxf(mx1, fmaxf(sf[i][2], sf[i][3]));
        }
        mx0 *= sc; mx1 *= sc;
        mx0 = fmaxf(mx0, __shfl_xor_sync(0xffffffffu, mx0, 1));
        mx0 = fmaxf(mx0, __shfl_xor_sync(0xffffffffu, mx0, 2));
        mx1 = fmaxf(mx1, __shfl_xor_sync(0xffffffffu, mx1, 1));
        mx1 = fmaxf(mx1, __shfl_xor_sync(0xffffffffu, mx1, 2));
        float mn0 = fmaxf(m0, mx0), mn1 = fmaxf(m1, mx1);
        float al0 = __expf(m0 - mn0), al1 = __expf(m1 - mn1);
        m0 = mn0; m1 = mn1;
        float ps0 = 0.f, ps1 = 0.f;
        #pragma unroll
        for (int i = 0; i < 16; ++i) {
            sf[i][0] = __expf(fmaf(sf[i][0], sc, -m0)); ps0 += sf[i][0];
            sf[i][1] = __expf(fmaf(sf[i][1], sc, -m0)); ps0 += sf[i][1];
            sf[i][2] = __expf(fmaf(sf[i][2], sc, -m1)); ps1 += sf[i][2];
            sf[i][3] = __expf(fmaf(sf[i][3], sc, -m1)); ps1 += sf[i][3];
        }
        ps0 += __shfl_xor_sync(0xffffffffu, ps0, 1);
        ps0 += __shfl_xor_sync(0xffffffffu, ps0, 2);
        ps1 += __shfl_xor_sync(0xffffffffu, ps1, 1);
        ps1 += __shfl_xor_sync(0xffffffffu, ps1, 2);
        l0 = l0 * al0 + ps0; l1 = l1 * al1 + ps1;
        #pragma unroll
        for (int g = 0; g < 16; ++g) {
            Oa[g][0] *= al0; Oa[g][1] *= al0;
            Oa[g][2] *= al1; Oa[g][3] *= al1;
        }

        // ---- O += P V (P built per k-chunk; V via ldmatrix.trans) ----
        #pragma unroll
        for (int c2 = 0; c2 < 8; ++c2) {
            uint32_t ph[4];
            ph[0] = pack_h2(sf[2 * c2][0],     sf[2 * c2][1]);
            ph[1] = pack_h2(sf[2 * c2][2],     sf[2 * c2][3]);
            ph[2] = pack_h2(sf[2 * c2 + 1][0], sf[2 * c2 + 1][1]);
            ph[3] = pack_h2(sf[2 * c2 + 1][2], sf[2 * c2 + 1][3]);
            const uint32_t bVc = bV + (uint32_t)c2 * 4096u;
            #pragma unroll
            for (int hb = 0; hb < 8; ++hb) {
                uint32_t vh[4];
                ldsm4t(vh, bVc + offV[hb]);
                mma_f16(Oa[hb * 2],     ph, vh);
                mma_f16(Oa[hb * 2 + 1], ph, vh + 2);
            }
        }
        __syncthreads();
    }

    // ---- epilogue: O/l -> fp16 ----
    const float il0 = 1.0f / l0, il1 = 1.0f / l1;
    const size_t tok0 = (size_t)(bT + row0);
    #pragma unroll
    for (int g = 0; g < 16; ++g) {
        const int col = hO + g * 8 + (lane & 3) * 2;
        *(uint32_t*)(o + tok0 * DD + col) = pack_h2(Oa[g][0] * il0, Oa[g][1] * il0);
        *(uint32_t*)(o + (tok0 + 8) * DD + col) = pack_h2(Oa[g][2] * il1, Oa[g][3] * il1);
    }
#undef LOAD_KV
}

// ---------------- launch ----------------
extern "C" void kernel_launch(void* const* d_in, const int* in_sizes, int n_in,
                              void* d_out, int out_size)
{
    const float* x      = (const float*)d_in[0];
    const float* gamma  = (const float*)d_in[1];
    const float* beta   = (const float*)d_in[2];
    const float* qkv_w  = (const float*)d_in[3];
    const float* o_w    = (const float*)d_in[4];
    const float* gate_w = (const float*)d_in[5];
    const float* up_w   = (const float*)d_in[6];
    const float* down_w = (const float*)d_in[7];
    const float* n1w    = (const float*)d_in[8];
    const float* n2w    = (const float*)d_in[9];
    float* out = (float*)d_out;

    float *x1_;
    __half *gate_, *act_, *qkv_, *w_;
    cudaGetSymbolAddress((void**)&x1_,   g_x1);
    cudaGetSymbolAddress((void**)&gate_, g_gate);
    cudaGetSymbolAddress((void**)&act_,  g_act);
    cudaGetSymbolAddress((void**)&qkv_,  g_qkv);
    cudaGetSymbolAddress((void**)&w_,    g_w);
    __half* wq_ = w_ + W_QKV_OFF;
    __half* wo_ = w_ + W_O_OFF;
    __half* wg_ = w_ + W_G_OFF;
    __half* wu_ = w_ + W_U_OFF;
    __half* wd_ = w_ + W_D_OFF;

    cudaFuncSetAttribute(flash_attn_mma_kernel,
                         cudaFuncAttributeMaxDynamicSharedMemorySize, ATT_SMEM);
    cudaFuncSetAttribute(gemm_mma_kernel<1>,
                         cudaFuncAttributeMaxDynamicSharedMemorySize, GEMM_SMEM);
    cudaFuncSetAttribute(gemm_mma_kernel<2>,
                         cudaFuncAttributeMaxDynamicSharedMemorySize, GEMM_SMEM);
    cudaFuncSetAttribute(gemm_mma_kernel<3>,
                         cudaFuncAttributeMaxDynamicSharedMemorySize, GEMM_SMEM);

    // 0. all weights -> single fp16 slab, ONE launch (grid-stride)
    cvt_all_kernel<<<2368, 256>>>(qkv_w, o_w, gate_w, up_w, down_w, w_);

    // 1. h = rmsnorm(x, n1)*gamma+beta -> act (fp16)
    rmsnorm_affine_kernel<<<MTOK, 256>>>(x, n1w, gamma, beta, act_);
    // 2. qkv = h @ qkv_w^T -> fp16
    gemm_mma_kernel<2><<<dim3(QKVW / 256, MTOK / 128), 256, GEMM_SMEM>>>(
        act_, wq_, nullptr, nullptr, qkv_, nullptr, QKVW, DD);
    // 3. attention (heavy tiles first) -> act (fp16)
    flash_attn_mma_kernel<<<(TT / 128) * BB * HH, 256, ATT_SMEM>>>(qkv_, act_);
    // 4. x1 = x + attn @ o_w^T
    gemm_mma_kernel<1><<<dim3(DD / 256, MTOK / 128), 256, GEMM_SMEM>>>(
        act_, wo_, x, x1_, nullptr, nullptr, DD, DD);
    // 5. h = rmsnorm(x1, n2)*gamma+beta -> act (fp16)
    rmsnorm_affine_kernel<<<MTOK, 256>>>(x1_, n2w, gamma, beta, act_);
    // 6. gate -> fp16
    gemm_mma_kernel<2><<<dim3(FF / 256, MTOK / 128), 256, GEMM_SMEM>>>(
        act_, wg_, nullptr, nullptr, gate_, nullptr, FF, DD);
    // 7. up with fused silu(gate)*up -> ff (fp16) into qkv buffer
    gemm_mma_kernel<3><<<dim3(FF / 256, MTOK / 128), 256, GEMM_SMEM>>>(
        act_, wu_, nullptr, nullptr, qkv_, gate_, FF, DD);
    // 8. out = x1 + ff @ down_w^T
    gemm_mma_kernel<1><<<dim3(DD / 256, MTOK / 128), 256, GEMM_SMEM>>>(
        qkv_, wd_, x1_, out, nullptr, nullptr, DD, FF);
}

// round 16
// speedup vs baseline: 2.8450x; 1.1712x over previous
#include <cuda_runtime.h>
#include <cuda_bf16.h>
#include <cuda_fp16.h>
#include <math.h>
#include <stdint.h>

// Problem dims (fixed)
#define BB   2
#define TT   2048
#define DD   2048
#define HH   16
#define HD   128
#define FF   4096
#define MTOK 4096            // B*T
#define QKVW (3*DD)          // 6144

// ---------------- scratch (static __device__, no allocations) ----------------
__device__ float g_x1  [(size_t)MTOK * DD];    // x after attention residual
__device__ __half g_gate[(size_t)MTOK * FF];   // gate proj (fp16)

// fp16 activation operand (h1 -> attn-out -> h2)
__device__ __half g_act [(size_t)MTOK * DD];
// fp16 qkv (QKV GEMM out); reused as ff buffer after attention
__device__ __half g_qkv [(size_t)MTOK * QKVW];

// weights: all single fp16 in ONE slab
#define W_QKV_OFF  0
#define W_O_OFF    ((size_t)QKVW * DD)
#define W_G_OFF    (W_O_OFF + (size_t)DD * DD)
#define W_U_OFF    (W_G_OFF + (size_t)FF * DD)
#define W_D_OFF    (W_U_OFF + (size_t)FF * DD)
#define W_TOTAL    (W_D_OFF + (size_t)DD * FF)
__device__ __half g_w[W_TOTAL];

// ======================= PTX helpers (baseline ISA only) =======================
__device__ __forceinline__ uint32_t smem_u32(const void* p) {
    uint32_t a;
    asm("{ .reg .u64 t; cvta.to.shared.u64 t, %1; cvt.u32.u64 %0, t; }" : "=r"(a) : "l"(p));
    return a;
}
__device__ __forceinline__ void cp_async16(uint32_t s, const void* g) {
    asm volatile("cp.async.cg.shared.global [%0], [%1], 16;" :: "r"(s), "l"(g));
}
__device__ __forceinline__ void cp_commit() { asm volatile("cp.async.commit_group;" ::: "memory"); }
#define CP_WAIT(n) asm volatile("cp.async.wait_group %0;" :: "n"(n) : "memory")

__device__ __forceinline__ void ldsm4(uint32_t* r, uint32_t addr) {
    asm volatile("ldmatrix.sync.aligned.m8n8.x4.shared.b16 {%0,%1,%2,%3}, [%4];"
        : "=r"(r[0]), "=r"(r[1]), "=r"(r[2]), "=r"(r[3]) : "r"(addr));
}
__device__ __forceinline__ void ldsm4t(uint32_t* r, uint32_t addr) {
    asm volatile("ldmatrix.sync.aligned.m8n8.x4.trans.shared.b16 {%0,%1,%2,%3}, [%4];"
        : "=r"(r[0]), "=r"(r[1]), "=r"(r[2]), "=r"(r[3]) : "r"(addr));
}
__device__ __forceinline__ void mma_f16(float* d, const uint32_t* a, const uint32_t* b) {
    asm volatile("mma.sync.aligned.m16n8k16.row.col.f32.f16.f16.f32 "
        "{%0,%1,%2,%3}, {%4,%5,%6,%7}, {%8,%9}, {%0,%1,%2,%3};"
        : "+f"(d[0]), "+f"(d[1]), "+f"(d[2]), "+f"(d[3])
        : "r"(a[0]), "r"(a[1]), "r"(a[2]), "r"(a[3]), "r"(b[0]), "r"(b[1]));
}

__device__ __forceinline__ uint32_t pack_h2(float a, float b) {
    __half2 h = __floats2half2_rn(a, b);
    return *(uint32_t*)&h;
}

// ---- ONE merged weight convert: 5 sources -> one fp16 slab ----
__global__ void __launch_bounds__(256) cvt_all_kernel(
    const float* __restrict__ s0, const float* __restrict__ s1,
    const float* __restrict__ s2, const float* __restrict__ s3,
    const float* __restrict__ s4, __half* __restrict__ out)
{
    const int n0 = QKVW * DD / 4;
    const int n1 = n0 + DD * DD / 4;
    const int n2 = n1 + FF * DD / 4;
    const int n3 = n2 + FF * DD / 4;
    const int n4 = n3 + DD * FF / 4;
    const int stride = gridDim.x * blockDim.x;
    for (int i = blockIdx.x * blockDim.x + threadIdx.x; i < n4; i += stride) {
        const float* src;
        int j;
        if (i < n0)      { src = s0; j = i; }
        else if (i < n1) { src = s1; j = i - n0; }
        else if (i < n2) { src = s2; j = i - n1; }
        else if (i < n3) { src = s3; j = i - n2; }
        else             { src = s4; j = i - n3; }
        float4 v = ((const float4*)src)[j];
        ((__half2*)out)[2 * (size_t)i]     = __floats2half2_rn(v.x, v.y);
        ((__half2*)out)[2 * (size_t)i + 1] = __floats2half2_rn(v.z, v.w);
    }
}

// ---------------- RMSNorm * w * gamma + beta -> fp16 ----------------
__global__ void __launch_bounds__(256) rmsnorm_affine_kernel(
    const float* __restrict__ x, const float* __restrict__ w,
    const float* __restrict__ gamma, const float* __restrict__ beta,
    __half* __restrict__ o)
{
    const int row = blockIdx.x;
    const float4* xr = (const float4*)(x + (size_t)row * DD);
    const int t = threadIdx.x;

    float4 v0 = xr[t];
    float4 v1 = xr[t + 256];
    float ss = v0.x*v0.x + v0.y*v0.y + v0.z*v0.z + v0.w*v0.w
             + v1.x*v1.x + v1.y*v1.y + v1.z*v1.z + v1.w*v1.w;
    #pragma unroll
    for (int d = 16; d; d >>= 1) ss += __shfl_xor_sync(0xffffffffu, ss, d);
    __shared__ float red[8];
    if ((t & 31) == 0) red[t >> 5] = ss;
    __syncthreads();
    float tot = red[0] + red[1] + red[2] + red[3] + red[4] + red[5] + red[6] + red[7];
    const float inv = rsqrtf(tot * (1.0f / DD) + 1.1920929e-07f);

    const float4* w4 = (const float4*)w;
    const float4* g4 = (const float4*)gamma;
    const float4* b4 = (const float4*)beta;
    __half2* orow = (__half2*)(o + (size_t)row * DD);
    #pragma unroll
    for (int c = 0; c < 2; ++c) {
        int i = t + c * 256;
        float4 xv = (c == 0) ? v0 : v1;
        float4 wv = w4[i], gv = g4[i], bv = b4[i];
        float4 r;
        r.x = xv.x * inv * wv.x * gv.x + bv.x;
        r.y = xv.y * inv * wv.y * gv.y + bv.y;
        r.z = xv.z * inv * wv.z * gv.z + bv.z;
        r.w = xv.w * inv * wv.w * gv.w + bv.w;
        orow[2 * i]     = __floats2half2_rn(r.x, r.y);
        orow[2 * i + 1] = __floats2half2_rn(r.z, r.w);
    }
}

// ======================= mma.sync GEMM (single fp16, 128x128 tile, occ 2) =======================
// C[M,N] = A[M,K] @ B[N,K]^T. CTA 128x128, BK=32, 8 warps (2Mx4N), warp 64x32.
// 4-stage cp.async ring, ONE barrier per iteration, 2 CTAs/SM.
// MODE: 1 = fp32 + res(fp32), 2 = fp16 out, 3 = silu(res16)*acc -> fp16 out
#define BKC 32
#define STG 4
#define STAGE_B 16384            // A 8K | B 8K
#define OFF_A 0
#define OFF_B 8192
#define GEMM_SMEM (STG * STAGE_B)   // 64 KB

// swizzled byte offset for (row, 16B-unit u) in a [rows][32]x16bit tile (64B rows)
#define SWZ(r_, u_) ((uint32_t)(r_) * 64u + ((((uint32_t)(u_)) ^ (((uint32_t)(r_) >> 1) & 3u)) << 4))

template<int MODE>
__global__ void __launch_bounds__(256, 2) gemm_mma_kernel(
    const __half* __restrict__ A, const __half* __restrict__ B,
    const float* __restrict__ res, float* __restrict__ C,
    __half* __restrict__ Ch, const __half* __restrict__ resh,
    int N, int K)
{
    extern __shared__ char smraw[];
    const uint32_t sb = smem_u32(smraw);
    const int tid  = threadIdx.x;
    const int lane = tid & 31;
    const int warp = tid >> 5;
    const int wm = warp >> 2, wn = warp & 3;
    const int row0 = blockIdx.y << 7;
    const int col0 = blockIdx.x << 7;

    const int lr = tid >> 2, lu = tid & 3;
    const uint32_t wsw0 = SWZ(lr, lu);
    const uint32_t wsw1 = SWZ(lr + 64, lu);
    const size_t rK64 = (size_t)64 * K;
    const __half* gA = A + (size_t)(row0 + lr) * K + lu * 8;
    const __half* gB = B + (size_t)(col0 + lr) * K + lu * 8;

#define LOAD_STAGE(kt_, st_) do {                                   \
    uint32_t b_ = sb + (uint32_t)(st_) * STAGE_B;                   \
    size_t ko_ = (size_t)(kt_) * BKC;                               \
    cp_async16(b_ + OFF_A + wsw0, gA + ko_);                        \
    cp_async16(b_ + OFF_A + wsw1, gA + rK64 + ko_);                 \
    cp_async16(b_ + OFF_B + wsw0, gB + ko_);                        \
    cp_async16(b_ + OFF_B + wsw1, gB + rK64 + ko_);                 \
    cp_commit();                                                    \
} while (0)

    const int m8 = lane >> 3;
    uint32_t offA[4][2], offB[2][2];
    #pragma unroll
    for (int i = 0; i < 4; ++i)
        #pragma unroll
        for (int kc = 0; kc < 2; ++kc) {
            int rowa = wm * 64 + i * 16 + ((m8 & 1) << 3) + (lane & 7);
            offA[i][kc] = SWZ(rowa, kc * 2 + (m8 >> 1));
        }
    #pragma unroll
    for (int nb = 0; nb < 2; ++nb)
        #pragma unroll
        for (int kc = 0; kc < 2; ++kc) {
            int rowb = wn * 32 + nb * 16 + ((m8 >> 1) << 3) + (lane & 7);
            offB[nb][kc] = SWZ(rowb, kc * 2 + (m8 & 1));
        }

    float acc[4][4][4];
    #pragma unroll
    for (int i = 0; i < 4; ++i)
        #pragma unroll
        for (int j = 0; j < 4; ++j)
            #pragma unroll
            for (int r = 0; r < 4; ++r) acc[i][j][r] = 0.f;

    const int nk = K / BKC;

    LOAD_STAGE(0, 0);
    LOAD_STAGE(1, 1);
    LOAD_STAGE(2, 2);

    for (int kt = 0; kt < nk; ++kt) {
        const int rem = nk - 1 - kt;
        if (rem >= 2)      CP_WAIT(2);
        else if (rem == 1) CP_WAIT(1);
        else               CP_WAIT(0);
        __syncthreads();
        if (kt + 3 < nk) LOAD_STAGE(kt + 3, (kt + 3) & 3);

        const uint32_t base = sb + (uint32_t)(kt & 3) * STAGE_B;
        #pragma unroll
        for (int kc = 0; kc < 2; ++kc) {
            uint32_t ah[4][4];
            #pragma unroll
            for (int i = 0; i < 4; ++i)
                ldsm4(ah[i], base + OFF_A + offA[i][kc]);
            #pragma unroll
            for (int nb = 0; nb < 2; ++nb) {
                uint32_t bh[4];
                ldsm4(bh, base + OFF_B + offB[nb][kc]);
                #pragma unroll
                for (int i = 0; i < 4; ++i) {
                    mma_f16(acc[i][nb * 2],     ah[i], bh);
                    mma_f16(acc[i][nb * 2 + 1], ah[i], bh + 2);
                }
            }
        }
    }

    // ---- epilogue ----
    const int er = lane >> 2;
    const int ec = (lane & 3) * 2;
    #pragma unroll
    for (int i = 0; i < 4; ++i) {
        const int grow = row0 + wm * 64 + i * 16 + er;
        #pragma unroll
        for (int jf = 0; jf < 4; ++jf) {
            const int gcol = col0 + wn * 32 + jf * 8 + ec;
            float v00 = acc[i][jf][0], v01 = acc[i][jf][1];
            float v10 = acc[i][jf][2], v11 = acc[i][jf][3];
            if (MODE == 1) {
                float2 r0 = *(const float2*)(res + (size_t)grow * N + gcol);
                float2 r1 = *(const float2*)(res + (size_t)(grow + 8) * N + gcol);
                v00 += r0.x; v01 += r0.y; v10 += r1.x; v11 += r1.y;
                *(float2*)(C + (size_t)grow * N + gcol) = make_float2(v00, v01);
                *(float2*)(C + (size_t)(grow + 8) * N + gcol) = make_float2(v10, v11);
            } else {
                if (MODE == 3) {
                    uint32_t u0 = *(const uint32_t*)(resh + (size_t)grow * N + gcol);
                    uint32_t u1 = *(const uint32_t*)(resh + (size_t)(grow + 8) * N + gcol);
                    float2 r0 = __half22float2(*(__half2*)&u0);
                    float2 r1 = __half22float2(*(__half2*)&u1);
                    v00 *= r0.x / (1.f + __expf(-r0.x));
                    v01 *= r0.y / (1.f + __expf(-r0.y));
                    v10 *= r1.x / (1.f + __expf(-r1.x));
                    v11 *= r1.y / (1.f + __expf(-r1.y));
                }
                *(uint32_t*)(Ch + (size_t)grow * N + gcol) = pack_h2(v00, v01);
                *(uint32_t*)(Ch + (size_t)(grow + 8) * N + gcol) = pack_h2(v10, v11);
            }
        }
    }
#undef LOAD_STAGE
}

// ======================= tensor-core causal flash attention (fp16, BC=128) =======================
// BR=128 (8 warps x m16), BC=128, HD=128. Heavy Q-tiles first.
// smem: Q 32K | 2 stages x (K 32K, V 32K) = 160KB.
#define ATT_SMEM 163840
// [128]fp16 rows = 256B = 16 units of 16B; swizzle u ^ (r&7)
#define SWA(r_, u_) ((uint32_t)(r_) * 256u + ((((uint32_t)(u_)) ^ ((uint32_t)(r_) & 7u)) << 4))

__global__ void __launch_bounds__(256) flash_attn_mma_kernel(
    const __half* __restrict__ qkv, __half* __restrict__ o)
{
    const int flat = blockIdx.x;
    const int qt = (TT / 128 - 1) - (flat >> 5);   // 15 .. 0 (heavy first)
    const int bh = flat & 31;
    const int b = bh >> 4, h = bh & 15;
    extern __shared__ char smraw[];
    const uint32_t sb = smem_u32(smraw);
    const uint32_t sQ = sb;

    const int tid = threadIdx.x;
    const int lane = tid & 31;
    const int w = tid >> 5;
    const int bT = b * TT;
    const int hO = h * HD;
    const float sc = 0.08838834764831845f;   // 1/sqrt(128)

    {
        const int r = tid >> 1, ub = (tid & 1) * 8;
        const __half* q_row = qkv + (size_t)(bT + qt * 128 + r) * QKVW + hO;
        #pragma unroll
        for (int i = 0; i < 8; ++i) {
            int u = ub + i;
            cp_async16(sQ + SWA(r, u), q_row + u * 8);
        }
    }
    const int kvr = tid >> 1, kvu = (tid & 1) * 8;
#define LOAD_KV(jt_, s_) do {                                                        \
    uint32_t bb_ = sb + 32768u + (uint32_t)(s_) * 65536u;                            \
    size_t tok_ = (size_t)(bT + (jt_) * 128 + kvr) * QKVW + hO;                      \
    _Pragma("unroll")                                                                \
    for (int i_ = 0; i_ < 8; ++i_) {                                                 \
        int u_ = kvu + i_;                                                           \
        uint32_t so_ = SWA(kvr, u_);                                                 \
        cp_async16(bb_ + so_,          qkv + tok_ + 2048 + u_ * 8);                  \
        cp_async16(bb_ + 32768u + so_, qkv + tok_ + 4096 + u_ * 8);                  \
    }                                                                                \
} while (0)

    LOAD_KV(0, 0);
    cp_commit();

    uint32_t offQ[8], offK[8], offV[8];
    {
        int rq = w * 16 + ((lane >> 3) & 1) * 8 + (lane & 7);
        #pragma unroll
        for (int c = 0; c < 8; ++c) offQ[c] = SWA(rq, 2 * c + (lane >> 4));
        int rk = ((lane >> 4) << 3) + (lane & 7);
        #pragma unroll
        for (int c = 0; c < 8; ++c) offK[c] = SWA(rk, 2 * c + ((lane >> 3) & 1));
        int rv = ((lane >> 3) & 1) * 8 + (lane & 7);
        #pragma unroll
        for (int hb = 0; hb < 8; ++hb) offV[hb] = SWA(rv, hb * 2 + (lane >> 4));
    }

    uint32_t qr[8][4];
    float Oa[16][4];
    #pragma unroll
    for (int g = 0; g < 16; ++g)
        #pragma unroll
        for (int r = 0; r < 4; ++r) Oa[g][r] = 0.f;
    float m0 = -INFINITY, m1 = -INFINITY, l0 = 0.f, l1 = 0.f;

    const int row0 = qt * 128 + w * 16 + (lane >> 2);
    const int row1 = row0 + 8;

    for (int jt = 0; jt <= qt; ++jt) {
        const int s = jt & 1;
        if (jt < qt) { LOAD_KV(jt + 1, s ^ 1); cp_commit(); CP_WAIT(1); }
        else         { CP_WAIT(0); }
        __syncthreads();

        if (jt == 0) {
            #pragma unroll
            for (int c = 0; c < 8; ++c) ldsm4(qr[c], sQ + offQ[c]);
        }

        const uint32_t bK = sb + 32768u + (uint32_t)s * 65536u;
        const uint32_t bV = bK + 32768u;

        float sf[16][4];
        #pragma unroll
        for (int i = 0; i < 16; ++i)
            #pragma unroll
            for (int r = 0; r < 4; ++r) sf[i][r] = 0.f;
        #pragma unroll
        for (int nb = 0; nb < 8; ++nb) {
            const uint32_t bKn = bK + (uint32_t)nb * 4096u;
            #pragma unroll
            for (int c = 0; c < 8; ++c) {
                uint32_t kh[4];
                ldsm4(kh, bKn + offK[c]);
                mma_f16(sf[nb * 2],     qr[c], kh);
                mma_f16(sf[nb * 2 + 1], qr[c], kh + 2);
            }
        }

        if (jt == qt) {
            const int jb = jt * 128 + (lane & 3) * 2;
            #pragma unroll
            for (int i = 0; i < 16; ++i) {
                int c0 = jb + i * 8;
                if (c0     > row0) sf[i][0] = -INFINITY;
                if (c0 + 1 > row0) sf[i][1] = -INFINITY;
                if (c0     > row1) sf[i][2] = -INFINITY;
                if (c0 + 1 > row1) sf[i][3] = -INFINITY;
            }
        }

        float mx0 = -INFINITY, mx1 = -INFINITY;
        #pragma unroll
        for (int i = 0; i < 16; ++i) {
            mx0 = fmaxf(mx0, fmaxf(sf[i][0], sf[i][1]));
            mx1 = fmaxf(mx1, fmaxf(sf[i][2], sf[i][3]));
        }
        mx0 *= sc; mx1 *= sc;
        mx0 = fmaxf(mx0, __shfl_xor_sync(0xffffffffu, mx0, 1));
        mx0 = fmaxf(mx0, __shfl_xor_sync(0xffffffffu, mx0, 2));
        mx1 = fmaxf(mx1, __shfl_xor_sync(0xffffffffu, mx1, 1));
        mx1 = fmaxf(mx1, __shfl_xor_sync(0xffffffffu, mx1, 2));
        float mn0 = fmaxf(m0, mx0), mn1 = fmaxf(m1, mx1);
        float al0 = __expf(m0 - mn0), al1 = __expf(m1 - mn1);
        m0 = mn0; m1 = mn1;
        float ps0 = 0.f, ps1 = 0.f;
        #pragma unroll
        for (int i = 0; i < 16; ++i) {
            sf[i][0] = __expf(fmaf(sf[i][0], sc, -m0)); ps0 += sf[i][0];
            sf[i][1] = __expf(fmaf(sf[i][1], sc, -m0)); ps0 += sf[i][1];
            sf[i][2] = __expf(fmaf(sf[i][2], sc, -m1)); ps1 += sf[i][2];
            sf[i][3] = __expf(fmaf(sf[i][3], sc, -m1)); ps1 += sf[i][3];
        }
        ps0 += __shfl_xor_sync(0xffffffffu, ps0, 1);
        ps0 += __shfl_xor_sync(0xffffffffu, ps0, 2);
        ps1 += __shfl_xor_sync(0xffffffffu, ps1, 1);
        ps1 += __shfl_xor_sync(0xffffffffu, ps1, 2);
        l0 = l0 * al0 + ps0; l1 = l1 * al1 + ps1;
        #pragma unroll
        for (int g = 0; g < 16; ++g) {
            Oa[g][0] *= al0; Oa[g][1] *= al0;
            Oa[g][2] *= al1; Oa[g][3] *= al1;
        }

        #pragma unroll
        for (int c2 = 0; c2 < 8; ++c2) {
            uint32_t ph[4];
            ph[0] = pack_h2(sf[2 * c2][0],     sf[2 * c2][1]);
            ph[1] = pack_h2(sf[2 * c2][2],     sf[2 * c2][3]);
            ph[2] = pack_h2(sf[2 * c2 + 1][0], sf[2 * c2 + 1][1]);
            ph[3] = pack_h2(sf[2 * c2 + 1][2], sf[2 * c2 + 1][3]);
            const uint32_t bVc = bV + (uint32_t)c2 * 4096u;
            #pragma unroll
            for (int hb = 0; hb < 8; ++hb) {
                uint32_t vh[4];
                ldsm4t(vh, bVc + offV[hb]);
                mma_f16(Oa[hb * 2],     ph, vh);
                mma_f16(Oa[hb * 2 + 1], ph, vh + 2);
            }
        }
        __syncthreads();
    }

    const float il0 = 1.0f / l0, il1 = 1.0f / l1;
    const size_t tok0 = (size_t)(bT + row0);
    #pragma unroll
    for (int g = 0; g < 16; ++g) {
        const int col = hO + g * 8 + (lane & 3) * 2;
        *(uint32_t*)(o + tok0 * DD + col) = pack_h2(Oa[g][0] * il0, Oa[g][1] * il0);
        *(uint32_t*)(o + (tok0 + 8) * DD + col) = pack_h2(Oa[g][2] * il1, Oa[g][3] * il1);
    }
#undef LOAD_KV
}

// ---------------- launch ----------------
extern "C" void kernel_launch(void* const* d_in, const int* in_sizes, int n_in,
                              void* d_out, int out_size)
{
    const float* x      = (const float*)d_in[0];
    const float* gamma  = (const float*)d_in[1];
    const float* beta   = (const float*)d_in[2];
    const float* qkv_w  = (const float*)d_in[3];
    const float* o_w    = (const float*)d_in[4];
    const float* gate_w = (const float*)d_in[5];
    const float* up_w   = (const float*)d_in[6];
    const float* down_w = (const float*)d_in[7];
    const float* n1w    = (const float*)d_in[8];
    const float* n2w    = (const float*)d_in[9];
    float* out = (float*)d_out;

    float *x1_;
    __half *gate_, *act_, *qkv_, *w_;
    cudaGetSymbolAddress((void**)&x1_,   g_x1);
    cudaGetSymbolAddress((void**)&gate_, g_gate);
    cudaGetSymbolAddress((void**)&act_,  g_act);
    cudaGetSymbolAddress((void**)&qkv_,  g_qkv);
    cudaGetSymbolAddress((void**)&w_,    g_w);
    __half* wq_ = w_ + W_QKV_OFF;
    __half* wo_ = w_ + W_O_OFF;
    __half* wg_ = w_ + W_G_OFF;
    __half* wu_ = w_ + W_U_OFF;
    __half* wd_ = w_ + W_D_OFF;

    cudaFuncSetAttribute(flash_attn_mma_kernel,
                         cudaFuncAttributeMaxDynamicSharedMemorySize, ATT_SMEM);
    cudaFuncSetAttribute(gemm_mma_kernel<1>,
                         cudaFuncAttributeMaxDynamicSharedMemorySize, GEMM_SMEM);
    cudaFuncSetAttribute(gemm_mma_kernel<2>,
                         cudaFuncAttributeMaxDynamicSharedMemorySize, GEMM_SMEM);
    cudaFuncSetAttribute(gemm_mma_kernel<3>,
                         cudaFuncAttributeMaxDynamicSharedMemorySize, GEMM_SMEM);

    // 0. all weights -> single fp16 slab, one launch
    cvt_all_kernel<<<2368, 256>>>(qkv_w, o_w, gate_w, up_w, down_w, w_);

    // 1. h = rmsnorm(x, n1)*gamma+beta -> act (fp16)
    rmsnorm_affine_kernel<<<MTOK, 256>>>(x, n1w, gamma, beta, act_);
    // 2. qkv = h @ qkv_w^T -> fp16
    gemm_mma_kernel<2><<<dim3(QKVW / 128, MTOK / 128), 256, GEMM_SMEM>>>(
        act_, wq_, nullptr, nullptr, qkv_, nullptr, QKVW, DD);
    // 3. attention (heavy tiles first) -> act (fp16)
    flash_attn_mma_kernel<<<(TT / 128) * BB * HH, 256, ATT_SMEM>>>(qkv_, act_);
    // 4. x1 = x + attn @ o_w^T
    gemm_mma_kernel<1><<<dim3(DD / 128, MTOK / 128), 256, GEMM_SMEM>>>(
        act_, wo_, x, x1_, nullptr, nullptr, DD, DD);
    // 5. h = rmsnorm(x1, n2)*gamma+beta -> act (fp16)
    rmsnorm_affine_kernel<<<MTOK, 256>>>(x1_, n2w, gamma, beta, act_);
    // 6. gate -> fp16
    gemm_mma_kernel<2><<<dim3(FF / 128, MTOK / 128), 256, GEMM_SMEM>>>(
        act_, wg_, nullptr, nullptr, gate_, nullptr, FF, DD);
    // 7. up with fused silu(gate)*up -> ff (fp16) into qkv buffer
    gemm_mma_kernel<3><<<dim3(FF / 128, MTOK / 128), 256, GEMM_SMEM>>>(
        act_, wu_, nullptr, nullptr, qkv_, gate_, FF, DD);
    // 8. out = x1 + ff @ down_w^T
    gemm_mma_kernel<1><<<dim3(DD / 128, MTOK / 128), 256, GEMM_SMEM>>>(
        qkv_, wd_, x1_, out, nullptr, nullptr, DD, FF);
}